// round 3
// baseline (speedup 1.0000x reference)
#include <cuda_runtime.h>
#include <cuda_bf16.h>
#include <cstddef>

constexpr int Bn = 8;
constexpr int Tn = 2304;
constexpr int NROW = Bn * Tn;
constexpr float LAMBDA_INIT_F = 0.6192834728526787f;
constexpr float QSCALE = 0.18033688011112042f;   // (1/8) * log2(e)

typedef unsigned long long ull;

__device__ float g_stats[NROW * 2];
__device__ float g_q[NROW * 128];
__device__ float g_k[NROW * 128];
__device__ float g_v[NROW * 128];
__device__ float g_lam;

// ---- packed f32x2 helpers ----
__device__ __forceinline__ ull fma2(ull a, ull b, ull c) {
  ull d;
  asm("fma.rn.f32x2 %0,%1,%2,%3;" : "=l"(d) : "l"(a), "l"(b), "l"(c));
  return d;
}
__device__ __forceinline__ ull mul2(ull a, ull b) {
  ull d;
  asm("mul.rn.f32x2 %0,%1,%2;" : "=l"(d) : "l"(a), "l"(b));
  return d;
}
__device__ __forceinline__ ull pk(float lo, float hi) {
  ull r;
  asm("mov.b64 %0,{%1,%2};" : "=l"(r) : "f"(lo), "f"(hi));
  return r;
}
__device__ __forceinline__ float2 upk(ull a) {
  float2 r;
  asm("mov.b64 {%0,%1},%2;" : "=f"(r.x), "=f"(r.y) : "l"(a));
  return r;
}

__device__ __forceinline__ float fast_exp2(float x) {
  x = fmaxf(x, -125.0f);
  float t = x + 12582912.0f;
  int e = __float_as_int(t) - 0x4B400000;
  float f = x - (t - 12582912.0f);
  float p =        1.3333558e-3f;
  p = fmaf(p, f,   9.6181291e-3f);
  p = fmaf(p, f,   5.5504109e-2f);
  p = fmaf(p, f,   2.4022651e-1f);
  p = fmaf(p, f,   6.9314718e-1f);
  p = fmaf(p, f,   1.0f);
  return __int_as_float(__float_as_int(p) + (e << 23));
}

__device__ __forceinline__ float redsum16(float v) {
  v += __shfl_xor_sync(0xffffffffu, v, 8);
  v += __shfl_xor_sync(0xffffffffu, v, 4);
  v += __shfl_xor_sync(0xffffffffu, v, 2);
  v += __shfl_xor_sync(0xffffffffu, v, 1);
  return v;
}
__device__ __forceinline__ float redmax16(float v) {
  v = fmaxf(v, __shfl_xor_sync(0xffffffffu, v, 8));
  v = fmaxf(v, __shfl_xor_sync(0xffffffffu, v, 4));
  v = fmaxf(v, __shfl_xor_sync(0xffffffffu, v, 2));
  v = fmaxf(v, __shfl_xor_sync(0xffffffffu, v, 1));
  return v;
}

// ---------------- lambda ----------------
__global__ void lambda_kernel(const float* __restrict__ lq1,
                              const float* __restrict__ lq2,
                              const float* __restrict__ lk1,
                              const float* __restrict__ lk2) {
  __shared__ float sh1[64], sh2[64];
  int t = threadIdx.x;
  sh1[t] = lq1[t] * lk1[t];
  sh2[t] = lq2[t] * lk2[t];
  __syncthreads();
  if (t == 0) {
    float a = 0.f, c = 0.f;
    for (int i = 0; i < 64; i++) { a += sh1[i]; c += sh2[i]; }
    g_lam = expf(a) - expf(c) + LAMBDA_INIT_F;
  }
}

// ---------------- LN stats ----------------
__global__ void stats_kernel(const float* __restrict__ x) {
  int row = blockIdx.x * 8 + threadIdx.y;
  const float4* xr = (const float4*)(x + (size_t)row * 1024);
  float s = 0.f, ss = 0.f;
  for (int i = threadIdx.x; i < 256; i += 32) {
    float4 v = xr[i];
    s += v.x + v.y + v.z + v.w;
    ss += v.x * v.x + v.y * v.y + v.z * v.z + v.w * v.w;
  }
#pragma unroll
  for (int o = 16; o > 0; o >>= 1) {
    s += __shfl_xor_sync(0xffffffffu, s, o);
    ss += __shfl_xor_sync(0xffffffffu, ss, o);
  }
  if (threadIdx.x == 0) {
    float mean = s * (1.0f / 1024.0f);
    float var = fmaf(-mean, mean, ss * (1.0f / 1024.0f));
    g_stats[row * 2 + 0] = mean;
    g_stats[row * 2 + 1] = rsqrtf(var + 1e-5f);
  }
}

// ---------------- LN-fused projection GEMM (f32x2) ----------------
struct ProjParams {
  const float* x;
  const float* W[3][3];
  const float* g[3];
  const float* bta[3];
};

__global__ __launch_bounds__(256) void proj_kernel(ProjParams p) {
  __shared__ float Asd[16][136];   // [k][2r+e] duplicated A
  __shared__ float Bs[16][132];
  __shared__ float mean_s[64], rstd_s[64];

  const int tile = blockIdx.x, bb = blockIdx.y, mat = blockIdx.z;
  const int seg = tile < 2 ? 0 : (tile < 34 ? 1 : 2);
  const float* __restrict__ W = p.W[mat][seg];
  const float* __restrict__ gg = p.g[seg];
  const float* __restrict__ bz = p.bta[seg];
  const int row0 = bb * Tn + tile * 64;
  const int tid = threadIdx.x;

  if (tid < 64) {
    mean_s[tid] = g_stats[(row0 + tid) * 2 + 0];
    rstd_s[tid] = g_stats[(row0 + tid) * 2 + 1];
  }

  const int rg = tid >> 4, ct = tid & 15;
  const int r0 = rg * 4, cc0 = ct * 8;
  const int ar = tid >> 2, ak = (tid & 3) * 4;

  ull acc[4][4];
#pragma unroll
  for (int i = 0; i < 4; i++)
#pragma unroll
    for (int j = 0; j < 4; j++) acc[i][j] = pk(0.f, 0.f);

  for (int k0 = 0; k0 < 1024; k0 += 16) {
    __syncthreads();
    {
      float4 v = *(const float4*)&p.x[(size_t)(row0 + ar) * 1024 + k0 + ak];
      float mn = mean_s[ar], rs = rstd_s[ar];
      float a0 = (v.x - mn) * rs * gg[k0 + ak + 0] + bz[k0 + ak + 0];
      float a1 = (v.y - mn) * rs * gg[k0 + ak + 1] + bz[k0 + ak + 1];
      float a2 = (v.z - mn) * rs * gg[k0 + ak + 2] + bz[k0 + ak + 2];
      float a3 = (v.w - mn) * rs * gg[k0 + ak + 3] + bz[k0 + ak + 3];
      *(float2*)&Asd[ak + 0][2 * ar] = make_float2(a0, a0);
      *(float2*)&Asd[ak + 1][2 * ar] = make_float2(a1, a1);
      *(float2*)&Asd[ak + 2][2 * ar] = make_float2(a2, a2);
      *(float2*)&Asd[ak + 3][2 * ar] = make_float2(a3, a3);
      float4 w0 = *(const float4*)&W[(size_t)(k0 + rg) * 128 + cc0];
      float4 w1 = *(const float4*)&W[(size_t)(k0 + rg) * 128 + cc0 + 4];
      *(float4*)&Bs[rg][cc0] = w0;
      *(float4*)&Bs[rg][cc0 + 4] = w1;
    }
    __syncthreads();
#pragma unroll
    for (int kk = 0; kk < 16; kk++) {
      const ull* ad = (const ull*)&Asd[kk][2 * r0];   // 4 dup pairs
      const ull* bp = (const ull*)&Bs[kk][cc0];       // 4 col pairs
      ull a0 = ad[0], a1 = ad[1], a2 = ad[2], a3 = ad[3];
      ull b0 = bp[0], b1 = bp[1], b2 = bp[2], b3 = bp[3];
      acc[0][0] = fma2(a0, b0, acc[0][0]); acc[0][1] = fma2(a0, b1, acc[0][1]);
      acc[0][2] = fma2(a0, b2, acc[0][2]); acc[0][3] = fma2(a0, b3, acc[0][3]);
      acc[1][0] = fma2(a1, b0, acc[1][0]); acc[1][1] = fma2(a1, b1, acc[1][1]);
      acc[1][2] = fma2(a1, b2, acc[1][2]); acc[1][3] = fma2(a1, b3, acc[1][3]);
      acc[2][0] = fma2(a2, b0, acc[2][0]); acc[2][1] = fma2(a2, b1, acc[2][1]);
      acc[2][2] = fma2(a2, b2, acc[2][2]); acc[2][3] = fma2(a2, b3, acc[2][3]);
      acc[3][0] = fma2(a3, b0, acc[3][0]); acc[3][1] = fma2(a3, b1, acc[3][1]);
      acc[3][2] = fma2(a3, b2, acc[3][2]); acc[3][3] = fma2(a3, b3, acc[3][3]);
    }
  }

  float* __restrict__ outp = (mat == 0) ? g_q : (mat == 1) ? g_k : g_v;
#pragma unroll
  for (int i = 0; i < 4; i++) {
    float2 c0v = upk(acc[i][0]), c1v = upk(acc[i][1]);
    float2 c2v = upk(acc[i][2]), c3v = upk(acc[i][3]);
    size_t off = (size_t)(row0 + r0 + i) * 128 + cc0;
    *(float4*)&outp[off]     = make_float4(c0v.x, c0v.y, c1v.x, c1v.y);
    *(float4*)&outp[off + 4] = make_float4(c2v.x, c2v.y, c3v.x, c3v.y);
  }
}

// ---------------- dual flash attention (f32x2) ----------------
// smem: Qs1d 64x136 | Qs2d 64x136 | Ks1 64x68 | Ks2 64x68 |
//       Ps1d 64x136 | Ps2d 64x136 | Vs 64x132
constexpr int OFF_Q1 = 0;
constexpr int OFF_Q2 = OFF_Q1 + 64 * 136;
constexpr int OFF_K1 = OFF_Q2 + 64 * 136;
constexpr int OFF_K2 = OFF_K1 + 64 * 68;
constexpr int OFF_P1 = OFF_K2 + 64 * 68;
constexpr int OFF_P2 = OFF_P1 + 64 * 136;
constexpr int OFF_V  = OFF_P2 + 64 * 136;
constexpr int ATTN_SMEM_FLOATS = OFF_V + 64 * 132;
constexpr int ATTN_SMEM_BYTES = ATTN_SMEM_FLOATS * 4;   // 207872

__global__ __launch_bounds__(256, 1) void attn_kernel(
    const float* __restrict__ gam, const float* __restrict__ bet,
    float* __restrict__ out) {
  extern __shared__ float sm[];
  float* Qs1d = sm + OFF_Q1;
  float* Qs2d = sm + OFF_Q2;
  float* Ks1  = sm + OFF_K1;
  float* Ks2  = sm + OFF_K2;
  float* Ps1d = sm + OFF_P1;
  float* Ps2d = sm + OFF_P2;
  float* Vs   = sm + OFF_V;

  const int tid = threadIdx.x;
  const int rg = tid >> 4, ct = tid & 15;
  const int r0 = rg * 4, c0 = ct * 4, cv0 = ct * 8;
  const size_t base = (size_t)blockIdx.y * Tn;
  const float lam = g_lam;
  const float4 gv0 = *(const float4*)&gam[cv0];
  const float4 gv1 = *(const float4*)&gam[cv0 + 4];
  const float4 bv0 = *(const float4*)&bet[cv0];
  const float4 bv1 = *(const float4*)&bet[cv0 + 4];

  for (int half = 0; half < 2; half++) {
    const int qt = half ? (35 - (int)blockIdx.x) : (int)blockIdx.x;
    const int q0 = qt * 64;

    __syncthreads();
    // load Q tile transposed + duplicated: Qs[d][2r+e]
    for (int i = tid; i < 2048; i += 256) {
      int r = i >> 5, quad = i & 31;
      float4 v = *(const float4*)&g_q[(base + q0 + r) * 128 + quad * 4];
      float* dst = (quad < 16) ? Qs1d : Qs2d;
      int dd = (quad * 4) & 63;
      *(float2*)&dst[(dd + 0) * 136 + 2 * r] = make_float2(v.x, v.x);
      *(float2*)&dst[(dd + 1) * 136 + 2 * r] = make_float2(v.y, v.y);
      *(float2*)&dst[(dd + 2) * 136 + 2 * r] = make_float2(v.z, v.z);
      *(float2*)&dst[(dd + 3) * 136 + 2 * r] = make_float2(v.w, v.w);
    }

    ull O1[4][4], O2[4][4];
    float m1[4], m2[4], l1[4], l2[4];
#pragma unroll
    for (int i = 0; i < 4; i++) {
      m1[i] = m2[i] = -3.0e38f;
      l1[i] = l2[i] = 0.f;
#pragma unroll
      for (int j = 0; j < 4; j++) { O1[i][j] = pk(0.f, 0.f); O2[i][j] = pk(0.f, 0.f); }
    }

    for (int kt = 0; kt <= qt; kt++) {
      const int k0 = kt * 64;
      __syncthreads();
      for (int i = tid; i < 2048; i += 256) {
        int c = i >> 5, quad = i & 31;
        float4 kv = *(const float4*)&g_k[(base + k0 + c) * 128 + quad * 4];
        float* dst = (quad < 16) ? Ks1 : Ks2;
        int dd = (quad * 4) & 63;
        dst[(dd + 0) * 68 + c] = kv.x;
        dst[(dd + 1) * 68 + c] = kv.y;
        dst[(dd + 2) * 68 + c] = kv.z;
        dst[(dd + 3) * 68 + c] = kv.w;
        float4 vv = *(const float4*)&g_v[(base + k0 + c) * 128 + quad * 4];
        *(float4*)&Vs[c * 132 + quad * 4] = vv;
      }
      __syncthreads();

      // ----- S = Q K^T (packed along k-columns) -----
      ull s1p[4][2], s2p[4][2];
#pragma unroll
      for (int i = 0; i < 4; i++)
#pragma unroll
        for (int j = 0; j < 2; j++) { s1p[i][j] = pk(0.f, 0.f); s2p[i][j] = pk(0.f, 0.f); }

      for (int d = 0; d < 64; d++) {
        const ull* q1 = (const ull*)&Qs1d[d * 136 + 2 * r0];
        const ull* k1 = (const ull*)&Ks1[d * 68 + c0];
        const ull* q2 = (const ull*)&Qs2d[d * 136 + 2 * r0];
        const ull* k2 = (const ull*)&Ks2[d * 68 + c0];
        ull qa0 = q1[0], qa1 = q1[1], qa2 = q1[2], qa3 = q1[3];
        ull ka0 = k1[0], ka1 = k1[1];
        ull qb0 = q2[0], qb1 = q2[1], qb2 = q2[2], qb3 = q2[3];
        ull kb0 = k2[0], kb1 = k2[1];
        s1p[0][0] = fma2(qa0, ka0, s1p[0][0]); s1p[0][1] = fma2(qa0, ka1, s1p[0][1]);
        s1p[1][0] = fma2(qa1, ka0, s1p[1][0]); s1p[1][1] = fma2(qa1, ka1, s1p[1][1]);
        s1p[2][0] = fma2(qa2, ka0, s1p[2][0]); s1p[2][1] = fma2(qa2, ka1, s1p[2][1]);
        s1p[3][0] = fma2(qa3, ka0, s1p[3][0]); s1p[3][1] = fma2(qa3, ka1, s1p[3][1]);
        s2p[0][0] = fma2(qb0, kb0, s2p[0][0]); s2p[0][1] = fma2(qb0, kb1, s2p[0][1]);
        s2p[1][0] = fma2(qb1, kb0, s2p[1][0]); s2p[1][1] = fma2(qb1, kb1, s2p[1][1]);
        s2p[2][0] = fma2(qb2, kb0, s2p[2][0]); s2p[2][1] = fma2(qb2, kb1, s2p[2][1]);
        s2p[3][0] = fma2(qb3, kb0, s2p[3][0]); s2p[3][1] = fma2(qb3, kb1, s2p[3][1]);
      }

      const bool diag = (kt == qt);
      float p1[4][4], p2[4][4];
#pragma unroll
      for (int i = 0; i < 4; i++) {
        float2 sa0 = upk(s1p[i][0]), sa1 = upk(s1p[i][1]);
        float2 sb0 = upk(s2p[i][0]), sb1 = upk(s2p[i][1]);
        float s1[4] = {sa0.x, sa0.y, sa1.x, sa1.y};
        float s2[4] = {sb0.x, sb0.y, sb1.x, sb1.y};
        float mx1 = -3.0e38f, mx2 = -3.0e38f;
#pragma unroll
        for (int j = 0; j < 4; j++) {
          float a = s1[j] * QSCALE;
          float b = s2[j] * QSCALE;
          if (diag && (c0 + j) > (r0 + i)) { a = -3.0e38f; b = -3.0e38f; }
          s1[j] = a; s2[j] = b;
          mx1 = fmaxf(mx1, a); mx2 = fmaxf(mx2, b);
        }
        mx1 = redmax16(mx1);
        mx2 = redmax16(mx2);
        float mn1 = fmaxf(m1[i], mx1), mn2 = fmaxf(m2[i], mx2);
        float al1 = fast_exp2(m1[i] - mn1), al2 = fast_exp2(m2[i] - mn2);
        m1[i] = mn1; m2[i] = mn2;
        float su1 = 0.f, su2 = 0.f;
#pragma unroll
        for (int j = 0; j < 4; j++) {
          float e1 = fast_exp2(s1[j] - mn1);
          float e2 = fast_exp2(s2[j] - mn2);
          p1[i][j] = e1; p2[i][j] = e2;
          su1 += e1; su2 += e2;
        }
        su1 = redsum16(su1);
        su2 = redsum16(su2);
        l1[i] = l1[i] * al1 + su1;
        l2[i] = l2[i] * al2 + su2;
        ull al1p = pk(al1, al1), al2p = pk(al2, al2);
#pragma unroll
        for (int j = 0; j < 4; j++) {
          O1[i][j] = mul2(O1[i][j], al1p);
          O2[i][j] = mul2(O2[i][j], al2p);
        }
      }
      // store P duplicated: Ps[c][2r+e]
#pragma unroll
      for (int j = 0; j < 4; j++) {
        *(float4*)&Ps1d[(c0 + j) * 136 + 2 * r0] =
            make_float4(p1[0][j], p1[0][j], p1[1][j], p1[1][j]);
        *(float4*)&Ps1d[(c0 + j) * 136 + 2 * r0 + 4] =
            make_float4(p1[2][j], p1[2][j], p1[3][j], p1[3][j]);
        *(float4*)&Ps2d[(c0 + j) * 136 + 2 * r0] =
            make_float4(p2[0][j], p2[0][j], p2[1][j], p2[1][j]);
        *(float4*)&Ps2d[(c0 + j) * 136 + 2 * r0 + 4] =
            make_float4(p2[2][j], p2[2][j], p2[3][j], p2[3][j]);
      }
      __syncthreads();

      // ----- O += P V (packed along v-columns) -----
      for (int c = 0; c < 64; c++) {
        const ull* pa = (const ull*)&Ps1d[c * 136 + 2 * r0];
        const ull* pb = (const ull*)&Ps2d[c * 136 + 2 * r0];
        const ull* vp = (const ull*)&Vs[c * 132 + cv0];
        ull v0 = vp[0], v1 = vp[1], v2 = vp[2], v3 = vp[3];
        ull pa0 = pa[0], pa1 = pa[1], pa2 = pa[2], pa3 = pa[3];
        ull pb0 = pb[0], pb1 = pb[1], pb2 = pb[2], pb3 = pb[3];
        O1[0][0] = fma2(pa0, v0, O1[0][0]); O1[0][1] = fma2(pa0, v1, O1[0][1]);
        O1[0][2] = fma2(pa0, v2, O1[0][2]); O1[0][3] = fma2(pa0, v3, O1[0][3]);
        O1[1][0] = fma2(pa1, v0, O1[1][0]); O1[1][1] = fma2(pa1, v1, O1[1][1]);
        O1[1][2] = fma2(pa1, v2, O1[1][2]); O1[1][3] = fma2(pa1, v3, O1[1][3]);
        O1[2][0] = fma2(pa2, v0, O1[2][0]); O1[2][1] = fma2(pa2, v1, O1[2][1]);
        O1[2][2] = fma2(pa2, v2, O1[2][2]); O1[2][3] = fma2(pa2, v3, O1[2][3]);
        O1[3][0] = fma2(pa3, v0, O1[3][0]); O1[3][1] = fma2(pa3, v1, O1[3][1]);
        O1[3][2] = fma2(pa3, v2, O1[3][2]); O1[3][3] = fma2(pa3, v3, O1[3][3]);
        O2[0][0] = fma2(pb0, v0, O2[0][0]); O2[0][1] = fma2(pb0, v1, O2[0][1]);
        O2[0][2] = fma2(pb0, v2, O2[0][2]); O2[0][3] = fma2(pb0, v3, O2[0][3]);
        O2[1][0] = fma2(pb1, v0, O2[1][0]); O2[1][1] = fma2(pb1, v1, O2[1][1]);
        O2[1][2] = fma2(pb1, v2, O2[1][2]); O2[1][3] = fma2(pb1, v3, O2[1][3]);
        O2[2][0] = fma2(pb2, v0, O2[2][0]); O2[2][1] = fma2(pb2, v1, O2[2][1]);
        O2[2][2] = fma2(pb2, v2, O2[2][2]); O2[2][3] = fma2(pb2, v3, O2[2][3]);
        O2[3][0] = fma2(pb3, v0, O2[3][0]); O2[3][1] = fma2(pb3, v1, O2[3][1]);
        O2[3][2] = fma2(pb3, v2, O2[3][2]); O2[3][3] = fma2(pb3, v3, O2[3][3]);
      }
    }

    // epilogue: combine + output LN
#pragma unroll
    for (int i = 0; i < 4; i++) {
      float inv1 = 1.0f / l1[i], inv2 = lam / l2[i];
      float att[8];
      float s = 0.f;
#pragma unroll
      for (int j = 0; j < 4; j++) {
        float2 o1 = upk(O1[i][j]);
        float2 o2 = upk(O2[i][j]);
        att[2 * j + 0] = o1.x * inv1 - o2.x * inv2;
        att[2 * j + 1] = o1.y * inv1 - o2.y * inv2;
        s += att[2 * j] + att[2 * j + 1];
      }
      float mean = redsum16(s) * (1.0f / 128.0f);
      float vs = 0.f;
#pragma unroll
      for (int j = 0; j < 8; j++) {
        float d = att[j] - mean;
        vs += d * d;
      }
      float var = redsum16(vs) * (1.0f / 128.0f);
      float rstd = rsqrtf(var + 1e-5f);
      float g8[8] = {gv0.x, gv0.y, gv0.z, gv0.w, gv1.x, gv1.y, gv1.z, gv1.w};
      float b8[8] = {bv0.x, bv0.y, bv0.z, bv0.w, bv1.x, bv1.y, bv1.z, bv1.w};
      float o[8];
#pragma unroll
      for (int j = 0; j < 8; j++)
        o[j] = (att[j] - mean) * rstd * g8[j] + b8[j];
      size_t off = (base + q0 + r0 + i) * 128 + cv0;
      *(float4*)&out[off]     = make_float4(o[0], o[1], o[2], o[3]);
      *(float4*)&out[off + 4] = make_float4(o[4], o[5], o[6], o[7]);
    }
  }
}

// ---------------- launch ----------------
extern "C" void kernel_launch(void* const* d_in, const int* in_sizes, int n_in,
                              void* d_out, int out_size) {
  const float* x     = (const float*)d_in[0];
  const float* Wq    = (const float*)d_in[1];
  const float* Wk    = (const float*)d_in[2];
  const float* Wv    = (const float*)d_in[3];
  const float* Wq_ss = (const float*)d_in[4];
  const float* Wk_ss = (const float*)d_in[5];
  const float* Wv_ss = (const float*)d_in[6];
  const float* Wq_se = (const float*)d_in[7];
  const float* Wk_se = (const float*)d_in[8];
  const float* Wv_se = (const float*)d_in[9];
  const float* g_in  = (const float*)d_in[10];
  const float* b_in  = (const float*)d_in[11];
  const float* g_ss  = (const float*)d_in[12];
  const float* b_ss  = (const float*)d_in[13];
  const float* g_se  = (const float*)d_in[14];
  const float* b_se  = (const float*)d_in[15];
  const float* g_out = (const float*)d_in[16];
  const float* b_out = (const float*)d_in[17];
  const float* lq1   = (const float*)d_in[18];
  const float* lq2   = (const float*)d_in[19];
  const float* lk1   = (const float*)d_in[20];
  const float* lk2   = (const float*)d_in[21];

  static bool attr_set = false;
  if (!attr_set) {
    cudaFuncSetAttribute(attn_kernel, cudaFuncAttributeMaxDynamicSharedMemorySize,
                         ATTN_SMEM_BYTES);
    attr_set = true;
  }

  lambda_kernel<<<1, 64>>>(lq1, lq2, lk1, lk2);
  stats_kernel<<<NROW / 8, dim3(32, 8)>>>(x);

  ProjParams p;
  p.x = x;
  p.W[0][0] = Wq_ss; p.W[0][1] = Wq; p.W[0][2] = Wq_se;
  p.W[1][0] = Wk_ss; p.W[1][1] = Wk; p.W[1][2] = Wk_se;
  p.W[2][0] = Wv_ss; p.W[2][1] = Wv; p.W[2][2] = Wv_se;
  p.g[0] = g_ss; p.g[1] = g_in; p.g[2] = g_se;
  p.bta[0] = b_ss; p.bta[1] = b_in; p.bta[2] = b_se;
  proj_kernel<<<dim3(36, 8, 3), 256>>>(p);

  attn_kernel<<<dim3(18, 8), 256, ATTN_SMEM_BYTES>>>(g_out, b_out, (float*)d_out);
}

// round 4
// speedup vs baseline: 1.1562x; 1.1562x over previous
#include <cuda_runtime.h>
#include <cuda_bf16.h>
#include <cstddef>

constexpr int Bn = 8;
constexpr int Tn = 2304;
constexpr int NROW = Bn * Tn;
constexpr float LAMBDA_INIT_F = 0.6192834728526787f;
constexpr float QSCALE = 0.18033688011112042f;   // (1/8) * log2(e)

typedef unsigned long long ull;

__device__ float g_stats[NROW * 2];
__device__ float g_q[NROW * 128];
__device__ float g_k[NROW * 128];
__device__ float g_v[NROW * 128];
__device__ float g_lam;

// ---- packed f32x2 helpers ----
__device__ __forceinline__ ull fma2(ull a, ull b, ull c) {
  ull d;
  asm("fma.rn.f32x2 %0,%1,%2,%3;" : "=l"(d) : "l"(a), "l"(b), "l"(c));
  return d;
}
__device__ __forceinline__ ull mul2(ull a, ull b) {
  ull d;
  asm("mul.rn.f32x2 %0,%1,%2;" : "=l"(d) : "l"(a), "l"(b));
  return d;
}
__device__ __forceinline__ ull pk(float lo, float hi) {
  ull r;
  asm("mov.b64 %0,{%1,%2};" : "=l"(r) : "f"(lo), "f"(hi));
  return r;
}
__device__ __forceinline__ ull dupf(float v) {
  ull r;
  asm("mov.b64 %0,{%1,%1};" : "=l"(r) : "f"(v));
  return r;
}
__device__ __forceinline__ float2 upk(ull a) {
  float2 r;
  asm("mov.b64 {%0,%1},%2;" : "=f"(r.x), "=f"(r.y) : "l"(a));
  return r;
}

__device__ __forceinline__ float fast_exp2(float x) {
  x = fmaxf(x, -125.0f);
  float t = x + 12582912.0f;
  int e = __float_as_int(t) - 0x4B400000;
  float f = x - (t - 12582912.0f);
  float p =        1.3333558e-3f;
  p = fmaf(p, f,   9.6181291e-3f);
  p = fmaf(p, f,   5.5504109e-2f);
  p = fmaf(p, f,   2.4022651e-1f);
  p = fmaf(p, f,   6.9314718e-1f);
  p = fmaf(p, f,   1.0f);
  return __int_as_float(__float_as_int(p) + (e << 23));
}

__device__ __forceinline__ float redsum16(float v) {
  v += __shfl_xor_sync(0xffffffffu, v, 8);
  v += __shfl_xor_sync(0xffffffffu, v, 4);
  v += __shfl_xor_sync(0xffffffffu, v, 2);
  v += __shfl_xor_sync(0xffffffffu, v, 1);
  return v;
}
__device__ __forceinline__ float redmax16(float v) {
  v = fmaxf(v, __shfl_xor_sync(0xffffffffu, v, 8));
  v = fmaxf(v, __shfl_xor_sync(0xffffffffu, v, 4));
  v = fmaxf(v, __shfl_xor_sync(0xffffffffu, v, 2));
  v = fmaxf(v, __shfl_xor_sync(0xffffffffu, v, 1));
  return v;
}

// ---------------- lambda ----------------
__global__ void lambda_kernel(const float* __restrict__ lq1,
                              const float* __restrict__ lq2,
                              const float* __restrict__ lk1,
                              const float* __restrict__ lk2) {
  __shared__ float sh1[64], sh2[64];
  int t = threadIdx.x;
  sh1[t] = lq1[t] * lk1[t];
  sh2[t] = lq2[t] * lk2[t];
  __syncthreads();
  if (t == 0) {
    float a = 0.f, c = 0.f;
    for (int i = 0; i < 64; i++) { a += sh1[i]; c += sh2[i]; }
    g_lam = expf(a) - expf(c) + LAMBDA_INIT_F;
  }
}

// ---------------- LN stats ----------------
__global__ void stats_kernel(const float* __restrict__ x) {
  int row = blockIdx.x * 8 + threadIdx.y;
  const float4* xr = (const float4*)(x + (size_t)row * 1024);
  float s = 0.f, ss = 0.f;
  for (int i = threadIdx.x; i < 256; i += 32) {
    float4 v = xr[i];
    s += v.x + v.y + v.z + v.w;
    ss += v.x * v.x + v.y * v.y + v.z * v.z + v.w * v.w;
  }
#pragma unroll
  for (int o = 16; o > 0; o >>= 1) {
    s += __shfl_xor_sync(0xffffffffu, s, o);
    ss += __shfl_xor_sync(0xffffffffu, ss, o);
  }
  if (threadIdx.x == 0) {
    float mean = s * (1.0f / 1024.0f);
    float var = fmaf(-mean, mean, ss * (1.0f / 1024.0f));
    g_stats[row * 2 + 0] = mean;
    g_stats[row * 2 + 1] = rsqrtf(var + 1e-5f);
  }
}

// ---------------- LN-fused projection GEMM (f32x2, reg-side dup) ----------------
struct ProjParams {
  const float* x;
  const float* W[3][3];
  const float* g[3];
  const float* bta[3];
};

__global__ __launch_bounds__(256, 2) void proj_kernel(ProjParams p) {
  __shared__ float As[16][68];    // [k][row] normalized-x transposed (scalar)
  __shared__ float Bs[16][132];   // [k][col]
  __shared__ float mean_s[64], rstd_s[64];

  const int tile = blockIdx.x, bb = blockIdx.y, mat = blockIdx.z;
  const int seg = tile < 2 ? 0 : (tile < 34 ? 1 : 2);
  const float* __restrict__ W = p.W[mat][seg];
  const float* __restrict__ gg = p.g[seg];
  const float* __restrict__ bz = p.bta[seg];
  const int row0 = bb * Tn + tile * 64;
  const int tid = threadIdx.x;

  if (tid < 64) {
    mean_s[tid] = g_stats[(row0 + tid) * 2 + 0];
    rstd_s[tid] = g_stats[(row0 + tid) * 2 + 1];
  }

  const int rg = tid >> 4, ct = tid & 15;
  const int r0 = rg * 4, cc0 = ct * 8;
  const int ar = tid >> 2, ak = (tid & 3) * 4;

  ull acc[4][4];
#pragma unroll
  for (int i = 0; i < 4; i++)
#pragma unroll
    for (int j = 0; j < 4; j++) acc[i][j] = pk(0.f, 0.f);

  for (int k0 = 0; k0 < 1024; k0 += 16) {
    __syncthreads();
    {
      float4 v = *(const float4*)&p.x[(size_t)(row0 + ar) * 1024 + k0 + ak];
      float mn = mean_s[ar], rs = rstd_s[ar];
      As[ak + 0][ar] = (v.x - mn) * rs * gg[k0 + ak + 0] + bz[k0 + ak + 0];
      As[ak + 1][ar] = (v.y - mn) * rs * gg[k0 + ak + 1] + bz[k0 + ak + 1];
      As[ak + 2][ar] = (v.z - mn) * rs * gg[k0 + ak + 2] + bz[k0 + ak + 2];
      As[ak + 3][ar] = (v.w - mn) * rs * gg[k0 + ak + 3] + bz[k0 + ak + 3];
      float4 w0 = *(const float4*)&W[(size_t)(k0 + rg) * 128 + cc0];
      float4 w1 = *(const float4*)&W[(size_t)(k0 + rg) * 128 + cc0 + 4];
      *(float4*)&Bs[rg][cc0] = w0;
      *(float4*)&Bs[rg][cc0 + 4] = w1;
    }
    __syncthreads();
#pragma unroll
    for (int kk = 0; kk < 16; kk++) {
      float4 a4 = *(const float4*)&As[kk][r0];
      ulonglong2 b01 = *(const ulonglong2*)&Bs[kk][cc0];
      ulonglong2 b23 = *(const ulonglong2*)&Bs[kk][cc0 + 4];
      ull a0 = dupf(a4.x), a1 = dupf(a4.y), a2 = dupf(a4.z), a3 = dupf(a4.w);
      acc[0][0] = fma2(a0, b01.x, acc[0][0]); acc[0][1] = fma2(a0, b01.y, acc[0][1]);
      acc[0][2] = fma2(a0, b23.x, acc[0][2]); acc[0][3] = fma2(a0, b23.y, acc[0][3]);
      acc[1][0] = fma2(a1, b01.x, acc[1][0]); acc[1][1] = fma2(a1, b01.y, acc[1][1]);
      acc[1][2] = fma2(a1, b23.x, acc[1][2]); acc[1][3] = fma2(a1, b23.y, acc[1][3]);
      acc[2][0] = fma2(a2, b01.x, acc[2][0]); acc[2][1] = fma2(a2, b01.y, acc[2][1]);
      acc[2][2] = fma2(a2, b23.x, acc[2][2]); acc[2][3] = fma2(a2, b23.y, acc[2][3]);
      acc[3][0] = fma2(a3, b01.x, acc[3][0]); acc[3][1] = fma2(a3, b01.y, acc[3][1]);
      acc[3][2] = fma2(a3, b23.x, acc[3][2]); acc[3][3] = fma2(a3, b23.y, acc[3][3]);
    }
  }

  float* __restrict__ outp = (mat == 0) ? g_q : (mat == 1) ? g_k : g_v;
#pragma unroll
  for (int i = 0; i < 4; i++) {
    float2 c0v = upk(acc[i][0]), c1v = upk(acc[i][1]);
    float2 c2v = upk(acc[i][2]), c3v = upk(acc[i][3]);
    size_t off = (size_t)(row0 + r0 + i) * 128 + cc0;
    *(float4*)&outp[off]     = make_float4(c0v.x, c0v.y, c1v.x, c1v.y);
    *(float4*)&outp[off + 4] = make_float4(c2v.x, c2v.y, c3v.x, c3v.y);
  }
}

// ---------------- dual flash attention (f32x2, reg-side dup) ----------------
// smem identical to the R2 scalar layout — no duplication anywhere.
constexpr int ATTN_SMEM_FLOATS = 6 * 4352 + 64 * 132;   // 34560
constexpr int ATTN_SMEM_BYTES = ATTN_SMEM_FLOATS * 4;   // 138240

__global__ __launch_bounds__(256, 1) void attn_kernel(
    const float* __restrict__ gam, const float* __restrict__ bet,
    float* __restrict__ out) {
  extern __shared__ float sm[];
  float* Qs1 = sm;                 // [d][r] 64x68
  float* Qs2 = sm + 4352;
  float* Ks1 = sm + 2 * 4352;      // [d][c]
  float* Ks2 = sm + 3 * 4352;
  float* Ps1 = sm + 4 * 4352;      // [c][r]
  float* Ps2 = sm + 5 * 4352;
  float* Vs  = sm + 6 * 4352;      // [c][cv] 64x132

  const int tid = threadIdx.x;
  const int rg = tid >> 4, ct = tid & 15;
  const int r0 = rg * 4, c0 = ct * 4, cv0 = ct * 8;
  const size_t base = (size_t)blockIdx.y * Tn;
  const float lam = g_lam;
  const float4 gv0 = *(const float4*)&gam[cv0];
  const float4 gv1 = *(const float4*)&gam[cv0 + 4];
  const float4 bv0 = *(const float4*)&bet[cv0];
  const float4 bv1 = *(const float4*)&bet[cv0 + 4];

  for (int half = 0; half < 2; half++) {
    const int qt = half ? (35 - (int)blockIdx.x) : (int)blockIdx.x;
    const int q0 = qt * 64;

    __syncthreads();
    // load Q tile transposed (scalar): Qs[d][r]
    for (int i = tid; i < 2048; i += 256) {
      int r = i >> 5, quad = i & 31;
      float4 v = *(const float4*)&g_q[(base + q0 + r) * 128 + quad * 4];
      float* dst = (quad < 16) ? Qs1 : Qs2;
      int dd = (quad * 4) & 63;
      dst[(dd + 0) * 68 + r] = v.x;
      dst[(dd + 1) * 68 + r] = v.y;
      dst[(dd + 2) * 68 + r] = v.z;
      dst[(dd + 3) * 68 + r] = v.w;
    }

    ull O1[4][4], O2[4][4];          // [row][colpair]
    float m1[4], m2[4], l1[4], l2[4];
#pragma unroll
    for (int i = 0; i < 4; i++) {
      m1[i] = m2[i] = -3.0e38f;
      l1[i] = l2[i] = 0.f;
#pragma unroll
      for (int j = 0; j < 4; j++) { O1[i][j] = pk(0.f, 0.f); O2[i][j] = pk(0.f, 0.f); }
    }

    for (int kt = 0; kt <= qt; kt++) {
      const int k0 = kt * 64;
      __syncthreads();
      for (int i = tid; i < 2048; i += 256) {
        int c = i >> 5, quad = i & 31;
        float4 kv = *(const float4*)&g_k[(base + k0 + c) * 128 + quad * 4];
        float* dst = (quad < 16) ? Ks1 : Ks2;
        int dd = (quad * 4) & 63;
        dst[(dd + 0) * 68 + c] = kv.x;
        dst[(dd + 1) * 68 + c] = kv.y;
        dst[(dd + 2) * 68 + c] = kv.z;
        dst[(dd + 3) * 68 + c] = kv.w;
        float4 vv = *(const float4*)&g_v[(base + k0 + c) * 128 + quad * 4];
        *(float4*)&Vs[c * 132 + quad * 4] = vv;
      }
      __syncthreads();

      // ----- S = Q K^T : rows scalar (dup in regs), cols packed -----
      ull s1p[4][2], s2p[4][2];
#pragma unroll
      for (int i = 0; i < 4; i++)
#pragma unroll
        for (int j = 0; j < 2; j++) { s1p[i][j] = pk(0.f, 0.f); s2p[i][j] = pk(0.f, 0.f); }

      for (int d = 0; d < 64; d++) {
        float4 qa = *(const float4*)&Qs1[d * 68 + r0];
        float4 qb = *(const float4*)&Qs2[d * 68 + r0];
        ulonglong2 ka = *(const ulonglong2*)&Ks1[d * 68 + c0];
        ulonglong2 kb = *(const ulonglong2*)&Ks2[d * 68 + c0];
        ull qa0 = dupf(qa.x), qa1 = dupf(qa.y), qa2 = dupf(qa.z), qa3 = dupf(qa.w);
        ull qb0 = dupf(qb.x), qb1 = dupf(qb.y), qb2 = dupf(qb.z), qb3 = dupf(qb.w);
        s1p[0][0] = fma2(qa0, ka.x, s1p[0][0]); s1p[0][1] = fma2(qa0, ka.y, s1p[0][1]);
        s1p[1][0] = fma2(qa1, ka.x, s1p[1][0]); s1p[1][1] = fma2(qa1, ka.y, s1p[1][1]);
        s1p[2][0] = fma2(qa2, ka.x, s1p[2][0]); s1p[2][1] = fma2(qa2, ka.y, s1p[2][1]);
        s1p[3][0] = fma2(qa3, ka.x, s1p[3][0]); s1p[3][1] = fma2(qa3, ka.y, s1p[3][1]);
        s2p[0][0] = fma2(qb0, kb.x, s2p[0][0]); s2p[0][1] = fma2(qb0, kb.y, s2p[0][1]);
        s2p[1][0] = fma2(qb1, kb.x, s2p[1][0]); s2p[1][1] = fma2(qb1, kb.y, s2p[1][1]);
        s2p[2][0] = fma2(qb2, kb.x, s2p[2][0]); s2p[2][1] = fma2(qb2, kb.y, s2p[2][1]);
        s2p[3][0] = fma2(qb3, kb.x, s2p[3][0]); s2p[3][1] = fma2(qb3, kb.y, s2p[3][1]);
      }

      const bool diag = (kt == qt);
      float p1[4][4], p2[4][4];
#pragma unroll
      for (int i = 0; i < 4; i++) {
        float2 sa0 = upk(s1p[i][0]), sa1 = upk(s1p[i][1]);
        float2 sb0 = upk(s2p[i][0]), sb1 = upk(s2p[i][1]);
        float s1[4] = {sa0.x, sa0.y, sa1.x, sa1.y};
        float s2[4] = {sb0.x, sb0.y, sb1.x, sb1.y};
        float mx1 = -3.0e38f, mx2 = -3.0e38f;
#pragma unroll
        for (int j = 0; j < 4; j++) {
          float a = s1[j] * QSCALE;
          float b = s2[j] * QSCALE;
          if (diag && (c0 + j) > (r0 + i)) { a = -3.0e38f; b = -3.0e38f; }
          s1[j] = a; s2[j] = b;
          mx1 = fmaxf(mx1, a); mx2 = fmaxf(mx2, b);
        }
        mx1 = redmax16(mx1);
        mx2 = redmax16(mx2);
        float mn1 = fmaxf(m1[i], mx1), mn2 = fmaxf(m2[i], mx2);
        float al1 = fast_exp2(m1[i] - mn1), al2 = fast_exp2(m2[i] - mn2);
        m1[i] = mn1; m2[i] = mn2;
        float su1 = 0.f, su2 = 0.f;
#pragma unroll
        for (int j = 0; j < 4; j++) {
          float e1 = fast_exp2(s1[j] - mn1);
          float e2 = fast_exp2(s2[j] - mn2);
          p1[i][j] = e1; p2[i][j] = e2;
          su1 += e1; su2 += e2;
        }
        su1 = redsum16(su1);
        su2 = redsum16(su2);
        l1[i] = l1[i] * al1 + su1;
        l2[i] = l2[i] * al2 + su2;
        ull al1p = dupf(al1), al2p = dupf(al2);
#pragma unroll
        for (int j = 0; j < 4; j++) {
          O1[i][j] = mul2(O1[i][j], al1p);
          O2[i][j] = mul2(O2[i][j], al2p);
        }
      }
      // store P transposed (scalar, no dup): Ps[c][r]
#pragma unroll
      for (int j = 0; j < 4; j++) {
        *(float4*)&Ps1[(c0 + j) * 68 + r0] =
            make_float4(p1[0][j], p1[1][j], p1[2][j], p1[3][j]);
        *(float4*)&Ps2[(c0 + j) * 68 + r0] =
            make_float4(p2[0][j], p2[1][j], p2[2][j], p2[3][j]);
      }
      __syncthreads();

      // ----- O += P V : rows scalar (dup in regs), v-cols packed -----
      for (int c = 0; c < 64; c++) {
        float4 pa = *(const float4*)&Ps1[c * 68 + r0];
        float4 pb = *(const float4*)&Ps2[c * 68 + r0];
        ulonglong2 va = *(const ulonglong2*)&Vs[c * 132 + cv0];
        ulonglong2 vb = *(const ulonglong2*)&Vs[c * 132 + cv0 + 4];
        ull pa0 = dupf(pa.x), pa1 = dupf(pa.y), pa2 = dupf(pa.z), pa3 = dupf(pa.w);
        ull pb0 = dupf(pb.x), pb1 = dupf(pb.y), pb2 = dupf(pb.z), pb3 = dupf(pb.w);
        O1[0][0] = fma2(pa0, va.x, O1[0][0]); O1[0][1] = fma2(pa0, va.y, O1[0][1]);
        O1[0][2] = fma2(pa0, vb.x, O1[0][2]); O1[0][3] = fma2(pa0, vb.y, O1[0][3]);
        O1[1][0] = fma2(pa1, va.x, O1[1][0]); O1[1][1] = fma2(pa1, va.y, O1[1][1]);
        O1[1][2] = fma2(pa1, vb.x, O1[1][2]); O1[1][3] = fma2(pa1, vb.y, O1[1][3]);
        O1[2][0] = fma2(pa2, va.x, O1[2][0]); O1[2][1] = fma2(pa2, va.y, O1[2][1]);
        O1[2][2] = fma2(pa2, vb.x, O1[2][2]); O1[2][3] = fma2(pa2, vb.y, O1[2][3]);
        O1[3][0] = fma2(pa3, va.x, O1[3][0]); O1[3][1] = fma2(pa3, va.y, O1[3][1]);
        O1[3][2] = fma2(pa3, vb.x, O1[3][2]); O1[3][3] = fma2(pa3, vb.y, O1[3][3]);
        O2[0][0] = fma2(pb0, va.x, O2[0][0]); O2[0][1] = fma2(pb0, va.y, O2[0][1]);
        O2[0][2] = fma2(pb0, vb.x, O2[0][2]); O2[0][3] = fma2(pb0, vb.y, O2[0][3]);
        O2[1][0] = fma2(pb1, va.x, O2[1][0]); O2[1][1] = fma2(pb1, va.y, O2[1][1]);
        O2[1][2] = fma2(pb1, vb.x, O2[1][2]); O2[1][3] = fma2(pb1, vb.y, O2[1][3]);
        O2[2][0] = fma2(pb2, va.x, O2[2][0]); O2[2][1] = fma2(pb2, va.y, O2[2][1]);
        O2[2][2] = fma2(pb2, vb.x, O2[2][2]); O2[2][3] = fma2(pb2, vb.y, O2[2][3]);
        O2[3][0] = fma2(pb3, va.x, O2[3][0]); O2[3][1] = fma2(pb3, va.y, O2[3][1]);
        O2[3][2] = fma2(pb3, vb.x, O2[3][2]); O2[3][3] = fma2(pb3, vb.y, O2[3][3]);
      }
    }

    // epilogue: combine + output LN
#pragma unroll
    for (int i = 0; i < 4; i++) {
      float inv1 = 1.0f / l1[i], inv2 = lam / l2[i];
      float att[8];
      float s = 0.f;
#pragma unroll
      for (int j = 0; j < 4; j++) {
        float2 o1 = upk(O1[i][j]);
        float2 o2 = upk(O2[i][j]);
        att[2 * j + 0] = o1.x * inv1 - o2.x * inv2;
        att[2 * j + 1] = o1.y * inv1 - o2.y * inv2;
        s += att[2 * j] + att[2 * j + 1];
      }
      float mean = redsum16(s) * (1.0f / 128.0f);
      float vs = 0.f;
#pragma unroll
      for (int j = 0; j < 8; j++) {
        float d = att[j] - mean;
        vs += d * d;
      }
      float var = redsum16(vs) * (1.0f / 128.0f);
      float rstd = rsqrtf(var + 1e-5f);
      float g8[8] = {gv0.x, gv0.y, gv0.z, gv0.w, gv1.x, gv1.y, gv1.z, gv1.w};
      float b8[8] = {bv0.x, bv0.y, bv0.z, bv0.w, bv1.x, bv1.y, bv1.z, bv1.w};
      float o[8];
#pragma unroll
      for (int j = 0; j < 8; j++)
        o[j] = (att[j] - mean) * rstd * g8[j] + b8[j];
      size_t off = (base + q0 + r0 + i) * 128 + cv0;
      *(float4*)&out[off]     = make_float4(o[0], o[1], o[2], o[3]);
      *(float4*)&out[off + 4] = make_float4(o[4], o[5], o[6], o[7]);
    }
  }
}

// ---------------- launch ----------------
extern "C" void kernel_launch(void* const* d_in, const int* in_sizes, int n_in,
                              void* d_out, int out_size) {
  const float* x     = (const float*)d_in[0];
  const float* Wq    = (const float*)d_in[1];
  const float* Wk    = (const float*)d_in[2];
  const float* Wv    = (const float*)d_in[3];
  const float* Wq_ss = (const float*)d_in[4];
  const float* Wk_ss = (const float*)d_in[5];
  const float* Wv_ss = (const float*)d_in[6];
  const float* Wq_se = (const float*)d_in[7];
  const float* Wk_se = (const float*)d_in[8];
  const float* Wv_se = (const float*)d_in[9];
  const float* g_in  = (const float*)d_in[10];
  const float* b_in  = (const float*)d_in[11];
  const float* g_ss  = (const float*)d_in[12];
  const float* b_ss  = (const float*)d_in[13];
  const float* g_se  = (const float*)d_in[14];
  const float* b_se  = (const float*)d_in[15];
  const float* g_out = (const float*)d_in[16];
  const float* b_out = (const float*)d_in[17];
  const float* lq1   = (const float*)d_in[18];
  const float* lq2   = (const float*)d_in[19];
  const float* lk1   = (const float*)d_in[20];
  const float* lk2   = (const float*)d_in[21];

  static bool attr_set = false;
  if (!attr_set) {
    cudaFuncSetAttribute(attn_kernel, cudaFuncAttributeMaxDynamicSharedMemorySize,
                         ATTN_SMEM_BYTES);
    attr_set = true;
  }

  lambda_kernel<<<1, 64>>>(lq1, lq2, lk1, lk2);
  stats_kernel<<<NROW / 8, dim3(32, 8)>>>(x);

  ProjParams p;
  p.x = x;
  p.W[0][0] = Wq_ss; p.W[0][1] = Wq; p.W[0][2] = Wq_se;
  p.W[1][0] = Wk_ss; p.W[1][1] = Wk; p.W[1][2] = Wk_se;
  p.W[2][0] = Wv_ss; p.W[2][1] = Wv; p.W[2][2] = Wv_se;
  p.g[0] = g_ss; p.g[1] = g_in; p.g[2] = g_se;
  p.bta[0] = b_ss; p.bta[1] = b_in; p.bta[2] = b_se;
  proj_kernel<<<dim3(36, 8, 3), 256>>>(p);

  attn_kernel<<<dim3(18, 8), 256, ATTN_SMEM_BYTES>>>(g_out, b_out, (float*)d_out);
}

// round 6
// speedup vs baseline: 1.9542x; 1.6902x over previous
#include <cuda_runtime.h>
#include <cuda_bf16.h>
#include <cstdint>
#include <cstddef>

constexpr int Bn = 8;
constexpr int Tn = 2304;
constexpr int NROW = Bn * Tn;          // 18432
constexpr float LAMBDA_INIT_F = 0.6192834728526787f;
constexpr float QSCALE = 0.18033688011112042f;   // (1/8) * log2(e)

typedef unsigned long long ull;

__device__ float g_q[NROW * 128];
__device__ float g_k[NROW * 128];
__device__ float g_v[NROW * 128];
__device__ float g_lam;
__device__ __align__(16) __nv_bfloat16 g_xh[NROW * 1024];
__device__ __align__(16) __nv_bfloat16 g_xl[NROW * 1024];
__device__ __align__(16) __nv_bfloat16 g_wh[9 * 128 * 1024];
__device__ __align__(16) __nv_bfloat16 g_wl[9 * 128 * 1024];

// ---- packed f32x2 helpers ----
__device__ __forceinline__ ull fma2(ull a, ull b, ull c) {
  ull d;
  asm("fma.rn.f32x2 %0,%1,%2,%3;" : "=l"(d) : "l"(a), "l"(b), "l"(c));
  return d;
}
__device__ __forceinline__ ull mul2(ull a, ull b) {
  ull d;
  asm("mul.rn.f32x2 %0,%1,%2;" : "=l"(d) : "l"(a), "l"(b));
  return d;
}
__device__ __forceinline__ ull pk(float lo, float hi) {
  ull r;
  asm("mov.b64 %0,{%1,%2};" : "=l"(r) : "f"(lo), "f"(hi));
  return r;
}
__device__ __forceinline__ ull dupf(float v) {
  ull r;
  asm("mov.b64 %0,{%1,%1};" : "=l"(r) : "f"(v));
  return r;
}
__device__ __forceinline__ float2 upk(ull a) {
  float2 r;
  asm("mov.b64 {%0,%1},%2;" : "=f"(r.x), "=f"(r.y) : "l"(a));
  return r;
}

__device__ __forceinline__ float fast_exp2(float x) {
  x = fmaxf(x, -125.0f);
  float t = x + 12582912.0f;
  int e = __float_as_int(t) - 0x4B400000;
  float f = x - (t - 12582912.0f);
  float p =        1.3333558e-3f;
  p = fmaf(p, f,   9.6181291e-3f);
  p = fmaf(p, f,   5.5504109e-2f);
  p = fmaf(p, f,   2.4022651e-1f);
  p = fmaf(p, f,   6.9314718e-1f);
  p = fmaf(p, f,   1.0f);
  return __int_as_float(__float_as_int(p) + (e << 23));
}

__device__ __forceinline__ float redsum16(float v) {
  v += __shfl_xor_sync(0xffffffffu, v, 8);
  v += __shfl_xor_sync(0xffffffffu, v, 4);
  v += __shfl_xor_sync(0xffffffffu, v, 2);
  v += __shfl_xor_sync(0xffffffffu, v, 1);
  return v;
}
__device__ __forceinline__ float redmax16(float v) {
  v = fmaxf(v, __shfl_xor_sync(0xffffffffu, v, 8));
  v = fmaxf(v, __shfl_xor_sync(0xffffffffu, v, 4));
  v = fmaxf(v, __shfl_xor_sync(0xffffffffu, v, 2));
  v = fmaxf(v, __shfl_xor_sync(0xffffffffu, v, 1));
  return v;
}

__device__ __forceinline__ uint32_t smem_u32(const void* p) {
  uint32_t a;
  asm("{ .reg .u64 t; cvta.to.shared.u64 t, %1; cvt.u32.u64 %0, t; }" : "=r"(a) : "l"(p));
  return a;
}
__device__ __forceinline__ uint32_t sw128(uint32_t off) {
  return off ^ ((off >> 3) & 0x70);
}
__device__ __forceinline__ void cpasync16(uint32_t dst, const void* src) {
  asm volatile("cp.async.cg.shared.global [%0], [%1], 16;" :: "r"(dst), "l"(src));
}
__device__ __forceinline__ void cp_commit() {
  asm volatile("cp.async.commit_group;" ::: "memory");
}
__device__ __forceinline__ void cp_wait1() {
  asm volatile("cp.async.wait_group 1;" ::: "memory");
}
__device__ __forceinline__ void cp_wait0() {
  asm volatile("cp.async.wait_group 0;" ::: "memory");
}
__device__ __forceinline__ void ldsm4(uint32_t* r, uint32_t a) {
  asm volatile("ldmatrix.sync.aligned.m8n8.x4.shared.b16 {%0,%1,%2,%3}, [%4];"
               : "=r"(r[0]), "=r"(r[1]), "=r"(r[2]), "=r"(r[3]) : "r"(a));
}
__device__ __forceinline__ void mma16816(float* d, const uint32_t* a, uint32_t b0, uint32_t b1) {
  asm volatile(
      "mma.sync.aligned.m16n8k16.row.col.f32.bf16.bf16.f32 "
      "{%0,%1,%2,%3},{%4,%5,%6,%7},{%8,%9},{%0,%1,%2,%3};"
      : "+f"(d[0]), "+f"(d[1]), "+f"(d[2]), "+f"(d[3])
      : "r"(a[0]), "r"(a[1]), "r"(a[2]), "r"(a[3]), "r"(b0), "r"(b1));
}

// ---------------- lambda ----------------
__global__ void lambda_kernel(const float* __restrict__ lq1,
                              const float* __restrict__ lq2,
                              const float* __restrict__ lk1,
                              const float* __restrict__ lk2) {
  __shared__ float sh1[64], sh2[64];
  int t = threadIdx.x;
  sh1[t] = lq1[t] * lk1[t];
  sh2[t] = lq2[t] * lk2[t];
  __syncthreads();
  if (t == 0) {
    float a = 0.f, c = 0.f;
    for (int i = 0; i < 64; i++) { a += sh1[i]; c += sh2[i]; }
    g_lam = expf(a) - expf(c) + LAMBDA_INIT_F;
  }
}

// ---------------- LN + bf16 hi/lo split of x ----------------
struct NormParams {
  const float* x;
  const float* g[3];
  const float* b[3];
};

__global__ void norm_split_kernel(NormParams p) {
  int row = blockIdx.x * 8 + threadIdx.y;
  int t = row % Tn;
  int seg = t < 128 ? 0 : (t < 2176 ? 1 : 2);
  const float* __restrict__ gg = p.g[seg];
  const float* __restrict__ bb = p.b[seg];
  int lid = threadIdx.x;
  const float* xr = p.x + (size_t)row * 1024;

  float v[32];
  float s = 0.f, ss = 0.f;
#pragma unroll
  for (int i = 0; i < 8; i++) {
    float4 f = *(const float4*)&xr[i * 128 + lid * 4];
    v[i * 4 + 0] = f.x; v[i * 4 + 1] = f.y; v[i * 4 + 2] = f.z; v[i * 4 + 3] = f.w;
    s += f.x + f.y + f.z + f.w;
    ss += f.x * f.x + f.y * f.y + f.z * f.z + f.w * f.w;
  }
#pragma unroll
  for (int o = 16; o > 0; o >>= 1) {
    s += __shfl_xor_sync(0xffffffffu, s, o);
    ss += __shfl_xor_sync(0xffffffffu, ss, o);
  }
  float mean = s * (1.0f / 1024.0f);
  float var = fmaf(-mean, mean, ss * (1.0f / 1024.0f));
  float rstd = rsqrtf(var + 1e-5f);

  __nv_bfloat16* xh = g_xh + (size_t)row * 1024;
  __nv_bfloat16* xl = g_xl + (size_t)row * 1024;
#pragma unroll
  for (int i = 0; i < 8; i++) {
    int k = i * 128 + lid * 4;
    float4 gf = *(const float4*)&gg[k];
    float4 bf = *(const float4*)&bb[k];
    float a0 = (v[i * 4 + 0] - mean) * rstd * gf.x + bf.x;
    float a1 = (v[i * 4 + 1] - mean) * rstd * gf.y + bf.y;
    float a2 = (v[i * 4 + 2] - mean) * rstd * gf.z + bf.z;
    float a3 = (v[i * 4 + 3] - mean) * rstd * gf.w + bf.w;
    __nv_bfloat162 h01 = {__float2bfloat16_rn(a0), __float2bfloat16_rn(a1)};
    __nv_bfloat162 h23 = {__float2bfloat16_rn(a2), __float2bfloat16_rn(a3)};
    __nv_bfloat162 l01 = {__float2bfloat16_rn(a0 - __bfloat162float(h01.x)),
                          __float2bfloat16_rn(a1 - __bfloat162float(h01.y))};
    __nv_bfloat162 l23 = {__float2bfloat16_rn(a2 - __bfloat162float(h23.x)),
                          __float2bfloat16_rn(a3 - __bfloat162float(h23.y))};
    uint2 hp, lp;
    hp.x = *(uint32_t*)&h01; hp.y = *(uint32_t*)&h23;
    lp.x = *(uint32_t*)&l01; lp.y = *(uint32_t*)&l23;
    *(uint2*)&xh[k] = hp;
    *(uint2*)&xl[k] = lp;
  }
}

// ---------------- weight transpose + bf16 hi/lo split ----------------
struct WPrepParams { const float* W[9]; };

__global__ void wprep_kernel(WPrepParams p) {
  __shared__ float tile[32][33];
  int mat = blockIdx.z;
  const float* __restrict__ W = p.W[mat];
  int kb = blockIdx.x * 32, nb = blockIdx.y * 32;
  int tx = threadIdx.x, ty = threadIdx.y;
  tile[ty][tx] = W[(size_t)(kb + ty) * 128 + nb + tx];
  __syncthreads();
  float v = tile[tx][ty];
  __nv_bfloat16 h = __float2bfloat16_rn(v);
  __nv_bfloat16 l = __float2bfloat16_rn(v - __bfloat162float(h));
  size_t o = (size_t)mat * 128 * 1024 + (size_t)(nb + ty) * 1024 + kb + tx;
  g_wh[o] = h;
  g_wl[o] = l;
}

// ---------------- projection GEMM: mma.sync bf16x3 emulation ----------------
// grid (144, 3): 128-row tile x mat. D[128x128] = LN(x)[128x1024] @ W^T.
// smem: double-buffered {Ah, Al, Bh, Bl}, each 128x64 bf16 (128B rows, SW128).
constexpr int PB_AH = 0;
constexpr int PB_AL = 16384;
constexpr int PB_BH = 32768;
constexpr int PB_BL = 49152;
constexpr int PBUF = 65536;
constexpr int PROJ_SMEM = 2 * PBUF;   // 131072

__global__ __launch_bounds__(256, 1) void proj_mma_kernel() {
  extern __shared__ char smem[];
  uint32_t sb = smem_u32(smem);
  const int tid = threadIdx.x;
  const int rt = blockIdx.x, mat = blockIdx.y;
  const int row0 = rt * 128;
  const int t0 = row0 % Tn;
  const int seg = t0 < 128 ? 0 : (t0 < 2176 ? 1 : 2);
  const size_t wbase = (size_t)(mat * 3 + seg) * 128 * 1024;
  const __nv_bfloat16* __restrict__ Ah_g = g_xh + (size_t)row0 * 1024;
  const __nv_bfloat16* __restrict__ Al_g = g_xl + (size_t)row0 * 1024;
  const __nv_bfloat16* __restrict__ Bh_g = g_wh + wbase;
  const __nv_bfloat16* __restrict__ Bl_g = g_wl + wbase;

  const int lane = tid & 31;
  const int wid = tid >> 5;
  const int wm = (wid & 3) * 32;        // warp row base
  const int wn = (wid >> 2) * 64;       // warp col base
  const int lrow = lane & 7;
  const int sel = lane >> 3;            // 0..3
  const int selm = (sel & 1) * 8;
  const int selc = (sel >> 1) * 16;     // byte col offset within 32B k-step

  float acc[2][8][4];
#pragma unroll
  for (int mt = 0; mt < 2; mt++)
#pragma unroll
    for (int nt = 0; nt < 8; nt++)
#pragma unroll
      for (int j = 0; j < 4; j++) acc[mt][nt][j] = 0.f;

  // issue cp.async loads for chunk ch into buffer b
  auto issue = [&](int ch, int b) {
    const int k0 = ch * 64;
    const uint32_t dst = sb + b * PBUF;
#pragma unroll
    for (int it = 0; it < 4; it++) {
      int i = tid + it * 256;
      int r = i >> 3, c = i & 7;
      uint32_t d = sw128((uint32_t)(r * 128 + c * 16));
      size_t go = (size_t)r * 1024 + k0 + c * 8;
      cpasync16(dst + PB_AH + d, Ah_g + go);
      cpasync16(dst + PB_AL + d, Al_g + go);
      cpasync16(dst + PB_BH + d, Bh_g + go);
      cpasync16(dst + PB_BL + d, Bl_g + go);
    }
  };

  issue(0, 0);
  cp_commit();

  for (int ch = 0; ch < 16; ch++) {
    if (ch + 1 < 16) {
      issue(ch + 1, (ch + 1) & 1);
      cp_commit();
      cp_wait1();
    } else {
      cp_wait0();
    }
    __syncthreads();

    const uint32_t base = sb + (ch & 1) * PBUF;
#pragma unroll
    for (int ks = 0; ks < 4; ks++) {
      const int colb = ks * 32 + selc;
      uint32_t ah[2][4], al[2][4];
#pragma unroll
      for (int mt = 0; mt < 2; mt++) {
        int r = wm + mt * 16 + selm + lrow;
        uint32_t off = sw128((uint32_t)(r * 128 + colb));
        ldsm4(ah[mt], base + PB_AH + off);
        ldsm4(al[mt], base + PB_AL + off);
      }
      uint32_t bh[8][2], bl[8][2];
#pragma unroll
      for (int np = 0; np < 4; np++) {
        int r = wn + np * 16 + selm + lrow;
        uint32_t off = sw128((uint32_t)(r * 128 + colb));
        uint32_t t4[4];
        ldsm4(t4, base + PB_BH + off);
        bh[2 * np][0] = t4[0]; bh[2 * np][1] = t4[2];
        bh[2 * np + 1][0] = t4[1]; bh[2 * np + 1][1] = t4[3];
        ldsm4(t4, base + PB_BL + off);
        bl[2 * np][0] = t4[0]; bl[2 * np][1] = t4[2];
        bl[2 * np + 1][0] = t4[1]; bl[2 * np + 1][1] = t4[3];
      }
#pragma unroll
      for (int mt = 0; mt < 2; mt++)
#pragma unroll
        for (int nt = 0; nt < 8; nt++) {
          mma16816(acc[mt][nt], ah[mt], bh[nt][0], bh[nt][1]);
          mma16816(acc[mt][nt], ah[mt], bl[nt][0], bl[nt][1]);
          mma16816(acc[mt][nt], al[mt], bh[nt][0], bh[nt][1]);
        }
    }
    __syncthreads();
  }

  float* __restrict__ outp = (mat == 0) ? g_q : (mat == 1) ? g_k : g_v;
  const int orow = lane >> 2, ocol = (lane & 3) * 2;
#pragma unroll
  for (int mt = 0; mt < 2; mt++)
#pragma unroll
    for (int nt = 0; nt < 8; nt++) {
      int r = row0 + wm + mt * 16 + orow;
      int c = wn + nt * 8 + ocol;
      *(float2*)&outp[(size_t)r * 128 + c] = make_float2(acc[mt][nt][0], acc[mt][nt][1]);
      *(float2*)&outp[(size_t)(r + 8) * 128 + c] = make_float2(acc[mt][nt][2], acc[mt][nt][3]);
    }
}

// ---------------- dual flash attention (f32x2, reg-side dup) — unchanged R4 ----------------
constexpr int ATTN_SMEM_FLOATS = 6 * 4352 + 64 * 132;
constexpr int ATTN_SMEM_BYTES = ATTN_SMEM_FLOATS * 4;   // 138240

__global__ __launch_bounds__(256, 1) void attn_kernel(
    const float* __restrict__ gam, const float* __restrict__ bet,
    float* __restrict__ out) {
  extern __shared__ float sm[];
  float* Qs1 = sm;
  float* Qs2 = sm + 4352;
  float* Ks1 = sm + 2 * 4352;
  float* Ks2 = sm + 3 * 4352;
  float* Ps1 = sm + 4 * 4352;
  float* Ps2 = sm + 5 * 4352;
  float* Vs  = sm + 6 * 4352;

  const int tid = threadIdx.x;
  const int rg = tid >> 4, ct = tid & 15;
  const int r0 = rg * 4, c0 = ct * 4, cv0 = ct * 8;
  const size_t base = (size_t)blockIdx.y * Tn;
  const float lam = g_lam;
  const float4 gv0 = *(const float4*)&gam[cv0];
  const float4 gv1 = *(const float4*)&gam[cv0 + 4];
  const float4 bv0 = *(const float4*)&bet[cv0];
  const float4 bv1 = *(const float4*)&bet[cv0 + 4];

  for (int half = 0; half < 2; half++) {
    const int qt = half ? (35 - (int)blockIdx.x) : (int)blockIdx.x;
    const int q0 = qt * 64;

    __syncthreads();
    for (int i = tid; i < 2048; i += 256) {
      int r = i >> 5, quad = i & 31;
      float4 v = *(const float4*)&g_q[(base + q0 + r) * 128 + quad * 4];
      float* dst = (quad < 16) ? Qs1 : Qs2;
      int dd = (quad * 4) & 63;
      dst[(dd + 0) * 68 + r] = v.x;
      dst[(dd + 1) * 68 + r] = v.y;
      dst[(dd + 2) * 68 + r] = v.z;
      dst[(dd + 3) * 68 + r] = v.w;
    }

    ull O1[4][4], O2[4][4];
    float m1[4], m2[4], l1[4], l2[4];
#pragma unroll
    for (int i = 0; i < 4; i++) {
      m1[i] = m2[i] = -3.0e38f;
      l1[i] = l2[i] = 0.f;
#pragma unroll
      for (int j = 0; j < 4; j++) { O1[i][j] = pk(0.f, 0.f); O2[i][j] = pk(0.f, 0.f); }
    }

    for (int kt = 0; kt <= qt; kt++) {
      const int k0 = kt * 64;
      __syncthreads();
      for (int i = tid; i < 2048; i += 256) {
        int c = i >> 5, quad = i & 31;
        float4 kv = *(const float4*)&g_k[(base + k0 + c) * 128 + quad * 4];
        float* dst = (quad < 16) ? Ks1 : Ks2;
        int dd = (quad * 4) & 63;
        dst[(dd + 0) * 68 + c] = kv.x;
        dst[(dd + 1) * 68 + c] = kv.y;
        dst[(dd + 2) * 68 + c] = kv.z;
        dst[(dd + 3) * 68 + c] = kv.w;
        float4 vv = *(const float4*)&g_v[(base + k0 + c) * 128 + quad * 4];
        *(float4*)&Vs[c * 132 + quad * 4] = vv;
      }
      __syncthreads();

      ull s1p[4][2], s2p[4][2];
#pragma unroll
      for (int i = 0; i < 4; i++)
#pragma unroll
        for (int j = 0; j < 2; j++) { s1p[i][j] = pk(0.f, 0.f); s2p[i][j] = pk(0.f, 0.f); }

      for (int d = 0; d < 64; d++) {
        float4 qa = *(const float4*)&Qs1[d * 68 + r0];
        float4 qb = *(const float4*)&Qs2[d * 68 + r0];
        ulonglong2 ka = *(const ulonglong2*)&Ks1[d * 68 + c0];
        ulonglong2 kb = *(const ulonglong2*)&Ks2[d * 68 + c0];
        ull qa0 = dupf(qa.x), qa1 = dupf(qa.y), qa2 = dupf(qa.z), qa3 = dupf(qa.w);
        ull qb0 = dupf(qb.x), qb1 = dupf(qb.y), qb2 = dupf(qb.z), qb3 = dupf(qb.w);
        s1p[0][0] = fma2(qa0, ka.x, s1p[0][0]); s1p[0][1] = fma2(qa0, ka.y, s1p[0][1]);
        s1p[1][0] = fma2(qa1, ka.x, s1p[1][0]); s1p[1][1] = fma2(qa1, ka.y, s1p[1][1]);
        s1p[2][0] = fma2(qa2, ka.x, s1p[2][0]); s1p[2][1] = fma2(qa2, ka.y, s1p[2][1]);
        s1p[3][0] = fma2(qa3, ka.x, s1p[3][0]); s1p[3][1] = fma2(qa3, ka.y, s1p[3][1]);
        s2p[0][0] = fma2(qb0, kb.x, s2p[0][0]); s2p[0][1] = fma2(qb0, kb.y, s2p[0][1]);
        s2p[1][0] = fma2(qb1, kb.x, s2p[1][0]); s2p[1][1] = fma2(qb1, kb.y, s2p[1][1]);
        s2p[2][0] = fma2(qb2, kb.x, s2p[2][0]); s2p[2][1] = fma2(qb2, kb.y, s2p[2][1]);
        s2p[3][0] = fma2(qb3, kb.x, s2p[3][0]); s2p[3][1] = fma2(qb3, kb.y, s2p[3][1]);
      }

      const bool diag = (kt == qt);
      float p1[4][4], p2[4][4];
#pragma unroll
      for (int i = 0; i < 4; i++) {
        float2 sa0 = upk(s1p[i][0]), sa1 = upk(s1p[i][1]);
        float2 sb0 = upk(s2p[i][0]), sb1 = upk(s2p[i][1]);
        float s1[4] = {sa0.x, sa0.y, sa1.x, sa1.y};
        float s2[4] = {sb0.x, sb0.y, sb1.x, sb1.y};
        float mx1 = -3.0e38f, mx2 = -3.0e38f;
#pragma unroll
        for (int j = 0; j < 4; j++) {
          float a = s1[j] * QSCALE;
          float b = s2[j] * QSCALE;
          if (diag && (c0 + j) > (r0 + i)) { a = -3.0e38f; b = -3.0e38f; }
          s1[j] = a; s2[j] = b;
          mx1 = fmaxf(mx1, a); mx2 = fmaxf(mx2, b);
        }
        mx1 = redmax16(mx1);
        mx2 = redmax16(mx2);
        float mn1 = fmaxf(m1[i], mx1), mn2 = fmaxf(m2[i], mx2);
        float al1 = fast_exp2(m1[i] - mn1), al2 = fast_exp2(m2[i] - mn2);
        m1[i] = mn1; m2[i] = mn2;
        float su1 = 0.f, su2 = 0.f;
#pragma unroll
        for (int j = 0; j < 4; j++) {
          float e1 = fast_exp2(s1[j] - mn1);
          float e2 = fast_exp2(s2[j] - mn2);
          p1[i][j] = e1; p2[i][j] = e2;
          su1 += e1; su2 += e2;
        }
        su1 = redsum16(su1);
        su2 = redsum16(su2);
        l1[i] = l1[i] * al1 + su1;
        l2[i] = l2[i] * al2 + su2;
        ull al1p = dupf(al1), al2p = dupf(al2);
#pragma unroll
        for (int j = 0; j < 4; j++) {
          O1[i][j] = mul2(O1[i][j], al1p);
          O2[i][j] = mul2(O2[i][j], al2p);
        }
      }
#pragma unroll
      for (int j = 0; j < 4; j++) {
        *(float4*)&Ps1[(c0 + j) * 68 + r0] =
            make_float4(p1[0][j], p1[1][j], p1[2][j], p1[3][j]);
        *(float4*)&Ps2[(c0 + j) * 68 + r0] =
            make_float4(p2[0][j], p2[1][j], p2[2][j], p2[3][j]);
      }
      __syncthreads();

      for (int c = 0; c < 64; c++) {
        float4 pa = *(const float4*)&Ps1[c * 68 + r0];
        float4 pb = *(const float4*)&Ps2[c * 68 + r0];
        ulonglong2 va = *(const ulonglong2*)&Vs[c * 132 + cv0];
        ulonglong2 vb = *(const ulonglong2*)&Vs[c * 132 + cv0 + 4];
        ull pa0 = dupf(pa.x), pa1 = dupf(pa.y), pa2 = dupf(pa.z), pa3 = dupf(pa.w);
        ull pb0 = dupf(pb.x), pb1 = dupf(pb.y), pb2 = dupf(pb.z), pb3 = dupf(pb.w);
        O1[0][0] = fma2(pa0, va.x, O1[0][0]); O1[0][1] = fma2(pa0, va.y, O1[0][1]);
        O1[0][2] = fma2(pa0, vb.x, O1[0][2]); O1[0][3] = fma2(pa0, vb.y, O1[0][3]);
        O1[1][0] = fma2(pa1, va.x, O1[1][0]); O1[1][1] = fma2(pa1, va.y, O1[1][1]);
        O1[1][2] = fma2(pa1, vb.x, O1[1][2]); O1[1][3] = fma2(pa1, vb.y, O1[1][3]);
        O1[2][0] = fma2(pa2, va.x, O1[2][0]); O1[2][1] = fma2(pa2, va.y, O1[2][1]);
        O1[2][2] = fma2(pa2, vb.x, O1[2][2]); O1[2][3] = fma2(pa2, vb.y, O1[2][3]);
        O1[3][0] = fma2(pa3, va.x, O1[3][0]); O1[3][1] = fma2(pa3, va.y, O1[3][1]);
        O1[3][2] = fma2(pa3, vb.x, O1[3][2]); O1[3][3] = fma2(pa3, vb.y, O1[3][3]);
        O2[0][0] = fma2(pb0, va.x, O2[0][0]); O2[0][1] = fma2(pb0, va.y, O2[0][1]);
        O2[0][2] = fma2(pb0, vb.x, O2[0][2]); O2[0][3] = fma2(pb0, vb.y, O2[0][3]);
        O2[1][0] = fma2(pb1, va.x, O2[1][0]); O2[1][1] = fma2(pb1, va.y, O2[1][1]);
        O2[1][2] = fma2(pb1, vb.x, O2[1][2]); O2[1][3] = fma2(pb1, vb.y, O2[1][3]);
        O2[2][0] = fma2(pb2, va.x, O2[2][0]); O2[2][1] = fma2(pb2, va.y, O2[2][1]);
        O2[2][2] = fma2(pb2, vb.x, O2[2][2]); O2[2][3] = fma2(pb2, vb.y, O2[2][3]);
        O2[3][0] = fma2(pb3, va.x, O2[3][0]); O2[3][1] = fma2(pb3, va.y, O2[3][1]);
        O2[3][2] = fma2(pb3, vb.x, O2[3][2]); O2[3][3] = fma2(pb3, vb.y, O2[3][3]);
      }
    }

#pragma unroll
    for (int i = 0; i < 4; i++) {
      float inv1 = 1.0f / l1[i], inv2 = lam / l2[i];
      float att[8];
      float s = 0.f;
#pragma unroll
      for (int j = 0; j < 4; j++) {
        float2 o1 = upk(O1[i][j]);
        float2 o2 = upk(O2[i][j]);
        att[2 * j + 0] = o1.x * inv1 - o2.x * inv2;
        att[2 * j + 1] = o1.y * inv1 - o2.y * inv2;
        s += att[2 * j] + att[2 * j + 1];
      }
      float mean = redsum16(s) * (1.0f / 128.0f);
      float vs = 0.f;
#pragma unroll
      for (int j = 0; j < 8; j++) {
        float d = att[j] - mean;
        vs += d * d;
      }
      float var = redsum16(vs) * (1.0f / 128.0f);
      float rstd = rsqrtf(var + 1e-5f);
      float g8[8] = {gv0.x, gv0.y, gv0.z, gv0.w, gv1.x, gv1.y, gv1.z, gv1.w};
      float b8[8] = {bv0.x, bv0.y, bv0.z, bv0.w, bv1.x, bv1.y, bv1.z, bv1.w};
      float o[8];
#pragma unroll
      for (int j = 0; j < 8; j++)
        o[j] = (att[j] - mean) * rstd * g8[j] + b8[j];
      size_t off = (base + q0 + r0 + i) * 128 + cv0;
      *(float4*)&out[off]     = make_float4(o[0], o[1], o[2], o[3]);
      *(float4*)&out[off + 4] = make_float4(o[4], o[5], o[6], o[7]);
    }
  }
}

// ---------------- launch ----------------
extern "C" void kernel_launch(void* const* d_in, const int* in_sizes, int n_in,
                              void* d_out, int out_size) {
  const float* x     = (const float*)d_in[0];
  const float* Wq    = (const float*)d_in[1];
  const float* Wk    = (const float*)d_in[2];
  const float* Wv    = (const float*)d_in[3];
  const float* Wq_ss = (const float*)d_in[4];
  const float* Wk_ss = (const float*)d_in[5];
  const float* Wv_ss = (const float*)d_in[6];
  const float* Wq_se = (const float*)d_in[7];
  const float* Wk_se = (const float*)d_in[8];
  const float* Wv_se = (const float*)d_in[9];
  const float* g_in  = (const float*)d_in[10];
  const float* b_in  = (const float*)d_in[11];
  const float* g_ss  = (const float*)d_in[12];
  const float* b_ss  = (const float*)d_in[13];
  const float* g_se  = (const float*)d_in[14];
  const float* b_se  = (const float*)d_in[15];
  const float* g_out = (const float*)d_in[16];
  const float* b_out = (const float*)d_in[17];
  const float* lq1   = (const float*)d_in[18];
  const float* lq2   = (const float*)d_in[19];
  const float* lk1   = (const float*)d_in[20];
  const float* lk2   = (const float*)d_in[21];

  static bool attr_set = false;
  if (!attr_set) {
    cudaFuncSetAttribute(attn_kernel, cudaFuncAttributeMaxDynamicSharedMemorySize,
                         ATTN_SMEM_BYTES);
    cudaFuncSetAttribute(proj_mma_kernel, cudaFuncAttributeMaxDynamicSharedMemorySize,
                         PROJ_SMEM);
    attr_set = true;
  }

  lambda_kernel<<<1, 64>>>(lq1, lq2, lk1, lk2);

  WPrepParams wp;
  wp.W[0] = Wq_ss; wp.W[1] = Wq; wp.W[2] = Wq_se;
  wp.W[3] = Wk_ss; wp.W[4] = Wk; wp.W[5] = Wk_se;
  wp.W[6] = Wv_ss; wp.W[7] = Wv; wp.W[8] = Wv_se;
  wprep_kernel<<<dim3(32, 4, 9), dim3(32, 32)>>>(wp);

  NormParams np;
  np.x = x;
  np.g[0] = g_ss; np.g[1] = g_in; np.g[2] = g_se;
  np.b[0] = b_ss; np.b[1] = b_in; np.b[2] = b_se;
  norm_split_kernel<<<NROW / 8, dim3(32, 8)>>>(np);

  proj_mma_kernel<<<dim3(144, 3), 256, PROJ_SMEM>>>();

  attn_kernel<<<dim3(18, 8), 256, ATTN_SMEM_BYTES>>>(g_out, b_out, (float*)d_out);
}

// round 8
// speedup vs baseline: 3.7436x; 1.9157x over previous
#include <cuda_runtime.h>
#include <cuda_bf16.h>
#include <cstdint>
#include <cstddef>

constexpr int Bn = 8;
constexpr int Tn = 2304;
constexpr int NROW = Bn * Tn;          // 18432
constexpr float LAMBDA_INIT_F = 0.6192834728526787f;
constexpr float QSCALE = 0.18033688011112042f;   // (1/8) * log2(e)

typedef unsigned long long ull;

__device__ float g_lam;
__device__ __align__(16) __nv_bfloat16 g_xh[NROW * 1024];
__device__ __align__(16) __nv_bfloat16 g_xl[NROW * 1024];
__device__ __align__(16) __nv_bfloat16 g_wh[9 * 128 * 1024];
__device__ __align__(16) __nv_bfloat16 g_wl[9 * 128 * 1024];
__device__ __align__(16) __nv_bfloat16 g_qh[NROW * 128];
__device__ __align__(16) __nv_bfloat16 g_ql[NROW * 128];
__device__ __align__(16) __nv_bfloat16 g_kh[NROW * 128];
__device__ __align__(16) __nv_bfloat16 g_kl[NROW * 128];
__device__ __align__(16) __nv_bfloat16 g_vh[NROW * 128];
__device__ __align__(16) __nv_bfloat16 g_vl[NROW * 128];

__device__ __forceinline__ float fast_exp2(float x) {
  x = fmaxf(x, -125.0f);
  float t = x + 12582912.0f;
  int e = __float_as_int(t) - 0x4B400000;
  float f = x - (t - 12582912.0f);
  float p =        1.3333558e-3f;
  p = fmaf(p, f,   9.6181291e-3f);
  p = fmaf(p, f,   5.5504109e-2f);
  p = fmaf(p, f,   2.4022651e-1f);
  p = fmaf(p, f,   6.9314718e-1f);
  p = fmaf(p, f,   1.0f);
  return __int_as_float(__float_as_int(p) + (e << 23));
}

__device__ __forceinline__ uint32_t smem_u32(const void* p) {
  uint32_t a;
  asm("{ .reg .u64 t; cvta.to.shared.u64 t, %1; cvt.u32.u64 %0, t; }" : "=r"(a) : "l"(p));
  return a;
}
__device__ __forceinline__ uint32_t sw128(uint32_t off) {
  return off ^ ((off >> 3) & 0x70);
}
__device__ __forceinline__ void cpasync16(uint32_t dst, const void* src) {
  asm volatile("cp.async.cg.shared.global [%0], [%1], 16;" :: "r"(dst), "l"(src));
}
__device__ __forceinline__ void cp_commit() {
  asm volatile("cp.async.commit_group;" ::: "memory");
}
__device__ __forceinline__ void cp_wait1() {
  asm volatile("cp.async.wait_group 1;" ::: "memory");
}
__device__ __forceinline__ void cp_wait0() {
  asm volatile("cp.async.wait_group 0;" ::: "memory");
}
__device__ __forceinline__ void ldsm4(uint32_t* r, uint32_t a) {
  asm volatile("ldmatrix.sync.aligned.m8n8.x4.shared.b16 {%0,%1,%2,%3}, [%4];"
               : "=r"(r[0]), "=r"(r[1]), "=r"(r[2]), "=r"(r[3]) : "r"(a));
}
__device__ __forceinline__ void ldsm4t(uint32_t* r, uint32_t a) {
  asm volatile("ldmatrix.sync.aligned.m8n8.x4.trans.shared.b16 {%0,%1,%2,%3}, [%4];"
               : "=r"(r[0]), "=r"(r[1]), "=r"(r[2]), "=r"(r[3]) : "r"(a));
}
__device__ __forceinline__ void mma16816(float* d, const uint32_t* a, uint32_t b0, uint32_t b1) {
  asm volatile(
      "mma.sync.aligned.m16n8k16.row.col.f32.bf16.bf16.f32 "
      "{%0,%1,%2,%3},{%4,%5,%6,%7},{%8,%9},{%0,%1,%2,%3};"
      : "+f"(d[0]), "+f"(d[1]), "+f"(d[2]), "+f"(d[3])
      : "r"(a[0]), "r"(a[1]), "r"(a[2]), "r"(a[3]), "r"(b0), "r"(b1));
}
__device__ __forceinline__ void hilo(float a, float b, uint32_t& h, uint32_t& l) {
  __nv_bfloat16 ha = __float2bfloat16_rn(a), hb = __float2bfloat16_rn(b);
  __nv_bfloat162 H; H.x = ha; H.y = hb;
  h = *(uint32_t*)&H;
  __nv_bfloat162 L;
  L.x = __float2bfloat16_rn(a - __bfloat162float(ha));
  L.y = __float2bfloat16_rn(b - __bfloat162float(hb));
  l = *(uint32_t*)&L;
}

// ---------------- lambda ----------------
__global__ void lambda_kernel(const float* __restrict__ lq1,
                              const float* __restrict__ lq2,
                              const float* __restrict__ lk1,
                              const float* __restrict__ lk2) {
  __shared__ float sh1[64], sh2[64];
  int t = threadIdx.x;
  sh1[t] = lq1[t] * lk1[t];
  sh2[t] = lq2[t] * lk2[t];
  __syncthreads();
  if (t == 0) {
    float a = 0.f, c = 0.f;
    for (int i = 0; i < 64; i++) { a += sh1[i]; c += sh2[i]; }
    g_lam = expf(a) - expf(c) + LAMBDA_INIT_F;
  }
}

// ---------------- LN + bf16 hi/lo split of x ----------------
struct NormParams {
  const float* x;
  const float* g[3];
  const float* b[3];
};

__global__ void norm_split_kernel(NormParams p) {
  int row = blockIdx.x * 8 + threadIdx.y;
  int t = row % Tn;
  int seg = t < 128 ? 0 : (t < 2176 ? 1 : 2);
  const float* __restrict__ gg = p.g[seg];
  const float* __restrict__ bb = p.b[seg];
  int lid = threadIdx.x;
  const float* xr = p.x + (size_t)row * 1024;

  float v[32];
  float s = 0.f, ss = 0.f;
#pragma unroll
  for (int i = 0; i < 8; i++) {
    float4 f = *(const float4*)&xr[i * 128 + lid * 4];
    v[i * 4 + 0] = f.x; v[i * 4 + 1] = f.y; v[i * 4 + 2] = f.z; v[i * 4 + 3] = f.w;
    s += f.x + f.y + f.z + f.w;
    ss += f.x * f.x + f.y * f.y + f.z * f.z + f.w * f.w;
  }
#pragma unroll
  for (int o = 16; o > 0; o >>= 1) {
    s += __shfl_xor_sync(0xffffffffu, s, o);
    ss += __shfl_xor_sync(0xffffffffu, ss, o);
  }
  float mean = s * (1.0f / 1024.0f);
  float var = fmaf(-mean, mean, ss * (1.0f / 1024.0f));
  float rstd = rsqrtf(var + 1e-5f);

  __nv_bfloat16* xh = g_xh + (size_t)row * 1024;
  __nv_bfloat16* xl = g_xl + (size_t)row * 1024;
#pragma unroll
  for (int i = 0; i < 8; i++) {
    int k = i * 128 + lid * 4;
    float4 gf = *(const float4*)&gg[k];
    float4 bf = *(const float4*)&bb[k];
    float a0 = (v[i * 4 + 0] - mean) * rstd * gf.x + bf.x;
    float a1 = (v[i * 4 + 1] - mean) * rstd * gf.y + bf.y;
    float a2 = (v[i * 4 + 2] - mean) * rstd * gf.z + bf.z;
    float a3 = (v[i * 4 + 3] - mean) * rstd * gf.w + bf.w;
    uint2 hp, lp;
    hilo(a0, a1, hp.x, lp.x);
    hilo(a2, a3, hp.y, lp.y);
    *(uint2*)&xh[k] = hp;
    *(uint2*)&xl[k] = lp;
  }
}

// ---------------- weight transpose + bf16 hi/lo split ----------------
struct WPrepParams { const float* W[9]; };

__global__ void wprep_kernel(WPrepParams p) {
  __shared__ float tile[32][33];
  int mat = blockIdx.z;
  const float* __restrict__ W = p.W[mat];
  int kb = blockIdx.x * 32, nb = blockIdx.y * 32;
  int tx = threadIdx.x, ty = threadIdx.y;
  tile[ty][tx] = W[(size_t)(kb + ty) * 128 + nb + tx];
  __syncthreads();
  float v = tile[tx][ty];
  __nv_bfloat16 h = __float2bfloat16_rn(v);
  __nv_bfloat16 l = __float2bfloat16_rn(v - __bfloat162float(h));
  size_t o = (size_t)mat * 128 * 1024 + (size_t)(nb + ty) * 1024 + kb + tx;
  g_wh[o] = h;
  g_wl[o] = l;
}

// ---------------- projection GEMM: mma.sync bf16x3, bf16 hi/lo output ----------------
constexpr int PB_AH = 0;
constexpr int PB_AL = 16384;
constexpr int PB_BH = 32768;
constexpr int PB_BL = 49152;
constexpr int PBUF = 65536;
constexpr int PROJ_SMEM = 2 * PBUF;   // 131072

__global__ __launch_bounds__(256, 1) void proj_mma_kernel() {
  extern __shared__ char smem[];
  uint32_t sb = smem_u32(smem);
  const int tid = threadIdx.x;
  const int rt = blockIdx.x, mat = blockIdx.y;
  const int row0 = rt * 128;
  const int t0 = row0 % Tn;
  const int seg = t0 < 128 ? 0 : (t0 < 2176 ? 1 : 2);
  const size_t wbase = (size_t)(mat * 3 + seg) * 128 * 1024;
  const __nv_bfloat16* __restrict__ Ah_g = g_xh + (size_t)row0 * 1024;
  const __nv_bfloat16* __restrict__ Al_g = g_xl + (size_t)row0 * 1024;
  const __nv_bfloat16* __restrict__ Bh_g = g_wh + wbase;
  const __nv_bfloat16* __restrict__ Bl_g = g_wl + wbase;

  const int lane = tid & 31;
  const int wid = tid >> 5;
  const int wm = (wid & 3) * 32;
  const int wn = (wid >> 2) * 64;
  const int lrow = lane & 7;
  const int sel = lane >> 3;
  const int selm = (sel & 1) * 8;
  const int selc = (sel >> 1) * 16;

  float acc[2][8][4];
#pragma unroll
  for (int mt = 0; mt < 2; mt++)
#pragma unroll
    for (int nt = 0; nt < 8; nt++)
#pragma unroll
      for (int j = 0; j < 4; j++) acc[mt][nt][j] = 0.f;

  auto issue = [&](int ch, int b) {
    const int k0 = ch * 64;
    const uint32_t dst = sb + b * PBUF;
#pragma unroll
    for (int it = 0; it < 4; it++) {
      int i = tid + it * 256;
      int r = i >> 3, c = i & 7;
      uint32_t d = sw128((uint32_t)(r * 128 + c * 16));
      size_t go = (size_t)r * 1024 + k0 + c * 8;
      cpasync16(dst + PB_AH + d, Ah_g + go);
      cpasync16(dst + PB_AL + d, Al_g + go);
      cpasync16(dst + PB_BH + d, Bh_g + go);
      cpasync16(dst + PB_BL + d, Bl_g + go);
    }
  };

  issue(0, 0);
  cp_commit();

  for (int ch = 0; ch < 16; ch++) {
    if (ch + 1 < 16) {
      issue(ch + 1, (ch + 1) & 1);
      cp_commit();
      cp_wait1();
    } else {
      cp_wait0();
    }
    __syncthreads();

    const uint32_t base = sb + (ch & 1) * PBUF;
#pragma unroll
    for (int ks = 0; ks < 4; ks++) {
      const int colb = ks * 32 + selc;
      uint32_t ah[2][4], al[2][4];
#pragma unroll
      for (int mt = 0; mt < 2; mt++) {
        int r = wm + mt * 16 + selm + lrow;
        uint32_t off = sw128((uint32_t)(r * 128 + colb));
        ldsm4(ah[mt], base + PB_AH + off);
        ldsm4(al[mt], base + PB_AL + off);
      }
      uint32_t bh[8][2], bl[8][2];
#pragma unroll
      for (int np = 0; np < 4; np++) {
        int r = wn + np * 16 + selm + lrow;
        uint32_t off = sw128((uint32_t)(r * 128 + colb));
        uint32_t t4[4];
        ldsm4(t4, base + PB_BH + off);
        bh[2 * np][0] = t4[0]; bh[2 * np][1] = t4[2];
        bh[2 * np + 1][0] = t4[1]; bh[2 * np + 1][1] = t4[3];
        ldsm4(t4, base + PB_BL + off);
        bl[2 * np][0] = t4[0]; bl[2 * np][1] = t4[2];
        bl[2 * np + 1][0] = t4[1]; bl[2 * np + 1][1] = t4[3];
      }
#pragma unroll
      for (int mt = 0; mt < 2; mt++)
#pragma unroll
        for (int nt = 0; nt < 8; nt++) {
          mma16816(acc[mt][nt], ah[mt], bh[nt][0], bh[nt][1]);
          mma16816(acc[mt][nt], ah[mt], bl[nt][0], bl[nt][1]);
          mma16816(acc[mt][nt], al[mt], bh[nt][0], bh[nt][1]);
        }
    }
    __syncthreads();
  }

  __nv_bfloat16* __restrict__ oh = (mat == 0) ? g_qh : (mat == 1) ? g_kh : g_vh;
  __nv_bfloat16* __restrict__ ol = (mat == 0) ? g_ql : (mat == 1) ? g_kl : g_vl;
  const int orow = lane >> 2, ocol = (lane & 3) * 2;
#pragma unroll
  for (int mt = 0; mt < 2; mt++)
#pragma unroll
    for (int nt = 0; nt < 8; nt++) {
      int r = row0 + wm + mt * 16 + orow;
      int c = wn + nt * 8 + ocol;
      uint32_t h0, l0, h1, l1;
      hilo(acc[mt][nt][0], acc[mt][nt][1], h0, l0);
      hilo(acc[mt][nt][2], acc[mt][nt][3], h1, l1);
      *(uint32_t*)&oh[(size_t)r * 128 + c] = h0;
      *(uint32_t*)&ol[(size_t)r * 128 + c] = l0;
      *(uint32_t*)&oh[(size_t)(r + 8) * 128 + c] = h1;
      *(uint32_t*)&ol[(size_t)(r + 8) * 128 + c] = l1;
    }
}

// ---------------- tensor-core dual flash attention ----------------
constexpr int KVBUF = 65536;              // per buffer: Kh(2x8K) Kl(2x8K) Vh(2x8K) Vl(2x8K)
constexpr int AOFF_Q   = 131072;          // Qh m0, Qh m1, Ql m0, Ql m1 (8K each)
constexpr int AOFF_P   = 163840;          // Ph1, Pl1, Ph2, Pl2 (8K each)
constexpr int AOFF_RED = 196608;          // 1024 B
constexpr int AOFF_RED2 = 197632;         // 1024 B
constexpr int ATTN_SMEM = 198656;

__global__ __launch_bounds__(256, 1) void attn_mma_kernel(
    const float* __restrict__ gam, const float* __restrict__ bet,
    float* __restrict__ out) {
  extern __shared__ char smem[];
  uint32_t sb = smem_u32(smem);
  float* REDf = (float*)(smem + AOFF_RED);
  float* RED2f = (float*)(smem + AOFF_RED2);

  const int tid = threadIdx.x;
  const int lane = tid & 31;
  const int wid = tid >> 5;
  const int wm = (wid & 3) * 16;
  const int wcol = wid >> 2;
  const int wn = wcol * 32;     // S cols
  const int wn2 = wcol * 64;    // O cols
  const int lrow = lane & 7;
  const int sel = lane >> 3;
  const int selm = (sel & 1) * 8;
  const int selc = (sel >> 1) * 16;
  const int r = lane >> 2;
  const int cq = (lane & 3) * 2;

  const int rowbase = (int)blockIdx.y * Tn;
  const float lam = g_lam;

  auto issueKV = [&](int kt, int b) {
    const int k0g = kt * 64;
    const uint32_t dst = sb + b * KVBUF;
#pragma unroll
    for (int it = 0; it < 16; it++) {
      int idx = tid + it * 256;
      int part = idx >> 9;
      int j = idx & 511;
      int key = j >> 3, c = j & 7;
      uint32_t so = (uint32_t)part * 8192 + sw128((uint32_t)(key * 128 + c * 16));
      size_t go = (size_t)(rowbase + k0g + key) * 128 + (part & 1) * 64 + c * 8;
      const __nv_bfloat16* src =
          (part < 2) ? g_kh : (part < 4) ? g_kl : (part < 6) ? g_vh : g_vl;
      cpasync16(dst + so, src + go);
    }
  };
  auto issueQ = [&](int q0) {
#pragma unroll
    for (int it = 0; it < 8; it++) {
      int idx = tid + it * 256;
      int part = idx >> 9;
      int j = idx & 511;
      int row = j >> 3, c = j & 7;
      uint32_t so = AOFF_Q + (uint32_t)part * 8192 + sw128((uint32_t)(row * 128 + c * 16));
      size_t go = (size_t)(rowbase + q0 + row) * 128 + (part & 1) * 64 + c * 8;
      const __nv_bfloat16* src = (part < 2) ? g_qh : g_ql;
      cpasync16(sb + so, src + go);
    }
  };

  for (int half = 0; half < 2; half++) {
    const int qt = half ? (35 - (int)blockIdx.x) : (int)blockIdx.x;
    const int q0 = qt * 64;

    float oacc[2][8][4];
    float mrow[2][2], lrow_s[2][2];
#pragma unroll
    for (int m = 0; m < 2; m++) {
#pragma unroll
      for (int h = 0; h < 2; h++) { mrow[m][h] = -3.0e38f; lrow_s[m][h] = 0.f; }
#pragma unroll
      for (int nt = 0; nt < 8; nt++)
#pragma unroll
        for (int j = 0; j < 4; j++) oacc[m][nt][j] = 0.f;
    }

    issueQ(q0);
    issueKV(0, 0);
    cp_commit();

    for (int kt = 0; kt <= qt; kt++) {
      if (kt < qt) {
        issueKV(kt + 1, (kt + 1) & 1);
        cp_commit();
        cp_wait1();
      } else {
        cp_wait0();
      }
      __syncthreads();   // A: buffers ready

      const uint32_t buf = sb + (kt & 1) * KVBUF;
      const int k0 = kt * 64;

      // ---- S = Q K^T ----
      float sacc[2][4][4];
#pragma unroll
      for (int m = 0; m < 2; m++)
#pragma unroll
        for (int nt = 0; nt < 4; nt++)
#pragma unroll
          for (int j = 0; j < 4; j++) sacc[m][nt][j] = 0.f;

#pragma unroll
      for (int m = 0; m < 2; m++) {
        const uint32_t Qh = sb + AOFF_Q + m * 8192;
        const uint32_t Ql = sb + AOFF_Q + 16384 + m * 8192;
        const uint32_t Kh = buf + m * 8192;
        const uint32_t Kl = buf + 16384 + m * 8192;
#pragma unroll
        for (int ks = 0; ks < 4; ks++) {
          const int colb = ks * 32 + selc;
          uint32_t aoff = sw128((uint32_t)((wm + selm + lrow) * 128 + colb));
          uint32_t qh[4], ql[4];
          ldsm4(qh, Qh + aoff);
          ldsm4(ql, Ql + aoff);
          uint32_t bh[4][2], bl[4][2];
#pragma unroll
          for (int np = 0; np < 2; np++) {
            uint32_t boff = sw128((uint32_t)((wn + np * 16 + selm + lrow) * 128 + colb));
            uint32_t t4[4];
            ldsm4(t4, Kh + boff);
            bh[2 * np][0] = t4[0]; bh[2 * np][1] = t4[2];
            bh[2 * np + 1][0] = t4[1]; bh[2 * np + 1][1] = t4[3];
            ldsm4(t4, Kl + boff);
            bl[2 * np][0] = t4[0]; bl[2 * np][1] = t4[2];
            bl[2 * np + 1][0] = t4[1]; bl[2 * np + 1][1] = t4[3];
          }
#pragma unroll
          for (int nt = 0; nt < 4; nt++) {
            mma16816(sacc[m][nt], qh, bh[nt][0], bh[nt][1]);
            mma16816(sacc[m][nt], ql, bh[nt][0], bh[nt][1]);
            mma16816(sacc[m][nt], qh, bl[nt][0], bl[nt][1]);
          }
        }
      }

      // ---- softmax ----
      const bool diag = (kt == qt);
      float mx[2][2];
#pragma unroll
      for (int m = 0; m < 2; m++)
#pragma unroll
        for (int h = 0; h < 2; h++) mx[m][h] = -3.0e38f;

#pragma unroll
      for (int m = 0; m < 2; m++)
#pragma unroll
        for (int nt = 0; nt < 4; nt++)
#pragma unroll
          for (int h = 0; h < 2; h++)
#pragma unroll
            for (int j = 0; j < 2; j++) {
              float v = sacc[m][nt][h * 2 + j] * QSCALE;
              if (diag && (k0 + wn + nt * 8 + cq + j) > (q0 + wm + r + h * 8)) v = -3.0e38f;
              sacc[m][nt][h * 2 + j] = v;
              mx[m][h] = fmaxf(mx[m][h], v);
            }
#pragma unroll
      for (int m = 0; m < 2; m++)
#pragma unroll
        for (int h = 0; h < 2; h++) {
          mx[m][h] = fmaxf(mx[m][h], __shfl_xor_sync(0xffffffffu, mx[m][h], 1));
          mx[m][h] = fmaxf(mx[m][h], __shfl_xor_sync(0xffffffffu, mx[m][h], 2));
        }
      if ((lane & 3) == 0) {
#pragma unroll
        for (int m = 0; m < 2; m++)
#pragma unroll
          for (int h = 0; h < 2; h++)
            REDf[(wcol * 2 + m) * 64 + wm + r + h * 8] = mx[m][h];
      }
      __syncthreads();   // B

      float alpha[2][2], lsum[2][2];
#pragma unroll
      for (int m = 0; m < 2; m++)
#pragma unroll
        for (int h = 0; h < 2; h++) {
          float g = fmaxf(mx[m][h], REDf[((1 - wcol) * 2 + m) * 64 + wm + r + h * 8]);
          float mn = fmaxf(mrow[m][h], g);
          alpha[m][h] = fast_exp2(mrow[m][h] - mn);
          mrow[m][h] = mn;
          lsum[m][h] = 0.f;
        }

      // exp, P hi/lo to smem, local sums
#pragma unroll
      for (int m = 0; m < 2; m++) {
        const uint32_t Ph = sb + AOFF_P + m * 16384;
        const uint32_t Pl = Ph + 8192;
#pragma unroll
        for (int nt = 0; nt < 4; nt++)
#pragma unroll
          for (int h = 0; h < 2; h++) {
            float p0 = fast_exp2(sacc[m][nt][h * 2 + 0] - mrow[m][h]);
            float p1 = fast_exp2(sacc[m][nt][h * 2 + 1] - mrow[m][h]);
            lsum[m][h] += p0 + p1;
            uint32_t hh, ll;
            hilo(p0, p1, hh, ll);
            uint32_t off = sw128((uint32_t)((wm + r + h * 8) * 128 + (wn + nt * 8 + cq) * 2));
            *(uint32_t*)(smem + (Ph - sb) + off) = hh;
            *(uint32_t*)(smem + (Pl - sb) + off) = ll;
          }
      }
#pragma unroll
      for (int m = 0; m < 2; m++)
#pragma unroll
        for (int h = 0; h < 2; h++) {
          lsum[m][h] += __shfl_xor_sync(0xffffffffu, lsum[m][h], 1);
          lsum[m][h] += __shfl_xor_sync(0xffffffffu, lsum[m][h], 2);
        }
      if ((lane & 3) == 0) {
#pragma unroll
        for (int m = 0; m < 2; m++)
#pragma unroll
          for (int h = 0; h < 2; h++)
            RED2f[(wcol * 2 + m) * 64 + wm + r + h * 8] = lsum[m][h];
      }
      // rescale O by alpha
#pragma unroll
      for (int m = 0; m < 2; m++)
#pragma unroll
        for (int nt = 0; nt < 8; nt++) {
          oacc[m][nt][0] *= alpha[m][0];
          oacc[m][nt][1] *= alpha[m][0];
          oacc[m][nt][2] *= alpha[m][1];
          oacc[m][nt][3] *= alpha[m][1];
        }
      __syncthreads();   // C: sums + P visible
#pragma unroll
      for (int m = 0; m < 2; m++)
#pragma unroll
        for (int h = 0; h < 2; h++) {
          float tot = lsum[m][h] + RED2f[((1 - wcol) * 2 + m) * 64 + wm + r + h * 8];
          lrow_s[m][h] = lrow_s[m][h] * alpha[m][h] + tot;
        }

      // ---- O += P V ----
      const uint32_t Vh = buf + 32768 + wcol * 8192;
      const uint32_t Vl = buf + 49152 + wcol * 8192;
#pragma unroll
      for (int ks = 0; ks < 4; ks++) {
        const int colb = ks * 32 + selc;
        uint32_t ph[2][4], pl[2][4];
#pragma unroll
        for (int m = 0; m < 2; m++) {
          uint32_t aoff = sw128((uint32_t)((wm + selm + lrow) * 128 + colb));
          ldsm4(ph[m], sb + AOFF_P + m * 16384 + aoff);
          ldsm4(pl[m], sb + AOFF_P + m * 16384 + 8192 + aoff);
        }
        uint32_t vh[8][2], vl[8][2];
#pragma unroll
        for (int np = 0; np < 4; np++) {
          uint32_t boff = sw128((uint32_t)((ks * 16 + selm + lrow) * 128 + np * 32 + selc));
          uint32_t t4[4];
          ldsm4t(t4, Vh + boff);
          vh[2 * np][0] = t4[0]; vh[2 * np][1] = t4[1];
          vh[2 * np + 1][0] = t4[2]; vh[2 * np + 1][1] = t4[3];
          ldsm4t(t4, Vl + boff);
          vl[2 * np][0] = t4[0]; vl[2 * np][1] = t4[1];
          vl[2 * np + 1][0] = t4[2]; vl[2 * np + 1][1] = t4[3];
        }
#pragma unroll
        for (int m = 0; m < 2; m++)
#pragma unroll
          for (int nt = 0; nt < 8; nt++) {
            mma16816(oacc[m][nt], ph[m], vh[nt][0], vh[nt][1]);
            mma16816(oacc[m][nt], pl[m], vh[nt][0], vh[nt][1]);
            mma16816(oacc[m][nt], ph[m], vl[nt][0], vl[nt][1]);
          }
      }
      __syncthreads();   // D: end of tile
    }

    // ---- epilogue: combine + output LN ----
    float invA[2], invB[2];
#pragma unroll
    for (int h = 0; h < 2; h++) {
      invA[h] = 1.0f / lrow_s[0][h];
      invB[h] = lam / lrow_s[1][h];
    }
    float rs[2] = {0.f, 0.f};
#pragma unroll
    for (int nt = 0; nt < 8; nt++)
#pragma unroll
      for (int h = 0; h < 2; h++)
#pragma unroll
        for (int j = 0; j < 2; j++)
          rs[h] += oacc[0][nt][h * 2 + j] * invA[h] - oacc[1][nt][h * 2 + j] * invB[h];
#pragma unroll
    for (int h = 0; h < 2; h++) {
      rs[h] += __shfl_xor_sync(0xffffffffu, rs[h], 1);
      rs[h] += __shfl_xor_sync(0xffffffffu, rs[h], 2);
    }
    if ((lane & 3) == 0) {
#pragma unroll
      for (int h = 0; h < 2; h++) REDf[wcol * 64 + wm + r + h * 8] = rs[h];
    }
    __syncthreads();
    float mean_[2];
#pragma unroll
    for (int h = 0; h < 2; h++)
      mean_[h] = (rs[h] + REDf[(1 - wcol) * 64 + wm + r + h * 8]) * (1.0f / 128.0f);

    float vs[2] = {0.f, 0.f};
#pragma unroll
    for (int nt = 0; nt < 8; nt++)
#pragma unroll
      for (int h = 0; h < 2; h++)
#pragma unroll
        for (int j = 0; j < 2; j++) {
          float a = oacc[0][nt][h * 2 + j] * invA[h] - oacc[1][nt][h * 2 + j] * invB[h] - mean_[h];
          vs[h] += a * a;
        }
#pragma unroll
    for (int h = 0; h < 2; h++) {
      vs[h] += __shfl_xor_sync(0xffffffffu, vs[h], 1);
      vs[h] += __shfl_xor_sync(0xffffffffu, vs[h], 2);
    }
    if ((lane & 3) == 0) {
#pragma unroll
      for (int h = 0; h < 2; h++) RED2f[wcol * 64 + wm + r + h * 8] = vs[h];
    }
    __syncthreads();
    float rstd_[2];
#pragma unroll
    for (int h = 0; h < 2; h++) {
      float var = (vs[h] + RED2f[(1 - wcol) * 64 + wm + r + h * 8]) * (1.0f / 128.0f);
      rstd_[h] = rsqrtf(var + 1e-5f);
    }
#pragma unroll
    for (int nt = 0; nt < 8; nt++) {
      int c = wn2 + nt * 8 + cq;
      float2 g2 = *(const float2*)&gam[c];
      float2 b2 = *(const float2*)&bet[c];
#pragma unroll
      for (int h = 0; h < 2; h++) {
        float a0 = oacc[0][nt][h * 2 + 0] * invA[h] - oacc[1][nt][h * 2 + 0] * invB[h];
        float a1 = oacc[0][nt][h * 2 + 1] * invA[h] - oacc[1][nt][h * 2 + 1] * invB[h];
        float o0 = (a0 - mean_[h]) * rstd_[h] * g2.x + b2.x;
        float o1 = (a1 - mean_[h]) * rstd_[h] * g2.y + b2.y;
        size_t off = (size_t)(rowbase + q0 + wm + r + h * 8) * 128 + c;
        *(float2*)&out[off] = make_float2(o0, o1);
      }
    }
    __syncthreads();   // protect smem before next half reuses
  }
}

// ---------------- launch ----------------
extern "C" void kernel_launch(void* const* d_in, const int* in_sizes, int n_in,
                              void* d_out, int out_size) {
  const float* x     = (const float*)d_in[0];
  const float* Wq    = (const float*)d_in[1];
  const float* Wk    = (const float*)d_in[2];
  const float* Wv    = (const float*)d_in[3];
  const float* Wq_ss = (const float*)d_in[4];
  const float* Wk_ss = (const float*)d_in[5];
  const float* Wv_ss = (const float*)d_in[6];
  const float* Wq_se = (const float*)d_in[7];
  const float* Wk_se = (const float*)d_in[8];
  const float* Wv_se = (const float*)d_in[9];
  const float* g_in  = (const float*)d_in[10];
  const float* b_in  = (const float*)d_in[11];
  const float* g_ss  = (const float*)d_in[12];
  const float* b_ss  = (const float*)d_in[13];
  const float* g_se  = (const float*)d_in[14];
  const float* b_se  = (const float*)d_in[15];
  const float* g_out = (const float*)d_in[16];
  const float* b_out = (const float*)d_in[17];
  const float* lq1   = (const float*)d_in[18];
  const float* lq2   = (const float*)d_in[19];
  const float* lk1   = (const float*)d_in[20];
  const float* lk2   = (const float*)d_in[21];

  static bool attr_set = false;
  if (!attr_set) {
    cudaFuncSetAttribute(proj_mma_kernel, cudaFuncAttributeMaxDynamicSharedMemorySize,
                         PROJ_SMEM);
    cudaFuncSetAttribute(attn_mma_kernel, cudaFuncAttributeMaxDynamicSharedMemorySize,
                         ATTN_SMEM);
    attr_set = true;
  }

  lambda_kernel<<<1, 64>>>(lq1, lq2, lk1, lk2);

  WPrepParams wp;
  wp.W[0] = Wq_ss; wp.W[1] = Wq; wp.W[2] = Wq_se;
  wp.W[3] = Wk_ss; wp.W[4] = Wk; wp.W[5] = Wk_se;
  wp.W[6] = Wv_ss; wp.W[7] = Wv; wp.W[8] = Wv_se;
  wprep_kernel<<<dim3(32, 4, 9), dim3(32, 32)>>>(wp);

  NormParams np;
  np.x = x;
  np.g[0] = g_ss; np.g[1] = g_in; np.g[2] = g_se;
  np.b[0] = b_ss; np.b[1] = b_in; np.b[2] = b_se;
  norm_split_kernel<<<NROW / 8, dim3(32, 8)>>>(np);

  proj_mma_kernel<<<dim3(144, 3), 256, PROJ_SMEM>>>();

  attn_mma_kernel<<<dim3(18, 8), 256, ATTN_SMEM>>>(g_out, b_out, (float*)d_out);
}

// round 10
// speedup vs baseline: 3.8587x; 1.0307x over previous
#include <cuda_runtime.h>
#include <cuda_bf16.h>
#include <cstdint>
#include <cstddef>

constexpr int Bn = 8;
constexpr int Tn = 2304;
constexpr int NROW = Bn * Tn;          // 18432
constexpr float LAMBDA_INIT_F = 0.6192834728526787f;
constexpr float QSCALE = 0.18033688011112042f;   // (1/8) * log2(e)

typedef unsigned long long ull;

__device__ float g_lam;
__device__ __align__(16) __nv_bfloat16 g_xh[NROW * 1024];
__device__ __align__(16) __nv_bfloat16 g_xl[NROW * 1024];
__device__ __align__(16) __nv_bfloat16 g_wh[9 * 128 * 1024];
__device__ __align__(16) __nv_bfloat16 g_wl[9 * 128 * 1024];
__device__ __align__(16) __nv_bfloat16 g_qh[NROW * 128];
__device__ __align__(16) __nv_bfloat16 g_ql[NROW * 128];
__device__ __align__(16) __nv_bfloat16 g_kh[NROW * 128];
__device__ __align__(16) __nv_bfloat16 g_kl[NROW * 128];
__device__ __align__(16) __nv_bfloat16 g_vh[NROW * 128];
__device__ __align__(16) __nv_bfloat16 g_vl[NROW * 128];

__device__ __forceinline__ float fast_exp2(float x) {
  x = fmaxf(x, -125.0f);
  float t = x + 12582912.0f;
  int e = __float_as_int(t) - 0x4B400000;
  float f = x - (t - 12582912.0f);
  float p =        1.3333558e-3f;
  p = fmaf(p, f,   9.6181291e-3f);
  p = fmaf(p, f,   5.5504109e-2f);
  p = fmaf(p, f,   2.4022651e-1f);
  p = fmaf(p, f,   6.9314718e-1f);
  p = fmaf(p, f,   1.0f);
  return __int_as_float(__float_as_int(p) + (e << 23));
}

__device__ __forceinline__ uint32_t smem_u32(const void* p) {
  uint32_t a;
  asm("{ .reg .u64 t; cvta.to.shared.u64 t, %1; cvt.u32.u64 %0, t; }" : "=r"(a) : "l"(p));
  return a;
}
__device__ __forceinline__ uint32_t sw128(uint32_t off) {
  return off ^ ((off >> 3) & 0x70);
}
__device__ __forceinline__ void cpasync16(uint32_t dst, const void* src) {
  asm volatile("cp.async.cg.shared.global [%0], [%1], 16;" :: "r"(dst), "l"(src));
}
__device__ __forceinline__ void cp_commit() {
  asm volatile("cp.async.commit_group;" ::: "memory");
}
__device__ __forceinline__ void cp_wait1() {
  asm volatile("cp.async.wait_group 1;" ::: "memory");
}
__device__ __forceinline__ void cp_wait0() {
  asm volatile("cp.async.wait_group 0;" ::: "memory");
}
__device__ __forceinline__ void ldsm4(uint32_t* r, uint32_t a) {
  asm volatile("ldmatrix.sync.aligned.m8n8.x4.shared.b16 {%0,%1,%2,%3}, [%4];"
               : "=r"(r[0]), "=r"(r[1]), "=r"(r[2]), "=r"(r[3]) : "r"(a));
}
__device__ __forceinline__ void ldsm4t(uint32_t* r, uint32_t a) {
  asm volatile("ldmatrix.sync.aligned.m8n8.x4.trans.shared.b16 {%0,%1,%2,%3}, [%4];"
               : "=r"(r[0]), "=r"(r[1]), "=r"(r[2]), "=r"(r[3]) : "r"(a));
}
__device__ __forceinline__ void mma16816(float* d, const uint32_t* a, uint32_t b0, uint32_t b1) {
  asm volatile(
      "mma.sync.aligned.m16n8k16.row.col.f32.bf16.bf16.f32 "
      "{%0,%1,%2,%3},{%4,%5,%6,%7},{%8,%9},{%0,%1,%2,%3};"
      : "+f"(d[0]), "+f"(d[1]), "+f"(d[2]), "+f"(d[3])
      : "r"(a[0]), "r"(a[1]), "r"(a[2]), "r"(a[3]), "r"(b0), "r"(b1));
}
__device__ __forceinline__ void hilo(float a, float b, uint32_t& h, uint32_t& l) {
  __nv_bfloat16 ha = __float2bfloat16_rn(a), hb = __float2bfloat16_rn(b);
  __nv_bfloat162 H; H.x = ha; H.y = hb;
  h = *(uint32_t*)&H;
  __nv_bfloat162 L;
  L.x = __float2bfloat16_rn(a - __bfloat162float(ha));
  L.y = __float2bfloat16_rn(b - __bfloat162float(hb));
  l = *(uint32_t*)&L;
}

// ---------------- lambda ----------------
__global__ void lambda_kernel(const float* __restrict__ lq1,
                              const float* __restrict__ lq2,
                              const float* __restrict__ lk1,
                              const float* __restrict__ lk2) {
  __shared__ float sh1[64], sh2[64];
  int t = threadIdx.x;
  sh1[t] = lq1[t] * lk1[t];
  sh2[t] = lq2[t] * lk2[t];
  __syncthreads();
  if (t == 0) {
    float a = 0.f, c = 0.f;
    for (int i = 0; i < 64; i++) { a += sh1[i]; c += sh2[i]; }
    g_lam = expf(a) - expf(c) + LAMBDA_INIT_F;
  }
}

// ---------------- LN + bf16 hi/lo split of x ----------------
struct NormParams {
  const float* x;
  const float* g[3];
  const float* b[3];
};

__global__ void norm_split_kernel(NormParams p) {
  int row = blockIdx.x * 8 + threadIdx.y;
  int t = row % Tn;
  int seg = t < 128 ? 0 : (t < 2176 ? 1 : 2);
  const float* __restrict__ gg = p.g[seg];
  const float* __restrict__ bb = p.b[seg];
  int lid = threadIdx.x;
  const float* xr = p.x + (size_t)row * 1024;

  float v[32];
  float s = 0.f, ss = 0.f;
#pragma unroll
  for (int i = 0; i < 8; i++) {
    float4 f = *(const float4*)&xr[i * 128 + lid * 4];
    v[i * 4 + 0] = f.x; v[i * 4 + 1] = f.y; v[i * 4 + 2] = f.z; v[i * 4 + 3] = f.w;
    s += f.x + f.y + f.z + f.w;
    ss += f.x * f.x + f.y * f.y + f.z * f.z + f.w * f.w;
  }
#pragma unroll
  for (int o = 16; o > 0; o >>= 1) {
    s += __shfl_xor_sync(0xffffffffu, s, o);
    ss += __shfl_xor_sync(0xffffffffu, ss, o);
  }
  float mean = s * (1.0f / 1024.0f);
  float var = fmaf(-mean, mean, ss * (1.0f / 1024.0f));
  float rstd = rsqrtf(var + 1e-5f);

  __nv_bfloat16* xh = g_xh + (size_t)row * 1024;
  __nv_bfloat16* xl = g_xl + (size_t)row * 1024;
#pragma unroll
  for (int i = 0; i < 8; i++) {
    int k = i * 128 + lid * 4;
    float4 gf = *(const float4*)&gg[k];
    float4 bf = *(const float4*)&bb[k];
    float a0 = (v[i * 4 + 0] - mean) * rstd * gf.x + bf.x;
    float a1 = (v[i * 4 + 1] - mean) * rstd * gf.y + bf.y;
    float a2 = (v[i * 4 + 2] - mean) * rstd * gf.z + bf.z;
    float a3 = (v[i * 4 + 3] - mean) * rstd * gf.w + bf.w;
    uint2 hp, lp;
    hilo(a0, a1, hp.x, lp.x);
    hilo(a2, a3, hp.y, lp.y);
    *(uint2*)&xh[k] = hp;
    *(uint2*)&xl[k] = lp;
  }
}

// ---------------- weight transpose + bf16 hi/lo split ----------------
struct WPrepParams { const float* W[9]; };

__global__ void wprep_kernel(WPrepParams p) {
  __shared__ float tile[32][33];
  int mat = blockIdx.z;
  const float* __restrict__ W = p.W[mat];
  int kb = blockIdx.x * 32, nb = blockIdx.y * 32;
  int tx = threadIdx.x, ty = threadIdx.y;
  tile[ty][tx] = W[(size_t)(kb + ty) * 128 + nb + tx];
  __syncthreads();
  float v = tile[tx][ty];
  __nv_bfloat16 h = __float2bfloat16_rn(v);
  __nv_bfloat16 l = __float2bfloat16_rn(v - __bfloat162float(h));
  size_t o = (size_t)mat * 128 * 1024 + (size_t)(nb + ty) * 1024 + kb + tx;
  g_wh[o] = h;
  g_wl[o] = l;
}

// ---------------- projection GEMM: mma.sync bf16x3, 128x64 tiles, occ 2 ----------------
// grid (144, 3, 2): x = 128-row tile, y = mat, z = 64-col half.
// smem per buffer: Ah 16K | Al 16K | Bh 8K | Bl 8K = 48KB; double buffered = 96KB.
constexpr int PB_AH = 0;
constexpr int PB_AL = 16384;
constexpr int PB_BH = 32768;
constexpr int PB_BL = 40960;
constexpr int PBUF = 49152;
constexpr int PROJ_SMEM = 2 * PBUF;   // 98304

__global__ __launch_bounds__(256, 2) void proj_mma_kernel() {
  extern __shared__ char smem[];
  uint32_t sb = smem_u32(smem);
  const int tid = threadIdx.x;
  const int rt = blockIdx.x, mat = blockIdx.y, nh = blockIdx.z;
  const int row0 = rt * 128;
  const int t0 = row0 % Tn;
  const int seg = t0 < 128 ? 0 : (t0 < 2176 ? 1 : 2);
  const size_t wbase = (size_t)(mat * 3 + seg) * 128 * 1024 + (size_t)nh * 64 * 1024;
  const __nv_bfloat16* __restrict__ Ah_g = g_xh + (size_t)row0 * 1024;
  const __nv_bfloat16* __restrict__ Al_g = g_xl + (size_t)row0 * 1024;
  const __nv_bfloat16* __restrict__ Bh_g = g_wh + wbase;
  const __nv_bfloat16* __restrict__ Bl_g = g_wl + wbase;

  const int lane = tid & 31;
  const int wid = tid >> 5;
  const int wm = (wid & 3) * 32;        // warp row base (0..96)
  const int wn = (wid >> 2) * 32;       // warp col base (0 or 32) within 64
  const int lrow = lane & 7;
  const int sel = lane >> 3;
  const int selm = (sel & 1) * 8;
  const int selc = (sel >> 1) * 16;

  float acc[2][4][4];
#pragma unroll
  for (int mt = 0; mt < 2; mt++)
#pragma unroll
    for (int nt = 0; nt < 4; nt++)
#pragma unroll
      for (int j = 0; j < 4; j++) acc[mt][nt][j] = 0.f;

  // cp.async: A = 128x64 bf16 (hi+lo) = 2048 xfers/2 halves... 1024 each of 16B;
  // B = 64x64 (hi+lo) = 512 each. Total 3072 16B xfers / 256 thr = 12 each.
  auto issue = [&](int ch, int b) {
    const int k0 = ch * 64;
    const uint32_t dst = sb + b * PBUF;
#pragma unroll
    for (int it = 0; it < 4; it++) {   // A: 1024 positions
      int i = tid + it * 256;
      int r = i >> 3, c = i & 7;
      uint32_t d = sw128((uint32_t)(r * 128 + c * 16));
      size_t go = (size_t)r * 1024 + k0 + c * 8;
      cpasync16(dst + PB_AH + d, Ah_g + go);
      cpasync16(dst + PB_AL + d, Al_g + go);
    }
#pragma unroll
    for (int it = 0; it < 2; it++) {   // B: 512 positions
      int i = tid + it * 256;
      int r = i >> 3, c = i & 7;
      uint32_t d = sw128((uint32_t)(r * 128 + c * 16));
      size_t go = (size_t)r * 1024 + k0 + c * 8;
      cpasync16(dst + PB_BH + d, Bh_g + go);
      cpasync16(dst + PB_BL + d, Bl_g + go);
    }
  };

  issue(0, 0);
  cp_commit();

  for (int ch = 0; ch < 16; ch++) {
    if (ch + 1 < 16) {
      issue(ch + 1, (ch + 1) & 1);
      cp_commit();
      cp_wait1();
    } else {
      cp_wait0();
    }
    __syncthreads();

    const uint32_t base = sb + (ch & 1) * PBUF;
#pragma unroll
    for (int ks = 0; ks < 4; ks++) {
      const int colb = ks * 32 + selc;
      uint32_t ah[2][4], al[2][4];
#pragma unroll
      for (int mt = 0; mt < 2; mt++) {
        int r = wm + mt * 16 + selm + lrow;
        uint32_t off = sw128((uint32_t)(r * 128 + colb));
        ldsm4(ah[mt], base + PB_AH + off);
        ldsm4(al[mt], base + PB_AL + off);
      }
      uint32_t bh[4][2], bl[4][2];
#pragma unroll
      for (int np = 0; np < 2; np++) {
        int r = wn + np * 16 + selm + lrow;
        uint32_t off = sw128((uint32_t)(r * 128 + colb));
        uint32_t t4[4];
        ldsm4(t4, base + PB_BH + off);
        bh[2 * np][0] = t4[0]; bh[2 * np][1] = t4[2];
        bh[2 * np + 1][0] = t4[1]; bh[2 * np + 1][1] = t4[3];
        ldsm4(t4, base + PB_BL + off);
        bl[2 * np][0] = t4[0]; bl[2 * np][1] = t4[2];
        bl[2 * np + 1][0] = t4[1]; bl[2 * np + 1][1] = t4[3];
      }
#pragma unroll
      for (int mt = 0; mt < 2; mt++)
#pragma unroll
        for (int nt = 0; nt < 4; nt++) {
          mma16816(acc[mt][nt], ah[mt], bh[nt][0], bh[nt][1]);
          mma16816(acc[mt][nt], ah[mt], bl[nt][0], bl[nt][1]);
          mma16816(acc[mt][nt], al[mt], bh[nt][0], bh[nt][1]);
        }
    }
    __syncthreads();
  }

  __nv_bfloat16* __restrict__ oh = (mat == 0) ? g_qh : (mat == 1) ? g_kh : g_vh;
  __nv_bfloat16* __restrict__ ol = (mat == 0) ? g_ql : (mat == 1) ? g_kl : g_vl;
  const int orow = lane >> 2, ocol = (lane & 3) * 2;
#pragma unroll
  for (int mt = 0; mt < 2; mt++)
#pragma unroll
    for (int nt = 0; nt < 4; nt++) {
      int r = row0 + wm + mt * 16 + orow;
      int c = nh * 64 + wn + nt * 8 + ocol;
      uint32_t h0, l0, h1, l1;
      hilo(acc[mt][nt][0], acc[mt][nt][1], h0, l0);
      hilo(acc[mt][nt][2], acc[mt][nt][3], h1, l1);
      *(uint32_t*)&oh[(size_t)r * 128 + c] = h0;
      *(uint32_t*)&ol[(size_t)r * 128 + c] = l0;
      *(uint32_t*)&oh[(size_t)(r + 8) * 128 + c] = h1;
      *(uint32_t*)&ol[(size_t)(r + 8) * 128 + c] = l1;
    }
}

// ---------------- tensor-core dual flash attention (unchanged R8) ----------------
constexpr int KVBUF = 65536;              // per buffer: Kh(2x8K) Kl(2x8K) Vh(2x8K) Vl(2x8K)
constexpr int AOFF_Q   = 131072;          // Qh m0, Qh m1, Ql m0, Ql m1 (8K each)
constexpr int AOFF_P   = 163840;          // Ph1, Pl1, Ph2, Pl2 (8K each)
constexpr int AOFF_RED = 196608;          // 1024 B
constexpr int AOFF_RED2 = 197632;         // 1024 B
constexpr int ATTN_SMEM = 198656;

__global__ __launch_bounds__(256, 1) void attn_mma_kernel(
    const float* __restrict__ gam, const float* __restrict__ bet,
    float* __restrict__ out) {
  extern __shared__ char smem[];
  uint32_t sb = smem_u32(smem);
  float* REDf = (float*)(smem + AOFF_RED);
  float* RED2f = (float*)(smem + AOFF_RED2);

  const int tid = threadIdx.x;
  const int lane = tid & 31;
  const int wid = tid >> 5;
  const int wm = (wid & 3) * 16;
  const int wcol = wid >> 2;
  const int wn = wcol * 32;     // S cols
  const int wn2 = wcol * 64;    // O cols
  const int lrow = lane & 7;
  const int sel = lane >> 3;
  const int selm = (sel & 1) * 8;
  const int selc = (sel >> 1) * 16;
  const int r = lane >> 2;
  const int cq = (lane & 3) * 2;

  const int rowbase = (int)blockIdx.y * Tn;
  const float lam = g_lam;

  auto issueKV = [&](int kt, int b) {
    const int k0g = kt * 64;
    const uint32_t dst = sb + b * KVBUF;
#pragma unroll
    for (int it = 0; it < 16; it++) {
      int idx = tid + it * 256;
      int part = idx >> 9;
      int j = idx & 511;
      int key = j >> 3, c = j & 7;
      uint32_t so = (uint32_t)part * 8192 + sw128((uint32_t)(key * 128 + c * 16));
      size_t go = (size_t)(rowbase + k0g + key) * 128 + (part & 1) * 64 + c * 8;
      const __nv_bfloat16* src =
          (part < 2) ? g_kh : (part < 4) ? g_kl : (part < 6) ? g_vh : g_vl;
      cpasync16(dst + so, src + go);
    }
  };
  auto issueQ = [&](int q0) {
#pragma unroll
    for (int it = 0; it < 8; it++) {
      int idx = tid + it * 256;
      int part = idx >> 9;
      int j = idx & 511;
      int row = j >> 3, c = j & 7;
      uint32_t so = AOFF_Q + (uint32_t)part * 8192 + sw128((uint32_t)(row * 128 + c * 16));
      size_t go = (size_t)(rowbase + q0 + row) * 128 + (part & 1) * 64 + c * 8;
      const __nv_bfloat16* src = (part < 2) ? g_qh : g_ql;
      cpasync16(sb + so, src + go);
    }
  };

  for (int half = 0; half < 2; half++) {
    const int qt = half ? (35 - (int)blockIdx.x) : (int)blockIdx.x;
    const int q0 = qt * 64;

    float oacc[2][8][4];
    float mrow[2][2], lrow_s[2][2];
#pragma unroll
    for (int m = 0; m < 2; m++) {
#pragma unroll
      for (int h = 0; h < 2; h++) { mrow[m][h] = -3.0e38f; lrow_s[m][h] = 0.f; }
#pragma unroll
      for (int nt = 0; nt < 8; nt++)
#pragma unroll
        for (int j = 0; j < 4; j++) oacc[m][nt][j] = 0.f;
    }

    issueQ(q0);
    issueKV(0, 0);
    cp_commit();

    for (int kt = 0; kt <= qt; kt++) {
      if (kt < qt) {
        issueKV(kt + 1, (kt + 1) & 1);
        cp_commit();
        cp_wait1();
      } else {
        cp_wait0();
      }
      __syncthreads();   // A: buffers ready

      const uint32_t buf = sb + (kt & 1) * KVBUF;
      const int k0 = kt * 64;

      // ---- S = Q K^T ----
      float sacc[2][4][4];
#pragma unroll
      for (int m = 0; m < 2; m++)
#pragma unroll
        for (int nt = 0; nt < 4; nt++)
#pragma unroll
          for (int j = 0; j < 4; j++) sacc[m][nt][j] = 0.f;

#pragma unroll
      for (int m = 0; m < 2; m++) {
        const uint32_t Qh = sb + AOFF_Q + m * 8192;
        const uint32_t Ql = sb + AOFF_Q + 16384 + m * 8192;
        const uint32_t Kh = buf + m * 8192;
        const uint32_t Kl = buf + 16384 + m * 8192;
#pragma unroll
        for (int ks = 0; ks < 4; ks++) {
          const int colb = ks * 32 + selc;
          uint32_t aoff = sw128((uint32_t)((wm + selm + lrow) * 128 + colb));
          uint32_t qh[4], ql[4];
          ldsm4(qh, Qh + aoff);
          ldsm4(ql, Ql + aoff);
          uint32_t bh[4][2], bl[4][2];
#pragma unroll
          for (int np = 0; np < 2; np++) {
            uint32_t boff = sw128((uint32_t)((wn + np * 16 + selm + lrow) * 128 + colb));
            uint32_t t4[4];
            ldsm4(t4, Kh + boff);
            bh[2 * np][0] = t4[0]; bh[2 * np][1] = t4[2];
            bh[2 * np + 1][0] = t4[1]; bh[2 * np + 1][1] = t4[3];
            ldsm4(t4, Kl + boff);
            bl[2 * np][0] = t4[0]; bl[2 * np][1] = t4[2];
            bl[2 * np + 1][0] = t4[1]; bl[2 * np + 1][1] = t4[3];
          }
#pragma unroll
          for (int nt = 0; nt < 4; nt++) {
            mma16816(sacc[m][nt], qh, bh[nt][0], bh[nt][1]);
            mma16816(sacc[m][nt], ql, bh[nt][0], bh[nt][1]);
            mma16816(sacc[m][nt], qh, bl[nt][0], bl[nt][1]);
          }
        }
      }

      // ---- softmax ----
      const bool diag = (kt == qt);
      float mx[2][2];
#pragma unroll
      for (int m = 0; m < 2; m++)
#pragma unroll
        for (int h = 0; h < 2; h++) mx[m][h] = -3.0e38f;

#pragma unroll
      for (int m = 0; m < 2; m++)
#pragma unroll
        for (int nt = 0; nt < 4; nt++)
#pragma unroll
          for (int h = 0; h < 2; h++)
#pragma unroll
            for (int j = 0; j < 2; j++) {
              float v = sacc[m][nt][h * 2 + j] * QSCALE;
              if (diag && (k0 + wn + nt * 8 + cq + j) > (q0 + wm + r + h * 8)) v = -3.0e38f;
              sacc[m][nt][h * 2 + j] = v;
              mx[m][h] = fmaxf(mx[m][h], v);
            }
#pragma unroll
      for (int m = 0; m < 2; m++)
#pragma unroll
        for (int h = 0; h < 2; h++) {
          mx[m][h] = fmaxf(mx[m][h], __shfl_xor_sync(0xffffffffu, mx[m][h], 1));
          mx[m][h] = fmaxf(mx[m][h], __shfl_xor_sync(0xffffffffu, mx[m][h], 2));
        }
      if ((lane & 3) == 0) {
#pragma unroll
        for (int m = 0; m < 2; m++)
#pragma unroll
          for (int h = 0; h < 2; h++)
            REDf[(wcol * 2 + m) * 64 + wm + r + h * 8] = mx[m][h];
      }
      __syncthreads();   // B

      float alpha[2][2], lsum[2][2];
#pragma unroll
      for (int m = 0; m < 2; m++)
#pragma unroll
        for (int h = 0; h < 2; h++) {
          float g = fmaxf(mx[m][h], REDf[((1 - wcol) * 2 + m) * 64 + wm + r + h * 8]);
          float mn = fmaxf(mrow[m][h], g);
          alpha[m][h] = fast_exp2(mrow[m][h] - mn);
          mrow[m][h] = mn;
          lsum[m][h] = 0.f;
        }

      // exp, P hi/lo to smem, local sums
#pragma unroll
      for (int m = 0; m < 2; m++) {
        const uint32_t Ph = sb + AOFF_P + m * 16384;
        const uint32_t Pl = Ph + 8192;
#pragma unroll
        for (int nt = 0; nt < 4; nt++)
#pragma unroll
          for (int h = 0; h < 2; h++) {
            float p0 = fast_exp2(sacc[m][nt][h * 2 + 0] - mrow[m][h]);
            float p1 = fast_exp2(sacc[m][nt][h * 2 + 1] - mrow[m][h]);
            lsum[m][h] += p0 + p1;
            uint32_t hh, ll;
            hilo(p0, p1, hh, ll);
            uint32_t off = sw128((uint32_t)((wm + r + h * 8) * 128 + (wn + nt * 8 + cq) * 2));
            *(uint32_t*)(smem + (Ph - sb) + off) = hh;
            *(uint32_t*)(smem + (Pl - sb) + off) = ll;
          }
      }
#pragma unroll
      for (int m = 0; m < 2; m++)
#pragma unroll
        for (int h = 0; h < 2; h++) {
          lsum[m][h] += __shfl_xor_sync(0xffffffffu, lsum[m][h], 1);
          lsum[m][h] += __shfl_xor_sync(0xffffffffu, lsum[m][h], 2);
        }
      if ((lane & 3) == 0) {
#pragma unroll
        for (int m = 0; m < 2; m++)
#pragma unroll
          for (int h = 0; h < 2; h++)
            RED2f[(wcol * 2 + m) * 64 + wm + r + h * 8] = lsum[m][h];
      }
      // rescale O by alpha
#pragma unroll
      for (int m = 0; m < 2; m++)
#pragma unroll
        for (int nt = 0; nt < 8; nt++) {
          oacc[m][nt][0] *= alpha[m][0];
          oacc[m][nt][1] *= alpha[m][0];
          oacc[m][nt][2] *= alpha[m][1];
          oacc[m][nt][3] *= alpha[m][1];
        }
      __syncthreads();   // C: sums + P visible
#pragma unroll
      for (int m = 0; m < 2; m++)
#pragma unroll
        for (int h = 0; h < 2; h++) {
          float tot = lsum[m][h] + RED2f[((1 - wcol) * 2 + m) * 64 + wm + r + h * 8];
          lrow_s[m][h] = lrow_s[m][h] * alpha[m][h] + tot;
        }

      // ---- O += P V ----
      const uint32_t Vh = buf + 32768 + wcol * 8192;
      const uint32_t Vl = buf + 49152 + wcol * 8192;
#pragma unroll
      for (int ks = 0; ks < 4; ks++) {
        const int colb = ks * 32 + selc;
        uint32_t ph[2][4], pl[2][4];
#pragma unroll
        for (int m = 0; m < 2; m++) {
          uint32_t aoff = sw128((uint32_t)((wm + selm + lrow) * 128 + colb));
          ldsm4(ph[m], sb + AOFF_P + m * 16384 + aoff);
          ldsm4(pl[m], sb + AOFF_P + m * 16384 + 8192 + aoff);
        }
        uint32_t vh[8][2], vl[8][2];
#pragma unroll
        for (int np = 0; np < 4; np++) {
          uint32_t boff = sw128((uint32_t)((ks * 16 + selm + lrow) * 128 + np * 32 + selc));
          uint32_t t4[4];
          ldsm4t(t4, Vh + boff);
          vh[2 * np][0] = t4[0]; vh[2 * np][1] = t4[1];
          vh[2 * np + 1][0] = t4[2]; vh[2 * np + 1][1] = t4[3];
          ldsm4t(t4, Vl + boff);
          vl[2 * np][0] = t4[0]; vl[2 * np][1] = t4[1];
          vl[2 * np + 1][0] = t4[2]; vl[2 * np + 1][1] = t4[3];
        }
#pragma unroll
        for (int m = 0; m < 2; m++)
#pragma unroll
          for (int nt = 0; nt < 8; nt++) {
            mma16816(oacc[m][nt], ph[m], vh[nt][0], vh[nt][1]);
            mma16816(oacc[m][nt], pl[m], vh[nt][0], vh[nt][1]);
            mma16816(oacc[m][nt], ph[m], vl[nt][0], vl[nt][1]);
          }
      }
      __syncthreads();   // D: end of tile
    }

    // ---- epilogue: combine + output LN ----
    float invA[2], invB[2];
#pragma unroll
    for (int h = 0; h < 2; h++) {
      invA[h] = 1.0f / lrow_s[0][h];
      invB[h] = lam / lrow_s[1][h];
    }
    float rs[2] = {0.f, 0.f};
#pragma unroll
    for (int nt = 0; nt < 8; nt++)
#pragma unroll
      for (int h = 0; h < 2; h++)
#pragma unroll
        for (int j = 0; j < 2; j++)
          rs[h] += oacc[0][nt][h * 2 + j] * invA[h] - oacc[1][nt][h * 2 + j] * invB[h];
#pragma unroll
    for (int h = 0; h < 2; h++) {
      rs[h] += __shfl_xor_sync(0xffffffffu, rs[h], 1);
      rs[h] += __shfl_xor_sync(0xffffffffu, rs[h], 2);
    }
    if ((lane & 3) == 0) {
#pragma unroll
      for (int h = 0; h < 2; h++) REDf[wcol * 64 + wm + r + h * 8] = rs[h];
    }
    __syncthreads();
    float mean_[2];
#pragma unroll
    for (int h = 0; h < 2; h++)
      mean_[h] = (rs[h] + REDf[(1 - wcol) * 64 + wm + r + h * 8]) * (1.0f / 128.0f);

    float vs[2] = {0.f, 0.f};
#pragma unroll
    for (int nt = 0; nt < 8; nt++)
#pragma unroll
      for (int h = 0; h < 2; h++)
#pragma unroll
        for (int j = 0; j < 2; j++) {
          float a = oacc[0][nt][h * 2 + j] * invA[h] - oacc[1][nt][h * 2 + j] * invB[h] - mean_[h];
          vs[h] += a * a;
        }
#pragma unroll
    for (int h = 0; h < 2; h++) {
      vs[h] += __shfl_xor_sync(0xffffffffu, vs[h], 1);
      vs[h] += __shfl_xor_sync(0xffffffffu, vs[h], 2);
    }
    if ((lane & 3) == 0) {
#pragma unroll
      for (int h = 0; h < 2; h++) RED2f[wcol * 64 + wm + r + h * 8] = vs[h];
    }
    __syncthreads();
    float rstd_[2];
#pragma unroll
    for (int h = 0; h < 2; h++) {
      float var = (vs[h] + RED2f[(1 - wcol) * 64 + wm + r + h * 8]) * (1.0f / 128.0f);
      rstd_[h] = rsqrtf(var + 1e-5f);
    }
#pragma unroll
    for (int nt = 0; nt < 8; nt++) {
      int c = wn2 + nt * 8 + cq;
      float2 g2 = *(const float2*)&gam[c];
      float2 b2 = *(const float2*)&bet[c];
#pragma unroll
      for (int h = 0; h < 2; h++) {
        float a0 = oacc[0][nt][h * 2 + 0] * invA[h] - oacc[1][nt][h * 2 + 0] * invB[h];
        float a1 = oacc[0][nt][h * 2 + 1] * invA[h] - oacc[1][nt][h * 2 + 1] * invB[h];
        float o0 = (a0 - mean_[h]) * rstd_[h] * g2.x + b2.x;
        float o1 = (a1 - mean_[h]) * rstd_[h] * g2.y + b2.y;
        size_t off = (size_t)(rowbase + q0 + wm + r + h * 8) * 128 + c;
        *(float2*)&out[off] = make_float2(o0, o1);
      }
    }
    __syncthreads();   // protect smem before next half reuses
  }
}

// ---------------- launch ----------------
extern "C" void kernel_launch(void* const* d_in, const int* in_sizes, int n_in,
                              void* d_out, int out_size) {
  const float* x     = (const float*)d_in[0];
  const float* Wq    = (const float*)d_in[1];
  const float* Wk    = (const float*)d_in[2];
  const float* Wv    = (const float*)d_in[3];
  const float* Wq_ss = (const float*)d_in[4];
  const float* Wk_ss = (const float*)d_in[5];
  const float* Wv_ss = (const float*)d_in[6];
  const float* Wq_se = (const float*)d_in[7];
  const float* Wk_se = (const float*)d_in[8];
  const float* Wv_se = (const float*)d_in[9];
  const float* g_in  = (const float*)d_in[10];
  const float* b_in  = (const float*)d_in[11];
  const float* g_ss  = (const float*)d_in[12];
  const float* b_ss  = (const float*)d_in[13];
  const float* g_se  = (const float*)d_in[14];
  const float* b_se  = (const float*)d_in[15];
  const float* g_out = (const float*)d_in[16];
  const float* b_out = (const float*)d_in[17];
  const float* lq1   = (const float*)d_in[18];
  const float* lq2   = (const float*)d_in[19];
  const float* lk1   = (const float*)d_in[20];
  const float* lk2   = (const float*)d_in[21];

  static bool attr_set = false;
  if (!attr_set) {
    cudaFuncSetAttribute(proj_mma_kernel, cudaFuncAttributeMaxDynamicSharedMemorySize,
                         PROJ_SMEM);
    cudaFuncSetAttribute(attn_mma_kernel, cudaFuncAttributeMaxDynamicSharedMemorySize,
                         ATTN_SMEM);
    attr_set = true;
  }

  lambda_kernel<<<1, 64>>>(lq1, lq2, lk1, lk2);

  WPrepParams wp;
  wp.W[0] = Wq_ss; wp.W[1] = Wq; wp.W[2] = Wq_se;
  wp.W[3] = Wk_ss; wp.W[4] = Wk; wp.W[5] = Wk_se;
  wp.W[6] = Wv_ss; wp.W[7] = Wv; wp.W[8] = Wv_se;
  wprep_kernel<<<dim3(32, 4, 9), dim3(32, 32)>>>(wp);

  NormParams np;
  np.x = x;
  np.g[0] = g_ss; np.g[1] = g_in; np.g[2] = g_se;
  np.b[0] = b_ss; np.b[1] = b_in; np.b[2] = b_se;
  norm_split_kernel<<<NROW / 8, dim3(32, 8)>>>(np);

  proj_mma_kernel<<<dim3(144, 3, 2), 256, PROJ_SMEM>>>();

  attn_mma_kernel<<<dim3(18, 8), 256, ATTN_SMEM>>>(g_out, b_out, (float*)d_out);
}

// round 12
// speedup vs baseline: 3.8768x; 1.0047x over previous
#include <cuda_runtime.h>
#include <cuda_bf16.h>
#include <cstdint>
#include <cstddef>

constexpr int Bn = 8;
constexpr int Tn = 2304;
constexpr int NROW = Bn * Tn;          // 18432
constexpr float LAMBDA_INIT_F = 0.6192834728526787f;
constexpr float QSCALE = 0.18033688011112042f;   // (1/8) * log2(e)

typedef unsigned long long ull;

__device__ float g_lam;
__device__ __align__(16) __nv_bfloat16 g_xh[NROW * 1024];
__device__ __align__(16) __nv_bfloat16 g_xl[NROW * 1024];
__device__ __align__(16) __nv_bfloat16 g_wh[9 * 128 * 1024];
__device__ __align__(16) __nv_bfloat16 g_wl[9 * 128 * 1024];
__device__ __align__(16) __nv_bfloat16 g_qh[NROW * 128];
__device__ __align__(16) __nv_bfloat16 g_ql[NROW * 128];
__device__ __align__(16) __nv_bfloat16 g_kh[NROW * 128];
__device__ __align__(16) __nv_bfloat16 g_kl[NROW * 128];
__device__ __align__(16) __nv_bfloat16 g_vh[NROW * 128];
__device__ __align__(16) __nv_bfloat16 g_vl[NROW * 128];

__device__ __forceinline__ float fast_exp2(float x) {
  x = fmaxf(x, -125.0f);
  float t = x + 12582912.0f;
  int e = __float_as_int(t) - 0x4B400000;
  float f = x - (t - 12582912.0f);
  float p =        1.3333558e-3f;
  p = fmaf(p, f,   9.6181291e-3f);
  p = fmaf(p, f,   5.5504109e-2f);
  p = fmaf(p, f,   2.4022651e-1f);
  p = fmaf(p, f,   6.9314718e-1f);
  p = fmaf(p, f,   1.0f);
  return __int_as_float(__float_as_int(p) + (e << 23));
}

__device__ __forceinline__ uint32_t smem_u32(const void* p) {
  uint32_t a;
  asm("{ .reg .u64 t; cvta.to.shared.u64 t, %1; cvt.u32.u64 %0, t; }" : "=r"(a) : "l"(p));
  return a;
}
__device__ __forceinline__ uint32_t sw128(uint32_t off) {
  return off ^ ((off >> 3) & 0x70);
}
__device__ __forceinline__ void cpasync16(uint32_t dst, const void* src) {
  asm volatile("cp.async.cg.shared.global [%0], [%1], 16;" :: "r"(dst), "l"(src));
}
__device__ __forceinline__ void cp_commit() {
  asm volatile("cp.async.commit_group;" ::: "memory");
}
__device__ __forceinline__ void cp_wait1() {
  asm volatile("cp.async.wait_group 1;" ::: "memory");
}
__device__ __forceinline__ void cp_wait0() {
  asm volatile("cp.async.wait_group 0;" ::: "memory");
}
__device__ __forceinline__ void ldsm4(uint32_t* r, uint32_t a) {
  asm volatile("ldmatrix.sync.aligned.m8n8.x4.shared.b16 {%0,%1,%2,%3}, [%4];"
               : "=r"(r[0]), "=r"(r[1]), "=r"(r[2]), "=r"(r[3]) : "r"(a));
}
__device__ __forceinline__ void ldsm4t(uint32_t* r, uint32_t a) {
  asm volatile("ldmatrix.sync.aligned.m8n8.x4.trans.shared.b16 {%0,%1,%2,%3}, [%4];"
               : "=r"(r[0]), "=r"(r[1]), "=r"(r[2]), "=r"(r[3]) : "r"(a));
}
__device__ __forceinline__ void mma16816(float* d, const uint32_t* a, uint32_t b0, uint32_t b1) {
  asm volatile(
      "mma.sync.aligned.m16n8k16.row.col.f32.bf16.bf16.f32 "
      "{%0,%1,%2,%3},{%4,%5,%6,%7},{%8,%9},{%0,%1,%2,%3};"
      : "+f"(d[0]), "+f"(d[1]), "+f"(d[2]), "+f"(d[3])
      : "r"(a[0]), "r"(a[1]), "r"(a[2]), "r"(a[3]), "r"(b0), "r"(b1));
}
__device__ __forceinline__ void hilo(float a, float b, uint32_t& h, uint32_t& l) {
  __nv_bfloat16 ha = __float2bfloat16_rn(a), hb = __float2bfloat16_rn(b);
  __nv_bfloat162 H; H.x = ha; H.y = hb;
  h = *(uint32_t*)&H;
  __nv_bfloat162 L;
  L.x = __float2bfloat16_rn(a - __bfloat162float(ha));
  L.y = __float2bfloat16_rn(b - __bfloat162float(hb));
  l = *(uint32_t*)&L;
}

// ---------------- lambda ----------------
__global__ void lambda_kernel(const float* __restrict__ lq1,
                              const float* __restrict__ lq2,
                              const float* __restrict__ lk1,
                              const float* __restrict__ lk2) {
  __shared__ float sh1[64], sh2[64];
  int t = threadIdx.x;
  sh1[t] = lq1[t] * lk1[t];
  sh2[t] = lq2[t] * lk2[t];
  __syncthreads();
  if (t == 0) {
    float a = 0.f, c = 0.f;
    for (int i = 0; i < 64; i++) { a += sh1[i]; c += sh2[i]; }
    g_lam = expf(a) - expf(c) + LAMBDA_INIT_F;
  }
}

// ---------------- LN + bf16 hi/lo split of x ----------------
struct NormParams {
  const float* x;
  const float* g[3];
  const float* b[3];
};

__global__ void norm_split_kernel(NormParams p) {
  int row = blockIdx.x * 8 + threadIdx.y;
  int t = row % Tn;
  int seg = t < 128 ? 0 : (t < 2176 ? 1 : 2);
  const float* __restrict__ gg = p.g[seg];
  const float* __restrict__ bb = p.b[seg];
  int lid = threadIdx.x;
  const float* xr = p.x + (size_t)row * 1024;

  float v[32];
  float s = 0.f, ss = 0.f;
#pragma unroll
  for (int i = 0; i < 8; i++) {
    float4 f = *(const float4*)&xr[i * 128 + lid * 4];
    v[i * 4 + 0] = f.x; v[i * 4 + 1] = f.y; v[i * 4 + 2] = f.z; v[i * 4 + 3] = f.w;
    s += f.x + f.y + f.z + f.w;
    ss += f.x * f.x + f.y * f.y + f.z * f.z + f.w * f.w;
  }
#pragma unroll
  for (int o = 16; o > 0; o >>= 1) {
    s += __shfl_xor_sync(0xffffffffu, s, o);
    ss += __shfl_xor_sync(0xffffffffu, ss, o);
  }
  float mean = s * (1.0f / 1024.0f);
  float var = fmaf(-mean, mean, ss * (1.0f / 1024.0f));
  float rstd = rsqrtf(var + 1e-5f);

  __nv_bfloat16* xh = g_xh + (size_t)row * 1024;
  __nv_bfloat16* xl = g_xl + (size_t)row * 1024;
#pragma unroll
  for (int i = 0; i < 8; i++) {
    int k = i * 128 + lid * 4;
    float4 gf = *(const float4*)&gg[k];
    float4 bf = *(const float4*)&bb[k];
    float a0 = (v[i * 4 + 0] - mean) * rstd * gf.x + bf.x;
    float a1 = (v[i * 4 + 1] - mean) * rstd * gf.y + bf.y;
    float a2 = (v[i * 4 + 2] - mean) * rstd * gf.z + bf.z;
    float a3 = (v[i * 4 + 3] - mean) * rstd * gf.w + bf.w;
    uint2 hp, lp;
    hilo(a0, a1, hp.x, lp.x);
    hilo(a2, a3, hp.y, lp.y);
    *(uint2*)&xh[k] = hp;
    *(uint2*)&xl[k] = lp;
  }
}

// ---------------- weight transpose + bf16 hi/lo split ----------------
struct WPrepParams { const float* W[9]; };

__global__ void wprep_kernel(WPrepParams p) {
  __shared__ float tile[32][33];
  int mat = blockIdx.z;
  const float* __restrict__ W = p.W[mat];
  int kb = blockIdx.x * 32, nb = blockIdx.y * 32;
  int tx = threadIdx.x, ty = threadIdx.y;
  tile[ty][tx] = W[(size_t)(kb + ty) * 128 + nb + tx];
  __syncthreads();
  float v = tile[tx][ty];
  __nv_bfloat16 h = __float2bfloat16_rn(v);
  __nv_bfloat16 l = __float2bfloat16_rn(v - __bfloat162float(h));
  size_t o = (size_t)mat * 128 * 1024 + (size_t)(nb + ty) * 1024 + kb + tx;
  g_wh[o] = h;
  g_wl[o] = l;
}

// ---------------- projection GEMM (unchanged R10) ----------------
constexpr int PB_AH = 0;
constexpr int PB_AL = 16384;
constexpr int PB_BH = 32768;
constexpr int PB_BL = 40960;
constexpr int PBUF = 49152;
constexpr int PROJ_SMEM = 2 * PBUF;   // 98304

__global__ __launch_bounds__(256, 2) void proj_mma_kernel() {
  extern __shared__ char smem[];
  uint32_t sb = smem_u32(smem);
  const int tid = threadIdx.x;
  const int rt = blockIdx.x, mat = blockIdx.y, nh = blockIdx.z;
  const int row0 = rt * 128;
  const int t0 = row0 % Tn;
  const int seg = t0 < 128 ? 0 : (t0 < 2176 ? 1 : 2);
  const size_t wbase = (size_t)(mat * 3 + seg) * 128 * 1024 + (size_t)nh * 64 * 1024;
  const __nv_bfloat16* __restrict__ Ah_g = g_xh + (size_t)row0 * 1024;
  const __nv_bfloat16* __restrict__ Al_g = g_xl + (size_t)row0 * 1024;
  const __nv_bfloat16* __restrict__ Bh_g = g_wh + wbase;
  const __nv_bfloat16* __restrict__ Bl_g = g_wl + wbase;

  const int lane = tid & 31;
  const int wid = tid >> 5;
  const int wm = (wid & 3) * 32;
  const int wn = (wid >> 2) * 32;
  const int lrow = lane & 7;
  const int sel = lane >> 3;
  const int selm = (sel & 1) * 8;
  const int selc = (sel >> 1) * 16;

  float acc[2][4][4];
#pragma unroll
  for (int mt = 0; mt < 2; mt++)
#pragma unroll
    for (int nt = 0; nt < 4; nt++)
#pragma unroll
      for (int j = 0; j < 4; j++) acc[mt][nt][j] = 0.f;

  auto issue = [&](int ch, int b) {
    const int k0 = ch * 64;
    const uint32_t dst = sb + b * PBUF;
#pragma unroll
    for (int it = 0; it < 4; it++) {
      int i = tid + it * 256;
      int r = i >> 3, c = i & 7;
      uint32_t d = sw128((uint32_t)(r * 128 + c * 16));
      size_t go = (size_t)r * 1024 + k0 + c * 8;
      cpasync16(dst + PB_AH + d, Ah_g + go);
      cpasync16(dst + PB_AL + d, Al_g + go);
    }
#pragma unroll
    for (int it = 0; it < 2; it++) {
      int i = tid + it * 256;
      int r = i >> 3, c = i & 7;
      uint32_t d = sw128((uint32_t)(r * 128 + c * 16));
      size_t go = (size_t)r * 1024 + k0 + c * 8;
      cpasync16(dst + PB_BH + d, Bh_g + go);
      cpasync16(dst + PB_BL + d, Bl_g + go);
    }
  };

  issue(0, 0);
  cp_commit();

  for (int ch = 0; ch < 16; ch++) {
    if (ch + 1 < 16) {
      issue(ch + 1, (ch + 1) & 1);
      cp_commit();
      cp_wait1();
    } else {
      cp_wait0();
    }
    __syncthreads();

    const uint32_t base = sb + (ch & 1) * PBUF;
#pragma unroll
    for (int ks = 0; ks < 4; ks++) {
      const int colb = ks * 32 + selc;
      uint32_t ah[2][4], al[2][4];
#pragma unroll
      for (int mt = 0; mt < 2; mt++) {
        int r = wm + mt * 16 + selm + lrow;
        uint32_t off = sw128((uint32_t)(r * 128 + colb));
        ldsm4(ah[mt], base + PB_AH + off);
        ldsm4(al[mt], base + PB_AL + off);
      }
      uint32_t bh[4][2], bl[4][2];
#pragma unroll
      for (int np = 0; np < 2; np++) {
        int r = wn + np * 16 + selm + lrow;
        uint32_t off = sw128((uint32_t)(r * 128 + colb));
        uint32_t t4[4];
        ldsm4(t4, base + PB_BH + off);
        bh[2 * np][0] = t4[0]; bh[2 * np][1] = t4[2];
        bh[2 * np + 1][0] = t4[1]; bh[2 * np + 1][1] = t4[3];
        ldsm4(t4, base + PB_BL + off);
        bl[2 * np][0] = t4[0]; bl[2 * np][1] = t4[2];
        bl[2 * np + 1][0] = t4[1]; bl[2 * np + 1][1] = t4[3];
      }
#pragma unroll
      for (int mt = 0; mt < 2; mt++)
#pragma unroll
        for (int nt = 0; nt < 4; nt++) {
          mma16816(acc[mt][nt], ah[mt], bh[nt][0], bh[nt][1]);
          mma16816(acc[mt][nt], ah[mt], bl[nt][0], bl[nt][1]);
          mma16816(acc[mt][nt], al[mt], bh[nt][0], bh[nt][1]);
        }
    }
    __syncthreads();
  }

  __nv_bfloat16* __restrict__ oh = (mat == 0) ? g_qh : (mat == 1) ? g_kh : g_vh;
  __nv_bfloat16* __restrict__ ol = (mat == 0) ? g_ql : (mat == 1) ? g_kl : g_vl;
  const int orow = lane >> 2, ocol = (lane & 3) * 2;
#pragma unroll
  for (int mt = 0; mt < 2; mt++)
#pragma unroll
    for (int nt = 0; nt < 4; nt++) {
      int r = row0 + wm + mt * 16 + orow;
      int c = nh * 64 + wn + nt * 8 + ocol;
      uint32_t h0, l0, h1, l1;
      hilo(acc[mt][nt][0], acc[mt][nt][1], h0, l0);
      hilo(acc[mt][nt][2], acc[mt][nt][3], h1, l1);
      *(uint32_t*)&oh[(size_t)r * 128 + c] = h0;
      *(uint32_t*)&ol[(size_t)r * 128 + c] = l0;
      *(uint32_t*)&oh[(size_t)(r + 8) * 128 + c] = h1;
      *(uint32_t*)&ol[(size_t)(r + 8) * 128 + c] = l1;
    }
}

// ---------------- tensor-core dual flash attention (register-P) ----------------
// warps: 4 row groups (16 rows) x 2 key halves (32 keys). O partial per key half,
// full 128 cols; summed in epilogue via padded scratch.
constexpr int KVBUF = 65536;              // Kh(2x8K) Kl(2x8K) Vh(2x8K) Vl(2x8K)
constexpr int AOFF_Q   = 131072;          // Qh m0, Qh m1, Ql m0, Ql m1 (8K each)
constexpr int AOFF_SCR = 163840;          // 64 x 132 f32 = 33792 B
constexpr int AOFF_RED = 197632;          // 1024 B
constexpr int AOFF_RED2 = 198656;         // 1024 B
constexpr int ATTN_SMEM = 199680;

__global__ __launch_bounds__(256, 1) void attn_mma_kernel(
    const float* __restrict__ gam, const float* __restrict__ bet,
    float* __restrict__ out) {
  extern __shared__ char smem[];
  uint32_t sb = smem_u32(smem);
  float* REDf = (float*)(smem + AOFF_RED);
  float* RED2f = (float*)(smem + AOFF_RED2);
  float* SCR = (float*)(smem + AOFF_SCR);

  const int tid = threadIdx.x;
  const int lane = tid & 31;
  const int wid = tid >> 5;
  const int wm = (wid & 3) * 16;
  const int kc = wid >> 2;      // key half 0/1
  const int kn = kc * 32;       // key base for S cols
  const int lrow = lane & 7;
  const int sel = lane >> 3;
  const int selm = (sel & 1) * 8;
  const int selc = (sel >> 1) * 16;
  const int r = lane >> 2;
  const int cq = (lane & 3) * 2;

  const int rowbase = (int)blockIdx.y * Tn;
  const float lam = g_lam;

  auto issueKV = [&](int kt, int b) {
    const int k0g = kt * 64;
    const uint32_t dst = sb + b * KVBUF;
#pragma unroll
    for (int it = 0; it < 16; it++) {
      int idx = tid + it * 256;
      int part = idx >> 9;
      int j = idx & 511;
      int key = j >> 3, c = j & 7;
      uint32_t so = (uint32_t)part * 8192 + sw128((uint32_t)(key * 128 + c * 16));
      size_t go = (size_t)(rowbase + k0g + key) * 128 + (part & 1) * 64 + c * 8;
      const __nv_bfloat16* src =
          (part < 2) ? g_kh : (part < 4) ? g_kl : (part < 6) ? g_vh : g_vl;
      cpasync16(dst + so, src + go);
    }
  };
  auto issueQ = [&](int q0) {
#pragma unroll
    for (int it = 0; it < 8; it++) {
      int idx = tid + it * 256;
      int part = idx >> 9;
      int j = idx & 511;
      int row = j >> 3, c = j & 7;
      uint32_t so = AOFF_Q + (uint32_t)part * 8192 + sw128((uint32_t)(row * 128 + c * 16));
      size_t go = (size_t)(rowbase + q0 + row) * 128 + (part & 1) * 64 + c * 8;
      const __nv_bfloat16* src = (part < 2) ? g_qh : g_ql;
      cpasync16(sb + so, src + go);
    }
  };

  for (int half = 0; half < 2; half++) {
    const int qt = half ? (35 - (int)blockIdx.x) : (int)blockIdx.x;
    const int q0 = qt * 64;

    float oacc[2][16][4];           // partial O over this warp's 32 keys, all 128 cols
    float mrow[2][2], lrow_s[2][2];
#pragma unroll
    for (int m = 0; m < 2; m++) {
#pragma unroll
      for (int h = 0; h < 2; h++) { mrow[m][h] = -3.0e38f; lrow_s[m][h] = 0.f; }
#pragma unroll
      for (int nt = 0; nt < 16; nt++)
#pragma unroll
        for (int j = 0; j < 4; j++) oacc[m][nt][j] = 0.f;
    }

    issueQ(q0);
    issueKV(0, 0);
    cp_commit();

    for (int kt = 0; kt <= qt; kt++) {
      if (kt < qt) {
        issueKV(kt + 1, (kt + 1) & 1);
        cp_commit();
        cp_wait1();
      } else {
        cp_wait0();
      }
      __syncthreads();   // A: buffers ready

      const uint32_t buf = sb + (kt & 1) * KVBUF;
      const int k0 = kt * 64;

      // ---- S = Q K^T (this warp: 16 rows x keys [kn, kn+32)) ----
      float sacc[2][4][4];
#pragma unroll
      for (int m = 0; m < 2; m++)
#pragma unroll
        for (int nt = 0; nt < 4; nt++)
#pragma unroll
          for (int j = 0; j < 4; j++) sacc[m][nt][j] = 0.f;

#pragma unroll
      for (int m = 0; m < 2; m++) {
        const uint32_t Qh = sb + AOFF_Q + m * 8192;
        const uint32_t Ql = sb + AOFF_Q + 16384 + m * 8192;
        const uint32_t Kh = buf + m * 8192;
        const uint32_t Kl = buf + 16384 + m * 8192;
#pragma unroll
        for (int ks = 0; ks < 4; ks++) {
          const int colb = ks * 32 + selc;
          uint32_t aoff = sw128((uint32_t)((wm + selm + lrow) * 128 + colb));
          uint32_t qh[4], ql[4];
          ldsm4(qh, Qh + aoff);
          ldsm4(ql, Ql + aoff);
          uint32_t bh[4][2], bl[4][2];
#pragma unroll
          for (int np = 0; np < 2; np++) {
            uint32_t boff = sw128((uint32_t)((kn + np * 16 + selm + lrow) * 128 + colb));
            uint32_t t4[4];
            ldsm4(t4, Kh + boff);
            bh[2 * np][0] = t4[0]; bh[2 * np][1] = t4[2];
            bh[2 * np + 1][0] = t4[1]; bh[2 * np + 1][1] = t4[3];
            ldsm4(t4, Kl + boff);
            bl[2 * np][0] = t4[0]; bl[2 * np][1] = t4[2];
            bl[2 * np + 1][0] = t4[1]; bl[2 * np + 1][1] = t4[3];
          }
#pragma unroll
          for (int nt = 0; nt < 4; nt++) {
            mma16816(sacc[m][nt], qh, bh[nt][0], bh[nt][1]);
            mma16816(sacc[m][nt], ql, bh[nt][0], bh[nt][1]);
            mma16816(sacc[m][nt], qh, bl[nt][0], bl[nt][1]);
          }
        }
      }

      // ---- softmax (cross-key-half reductions via smem) ----
      const bool diag = (kt == qt);
      float mx[2][2];
#pragma unroll
      for (int m = 0; m < 2; m++)
#pragma unroll
        for (int h = 0; h < 2; h++) mx[m][h] = -3.0e38f;

#pragma unroll
      for (int m = 0; m < 2; m++)
#pragma unroll
        for (int nt = 0; nt < 4; nt++)
#pragma unroll
          for (int h = 0; h < 2; h++)
#pragma unroll
            for (int j = 0; j < 2; j++) {
              float v = sacc[m][nt][h * 2 + j] * QSCALE;
              if (diag && (k0 + kn + nt * 8 + cq + j) > (q0 + wm + r + h * 8)) v = -3.0e38f;
              sacc[m][nt][h * 2 + j] = v;
              mx[m][h] = fmaxf(mx[m][h], v);
            }
#pragma unroll
      for (int m = 0; m < 2; m++)
#pragma unroll
        for (int h = 0; h < 2; h++) {
          mx[m][h] = fmaxf(mx[m][h], __shfl_xor_sync(0xffffffffu, mx[m][h], 1));
          mx[m][h] = fmaxf(mx[m][h], __shfl_xor_sync(0xffffffffu, mx[m][h], 2));
        }
      if ((lane & 3) == 0) {
#pragma unroll
        for (int m = 0; m < 2; m++)
#pragma unroll
          for (int h = 0; h < 2; h++)
            REDf[(kc * 2 + m) * 64 + wm + r + h * 8] = mx[m][h];
      }
      __syncthreads();   // B

      float alpha[2][2], lsum[2][2];
#pragma unroll
      for (int m = 0; m < 2; m++)
#pragma unroll
        for (int h = 0; h < 2; h++) {
          float g = fmaxf(mx[m][h], REDf[((1 - kc) * 2 + m) * 64 + wm + r + h * 8]);
          float mn = fmaxf(mrow[m][h], g);
          alpha[m][h] = fast_exp2(mrow[m][h] - mn);
          mrow[m][h] = mn;
          lsum[m][h] = 0.f;
        }

      // exp in place; P fragments in registers (S-accum -> A-frag layout)
      uint32_t pfh[2][2][4], pfl[2][2][4];
#pragma unroll
      for (int m = 0; m < 2; m++) {
#pragma unroll
        for (int nt = 0; nt < 4; nt++)
#pragma unroll
          for (int h = 0; h < 2; h++) {
            float p0 = fast_exp2(sacc[m][nt][h * 2 + 0] - mrow[m][h]);
            float p1 = fast_exp2(sacc[m][nt][h * 2 + 1] - mrow[m][h]);
            lsum[m][h] += p0 + p1;
            sacc[m][nt][h * 2 + 0] = p0;
            sacc[m][nt][h * 2 + 1] = p1;
          }
#pragma unroll
        for (int ks = 0; ks < 2; ks++) {
          hilo(sacc[m][2 * ks][0], sacc[m][2 * ks][1], pfh[m][ks][0], pfl[m][ks][0]);
          hilo(sacc[m][2 * ks][2], sacc[m][2 * ks][3], pfh[m][ks][1], pfl[m][ks][1]);
          hilo(sacc[m][2 * ks + 1][0], sacc[m][2 * ks + 1][1], pfh[m][ks][2], pfl[m][ks][2]);
          hilo(sacc[m][2 * ks + 1][2], sacc[m][2 * ks + 1][3], pfh[m][ks][3], pfl[m][ks][3]);
        }
      }
#pragma unroll
      for (int m = 0; m < 2; m++)
#pragma unroll
        for (int h = 0; h < 2; h++) {
          lsum[m][h] += __shfl_xor_sync(0xffffffffu, lsum[m][h], 1);
          lsum[m][h] += __shfl_xor_sync(0xffffffffu, lsum[m][h], 2);
        }
      if ((lane & 3) == 0) {
#pragma unroll
        for (int m = 0; m < 2; m++)
#pragma unroll
          for (int h = 0; h < 2; h++)
            RED2f[(kc * 2 + m) * 64 + wm + r + h * 8] = lsum[m][h];
      }
      // rescale partial O by alpha
#pragma unroll
      for (int m = 0; m < 2; m++)
#pragma unroll
        for (int nt = 0; nt < 16; nt++) {
          oacc[m][nt][0] *= alpha[m][0];
          oacc[m][nt][1] *= alpha[m][0];
          oacc[m][nt][2] *= alpha[m][1];
          oacc[m][nt][3] *= alpha[m][1];
        }
      __syncthreads();   // C: sums visible
#pragma unroll
      for (int m = 0; m < 2; m++)
#pragma unroll
        for (int h = 0; h < 2; h++) {
          float tot = lsum[m][h] + RED2f[((1 - kc) * 2 + m) * 64 + wm + r + h * 8];
          lrow_s[m][h] = lrow_s[m][h] * alpha[m][h] + tot;
        }

      // ---- O += P V (P from registers; V rows = this warp's 32 keys) ----
#pragma unroll
      for (int ks = 0; ks < 2; ks++) {
        const int vrow = kn + ks * 16 + selm + lrow;
#pragma unroll
        for (int np = 0; np < 8; np++) {
          const int part = np >> 2;
          const uint32_t boff = (uint32_t)part * 8192 +
              sw128((uint32_t)(vrow * 128 + (np & 3) * 32 + selc));
          uint32_t vh4[4], vl4[4];
          ldsm4t(vh4, buf + 32768 + boff);
          ldsm4t(vl4, buf + 49152 + boff);
#pragma unroll
          for (int m = 0; m < 2; m++)
#pragma unroll
            for (int e = 0; e < 2; e++) {
              float* d = oacc[m][2 * np + e];
              mma16816(d, pfh[m][ks], vh4[2 * e], vh4[2 * e + 1]);
              mma16816(d, pfl[m][ks], vh4[2 * e], vh4[2 * e + 1]);
              mma16816(d, pfh[m][ks], vl4[2 * e], vl4[2 * e + 1]);
            }
        }
      }
      __syncthreads();   // D: protect KV buffer reuse
    }

    // ---- epilogue: partial-O reduction + combine + output LN ----
#pragma unroll
    for (int m = 0; m < 2; m++) {
      if (kc == 1) {
#pragma unroll
        for (int nt = 0; nt < 16; nt++) {
#pragma unroll
          for (int h = 0; h < 2; h++) {
            int rr = wm + r + h * 8;
            SCR[rr * 132 + nt * 8 + cq]     = oacc[m][nt][h * 2 + 0];
            SCR[rr * 132 + nt * 8 + cq + 1] = oacc[m][nt][h * 2 + 1];
          }
        }
      }
      __syncthreads();
      if (kc == 0) {
#pragma unroll
        for (int nt = 0; nt < 16; nt++)
#pragma unroll
          for (int h = 0; h < 2; h++) {
            int rr = wm + r + h * 8;
            oacc[m][nt][h * 2 + 0] += SCR[rr * 132 + nt * 8 + cq];
            oacc[m][nt][h * 2 + 1] += SCR[rr * 132 + nt * 8 + cq + 1];
          }
      }
      __syncthreads();
    }

    if (kc == 0) {
      float invA[2], invB[2];
#pragma unroll
      for (int h = 0; h < 2; h++) {
        invA[h] = 1.0f / lrow_s[0][h];
        invB[h] = lam / lrow_s[1][h];
      }
      float rs[2] = {0.f, 0.f};
#pragma unroll
      for (int nt = 0; nt < 16; nt++)
#pragma unroll
        for (int h = 0; h < 2; h++)
#pragma unroll
          for (int j = 0; j < 2; j++)
            rs[h] += oacc[0][nt][h * 2 + j] * invA[h] - oacc[1][nt][h * 2 + j] * invB[h];
#pragma unroll
      for (int h = 0; h < 2; h++) {
        rs[h] += __shfl_xor_sync(0xffffffffu, rs[h], 1);
        rs[h] += __shfl_xor_sync(0xffffffffu, rs[h], 2);
      }
      float mean_[2];
#pragma unroll
      for (int h = 0; h < 2; h++) mean_[h] = rs[h] * (1.0f / 128.0f);

      float vs[2] = {0.f, 0.f};
#pragma unroll
      for (int nt = 0; nt < 16; nt++)
#pragma unroll
        for (int h = 0; h < 2; h++)
#pragma unroll
          for (int j = 0; j < 2; j++) {
            float a = oacc[0][nt][h * 2 + j] * invA[h] - oacc[1][nt][h * 2 + j] * invB[h] - mean_[h];
            vs[h] += a * a;
          }
#pragma unroll
      for (int h = 0; h < 2; h++) {
        vs[h] += __shfl_xor_sync(0xffffffffu, vs[h], 1);
        vs[h] += __shfl_xor_sync(0xffffffffu, vs[h], 2);
      }
      float rstd_[2];
#pragma unroll
      for (int h = 0; h < 2; h++)
        rstd_[h] = rsqrtf(vs[h] * (1.0f / 128.0f) + 1e-5f);

#pragma unroll
      for (int nt = 0; nt < 16; nt++) {
        int c = nt * 8 + cq;
        float2 g2 = *(const float2*)&gam[c];
        float2 b2 = *(const float2*)&bet[c];
#pragma unroll
        for (int h = 0; h < 2; h++) {
          float a0 = oacc[0][nt][h * 2 + 0] * invA[h] - oacc[1][nt][h * 2 + 0] * invB[h];
          float a1 = oacc[0][nt][h * 2 + 1] * invA[h] - oacc[1][nt][h * 2 + 1] * invB[h];
          float o0 = (a0 - mean_[h]) * rstd_[h] * g2.x + b2.x;
          float o1 = (a1 - mean_[h]) * rstd_[h] * g2.y + b2.y;
          size_t off = (size_t)(rowbase + q0 + wm + r + h * 8) * 128 + c;
          *(float2*)&out[off] = make_float2(o0, o1);
        }
      }
    }
    __syncthreads();   // protect smem before next half reuses
  }
}

// ---------------- launch ----------------
extern "C" void kernel_launch(void* const* d_in, const int* in_sizes, int n_in,
                              void* d_out, int out_size) {
  const float* x     = (const float*)d_in[0];
  const float* Wq    = (const float*)d_in[1];
  const float* Wk    = (const float*)d_in[2];
  const float* Wv    = (const float*)d_in[3];
  const float* Wq_ss = (const float*)d_in[4];
  const float* Wk_ss = (const float*)d_in[5];
  const float* Wv_ss = (const float*)d_in[6];
  const float* Wq_se = (const float*)d_in[7];
  const float* Wk_se = (const float*)d_in[8];
  const float* Wv_se = (const float*)d_in[9];
  const float* g_in  = (const float*)d_in[10];
  const float* b_in  = (const float*)d_in[11];
  const float* g_ss  = (const float*)d_in[12];
  const float* b_ss  = (const float*)d_in[13];
  const float* g_se  = (const float*)d_in[14];
  const float* b_se  = (const float*)d_in[15];
  const float* g_out = (const float*)d_in[16];
  const float* b_out = (const float*)d_in[17];
  const float* lq1   = (const float*)d_in[18];
  const float* lq2   = (const float*)d_in[19];
  const float* lk1   = (const float*)d_in[20];
  const float* lk2   = (const float*)d_in[21];

  static bool attr_set = false;
  if (!attr_set) {
    cudaFuncSetAttribute(proj_mma_kernel, cudaFuncAttributeMaxDynamicSharedMemorySize,
                         PROJ_SMEM);
    cudaFuncSetAttribute(attn_mma_kernel, cudaFuncAttributeMaxDynamicSharedMemorySize,
                         ATTN_SMEM);
    attr_set = true;
  }

  lambda_kernel<<<1, 64>>>(lq1, lq2, lk1, lk2);

  WPrepParams wp;
  wp.W[0] = Wq_ss; wp.W[1] = Wq; wp.W[2] = Wq_se;
  wp.W[3] = Wk_ss; wp.W[4] = Wk; wp.W[5] = Wk_se;
  wp.W[6] = Wv_ss; wp.W[7] = Wv; wp.W[8] = Wv_se;
  wprep_kernel<<<dim3(32, 4, 9), dim3(32, 32)>>>(wp);

  NormParams np;
  np.x = x;
  np.g[0] = g_ss; np.g[1] = g_in; np.g[2] = g_se;
  np.b[0] = b_ss; np.b[1] = b_in; np.b[2] = b_se;
  norm_split_kernel<<<NROW / 8, dim3(32, 8)>>>(np);

  proj_mma_kernel<<<dim3(144, 3, 2), 256, PROJ_SMEM>>>();

  attn_mma_kernel<<<dim3(18, 8), 256, ATTN_SMEM>>>(g_out, b_out, (float*)d_out);
}

// round 13
// speedup vs baseline: 4.1358x; 1.0668x over previous
#include <cuda_runtime.h>
#include <cuda_bf16.h>
#include <cstdint>
#include <cstddef>

constexpr int Bn = 8;
constexpr int Tn = 2304;
constexpr int NROW = Bn * Tn;          // 18432
constexpr float LAMBDA_INIT_F = 0.6192834728526787f;
constexpr float QSCALE = 0.18033688011112042f;   // (1/8) * log2(e)

typedef unsigned long long ull;

__device__ float g_lam;
__device__ __align__(16) __nv_bfloat16 g_xh[NROW * 1024];
__device__ __align__(16) __nv_bfloat16 g_xl[NROW * 1024];
__device__ __align__(16) __nv_bfloat16 g_wh[9 * 128 * 1024];
__device__ __align__(16) __nv_bfloat16 g_wl[9 * 128 * 1024];
__device__ __align__(16) __nv_bfloat16 g_qh[NROW * 128];
__device__ __align__(16) __nv_bfloat16 g_ql[NROW * 128];
__device__ __align__(16) __nv_bfloat16 g_kh[NROW * 128];
__device__ __align__(16) __nv_bfloat16 g_kl[NROW * 128];
__device__ __align__(16) __nv_bfloat16 g_vh[NROW * 128];
__device__ __align__(16) __nv_bfloat16 g_vl[NROW * 128];

__device__ __forceinline__ float fast_exp2(float x) {
  x = fmaxf(x, -125.0f);
  float t = x + 12582912.0f;
  int e = __float_as_int(t) - 0x4B400000;
  float f = x - (t - 12582912.0f);
  float p =        1.3333558e-3f;
  p = fmaf(p, f,   9.6181291e-3f);
  p = fmaf(p, f,   5.5504109e-2f);
  p = fmaf(p, f,   2.4022651e-1f);
  p = fmaf(p, f,   6.9314718e-1f);
  p = fmaf(p, f,   1.0f);
  return __int_as_float(__float_as_int(p) + (e << 23));
}

__device__ __forceinline__ uint32_t smem_u32(const void* p) {
  uint32_t a;
  asm("{ .reg .u64 t; cvta.to.shared.u64 t, %1; cvt.u32.u64 %0, t; }" : "=r"(a) : "l"(p));
  return a;
}
__device__ __forceinline__ uint32_t sw128(uint32_t off) {
  return off ^ ((off >> 3) & 0x70);
}
__device__ __forceinline__ void cpasync16(uint32_t dst, const void* src) {
  asm volatile("cp.async.cg.shared.global [%0], [%1], 16;" :: "r"(dst), "l"(src));
}
__device__ __forceinline__ void cp_commit() {
  asm volatile("cp.async.commit_group;" ::: "memory");
}
__device__ __forceinline__ void cp_wait1() {
  asm volatile("cp.async.wait_group 1;" ::: "memory");
}
__device__ __forceinline__ void cp_wait0() {
  asm volatile("cp.async.wait_group 0;" ::: "memory");
}
__device__ __forceinline__ void ldsm4(uint32_t* r, uint32_t a) {
  asm volatile("ldmatrix.sync.aligned.m8n8.x4.shared.b16 {%0,%1,%2,%3}, [%4];"
               : "=r"(r[0]), "=r"(r[1]), "=r"(r[2]), "=r"(r[3]) : "r"(a));
}
__device__ __forceinline__ void ldsm4t(uint32_t* r, uint32_t a) {
  asm volatile("ldmatrix.sync.aligned.m8n8.x4.trans.shared.b16 {%0,%1,%2,%3}, [%4];"
               : "=r"(r[0]), "=r"(r[1]), "=r"(r[2]), "=r"(r[3]) : "r"(a));
}
__device__ __forceinline__ void mma16816(float* d, const uint32_t* a, uint32_t b0, uint32_t b1) {
  asm volatile(
      "mma.sync.aligned.m16n8k16.row.col.f32.bf16.bf16.f32 "
      "{%0,%1,%2,%3},{%4,%5,%6,%7},{%8,%9},{%0,%1,%2,%3};"
      : "+f"(d[0]), "+f"(d[1]), "+f"(d[2]), "+f"(d[3])
      : "r"(a[0]), "r"(a[1]), "r"(a[2]), "r"(a[3]), "r"(b0), "r"(b1));
}
__device__ __forceinline__ void hilo(float a, float b, uint32_t& h, uint32_t& l) {
  __nv_bfloat16 ha = __float2bfloat16_rn(a), hb = __float2bfloat16_rn(b);
  __nv_bfloat162 H; H.x = ha; H.y = hb;
  h = *(uint32_t*)&H;
  __nv_bfloat162 L;
  L.x = __float2bfloat16_rn(a - __bfloat162float(ha));
  L.y = __float2bfloat16_rn(b - __bfloat162float(hb));
  l = *(uint32_t*)&L;
}

// ---------------- lambda ----------------
__global__ void lambda_kernel(const float* __restrict__ lq1,
                              const float* __restrict__ lq2,
                              const float* __restrict__ lk1,
                              const float* __restrict__ lk2) {
  __shared__ float sh1[64], sh2[64];
  int t = threadIdx.x;
  sh1[t] = lq1[t] * lk1[t];
  sh2[t] = lq2[t] * lk2[t];
  __syncthreads();
  if (t == 0) {
    float a = 0.f, c = 0.f;
    for (int i = 0; i < 64; i++) { a += sh1[i]; c += sh2[i]; }
    g_lam = expf(a) - expf(c) + LAMBDA_INIT_F;
  }
}

// ---------------- LN + bf16 hi/lo split of x ----------------
struct NormParams {
  const float* x;
  const float* g[3];
  const float* b[3];
};

__global__ void norm_split_kernel(NormParams p) {
  int row = blockIdx.x * 8 + threadIdx.y;
  int t = row % Tn;
  int seg = t < 128 ? 0 : (t < 2176 ? 1 : 2);
  const float* __restrict__ gg = p.g[seg];
  const float* __restrict__ bb = p.b[seg];
  int lid = threadIdx.x;
  const float* xr = p.x + (size_t)row * 1024;

  float v[32];
  float s = 0.f, ss = 0.f;
#pragma unroll
  for (int i = 0; i < 8; i++) {
    float4 f = *(const float4*)&xr[i * 128 + lid * 4];
    v[i * 4 + 0] = f.x; v[i * 4 + 1] = f.y; v[i * 4 + 2] = f.z; v[i * 4 + 3] = f.w;
    s += f.x + f.y + f.z + f.w;
    ss += f.x * f.x + f.y * f.y + f.z * f.z + f.w * f.w;
  }
#pragma unroll
  for (int o = 16; o > 0; o >>= 1) {
    s += __shfl_xor_sync(0xffffffffu, s, o);
    ss += __shfl_xor_sync(0xffffffffu, ss, o);
  }
  float mean = s * (1.0f / 1024.0f);
  float var = fmaf(-mean, mean, ss * (1.0f / 1024.0f));
  float rstd = rsqrtf(var + 1e-5f);

  __nv_bfloat16* xh = g_xh + (size_t)row * 1024;
  __nv_bfloat16* xl = g_xl + (size_t)row * 1024;
#pragma unroll
  for (int i = 0; i < 8; i++) {
    int k = i * 128 + lid * 4;
    float4 gf = *(const float4*)&gg[k];
    float4 bf = *(const float4*)&bb[k];
    float a0 = (v[i * 4 + 0] - mean) * rstd * gf.x + bf.x;
    float a1 = (v[i * 4 + 1] - mean) * rstd * gf.y + bf.y;
    float a2 = (v[i * 4 + 2] - mean) * rstd * gf.z + bf.z;
    float a3 = (v[i * 4 + 3] - mean) * rstd * gf.w + bf.w;
    uint2 hp, lp;
    hilo(a0, a1, hp.x, lp.x);
    hilo(a2, a3, hp.y, lp.y);
    *(uint2*)&xh[k] = hp;
    *(uint2*)&xl[k] = lp;
  }
}

// ---------------- weight transpose + bf16 hi/lo split ----------------
struct WPrepParams { const float* W[9]; };

__global__ void wprep_kernel(WPrepParams p) {
  __shared__ float tile[32][33];
  int mat = blockIdx.z;
  const float* __restrict__ W = p.W[mat];
  int kb = blockIdx.x * 32, nb = blockIdx.y * 32;
  int tx = threadIdx.x, ty = threadIdx.y;
  tile[ty][tx] = W[(size_t)(kb + ty) * 128 + nb + tx];
  __syncthreads();
  float v = tile[tx][ty];
  __nv_bfloat16 h = __float2bfloat16_rn(v);
  __nv_bfloat16 l = __float2bfloat16_rn(v - __bfloat162float(h));
  size_t o = (size_t)mat * 128 * 1024 + (size_t)(nb + ty) * 1024 + kb + tx;
  g_wh[o] = h;
  g_wl[o] = l;
}

// ---------------- projection GEMM (unchanged R10) ----------------
constexpr int PB_AH = 0;
constexpr int PB_AL = 16384;
constexpr int PB_BH = 32768;
constexpr int PB_BL = 40960;
constexpr int PBUF = 49152;
constexpr int PROJ_SMEM = 2 * PBUF;   // 98304

__global__ __launch_bounds__(256, 2) void proj_mma_kernel() {
  extern __shared__ char smem[];
  uint32_t sb = smem_u32(smem);
  const int tid = threadIdx.x;
  const int rt = blockIdx.x, mat = blockIdx.y, nh = blockIdx.z;
  const int row0 = rt * 128;
  const int t0 = row0 % Tn;
  const int seg = t0 < 128 ? 0 : (t0 < 2176 ? 1 : 2);
  const size_t wbase = (size_t)(mat * 3 + seg) * 128 * 1024 + (size_t)nh * 64 * 1024;
  const __nv_bfloat16* __restrict__ Ah_g = g_xh + (size_t)row0 * 1024;
  const __nv_bfloat16* __restrict__ Al_g = g_xl + (size_t)row0 * 1024;
  const __nv_bfloat16* __restrict__ Bh_g = g_wh + wbase;
  const __nv_bfloat16* __restrict__ Bl_g = g_wl + wbase;

  const int lane = tid & 31;
  const int wid = tid >> 5;
  const int wm = (wid & 3) * 32;
  const int wn = (wid >> 2) * 32;
  const int lrow = lane & 7;
  const int sel = lane >> 3;
  const int selm = (sel & 1) * 8;
  const int selc = (sel >> 1) * 16;

  float acc[2][4][4];
#pragma unroll
  for (int mt = 0; mt < 2; mt++)
#pragma unroll
    for (int nt = 0; nt < 4; nt++)
#pragma unroll
      for (int j = 0; j < 4; j++) acc[mt][nt][j] = 0.f;

  auto issue = [&](int ch, int b) {
    const int k0 = ch * 64;
    const uint32_t dst = sb + b * PBUF;
#pragma unroll
    for (int it = 0; it < 4; it++) {
      int i = tid + it * 256;
      int r = i >> 3, c = i & 7;
      uint32_t d = sw128((uint32_t)(r * 128 + c * 16));
      size_t go = (size_t)r * 1024 + k0 + c * 8;
      cpasync16(dst + PB_AH + d, Ah_g + go);
      cpasync16(dst + PB_AL + d, Al_g + go);
    }
#pragma unroll
    for (int it = 0; it < 2; it++) {
      int i = tid + it * 256;
      int r = i >> 3, c = i & 7;
      uint32_t d = sw128((uint32_t)(r * 128 + c * 16));
      size_t go = (size_t)r * 1024 + k0 + c * 8;
      cpasync16(dst + PB_BH + d, Bh_g + go);
      cpasync16(dst + PB_BL + d, Bl_g + go);
    }
  };

  issue(0, 0);
  cp_commit();

  for (int ch = 0; ch < 16; ch++) {
    if (ch + 1 < 16) {
      issue(ch + 1, (ch + 1) & 1);
      cp_commit();
      cp_wait1();
    } else {
      cp_wait0();
    }
    __syncthreads();

    const uint32_t base = sb + (ch & 1) * PBUF;
#pragma unroll
    for (int ks = 0; ks < 4; ks++) {
      const int colb = ks * 32 + selc;
      uint32_t ah[2][4], al[2][4];
#pragma unroll
      for (int mt = 0; mt < 2; mt++) {
        int r = wm + mt * 16 + selm + lrow;
        uint32_t off = sw128((uint32_t)(r * 128 + colb));
        ldsm4(ah[mt], base + PB_AH + off);
        ldsm4(al[mt], base + PB_AL + off);
      }
      uint32_t bh[4][2], bl[4][2];
#pragma unroll
      for (int np = 0; np < 2; np++) {
        int r = wn + np * 16 + selm + lrow;
        uint32_t off = sw128((uint32_t)(r * 128 + colb));
        uint32_t t4[4];
        ldsm4(t4, base + PB_BH + off);
        bh[2 * np][0] = t4[0]; bh[2 * np][1] = t4[2];
        bh[2 * np + 1][0] = t4[1]; bh[2 * np + 1][1] = t4[3];
        ldsm4(t4, base + PB_BL + off);
        bl[2 * np][0] = t4[0]; bl[2 * np][1] = t4[2];
        bl[2 * np + 1][0] = t4[1]; bl[2 * np + 1][1] = t4[3];
      }
#pragma unroll
      for (int mt = 0; mt < 2; mt++)
#pragma unroll
        for (int nt = 0; nt < 4; nt++) {
          mma16816(acc[mt][nt], ah[mt], bh[nt][0], bh[nt][1]);
          mma16816(acc[mt][nt], ah[mt], bl[nt][0], bl[nt][1]);
          mma16816(acc[mt][nt], al[mt], bh[nt][0], bh[nt][1]);
        }
    }
    __syncthreads();
  }

  __nv_bfloat16* __restrict__ oh = (mat == 0) ? g_qh : (mat == 1) ? g_kh : g_vh;
  __nv_bfloat16* __restrict__ ol = (mat == 0) ? g_ql : (mat == 1) ? g_kl : g_vl;
  const int orow = lane >> 2, ocol = (lane & 3) * 2;
#pragma unroll
  for (int mt = 0; mt < 2; mt++)
#pragma unroll
    for (int nt = 0; nt < 4; nt++) {
      int r = row0 + wm + mt * 16 + orow;
      int c = nh * 64 + wn + nt * 8 + ocol;
      uint32_t h0, l0, h1, l1;
      hilo(acc[mt][nt][0], acc[mt][nt][1], h0, l0);
      hilo(acc[mt][nt][2], acc[mt][nt][3], h1, l1);
      *(uint32_t*)&oh[(size_t)r * 128 + c] = h0;
      *(uint32_t*)&ol[(size_t)r * 128 + c] = l0;
      *(uint32_t*)&oh[(size_t)(r + 8) * 128 + c] = h1;
      *(uint32_t*)&ol[(size_t)(r + 8) * 128 + c] = l1;
    }
}

// ---------------- tensor-core dual flash attention (map-split warps) ----------------
// warps 0-3: map 0 (q1/k1), rows (wid&3)*16; warps 4-7: map 1 (q2/k2), same rows.
// Softmax fully warp-local. One cross-map SCR exchange per q-tile in the epilogue.
constexpr int KVBUF = 65536;              // Kh(2x8K) Kl(2x8K) Vh(2x8K) Vl(2x8K)
constexpr int AOFF_Q   = 131072;          // Qh d0-63, Qh d64-127, Ql d0-63, Ql d64-127
constexpr int AOFF_SCR = 163840;          // 64 x 132 f32 = 33792 B
constexpr int ATTN_SMEM = 197632;

__global__ __launch_bounds__(256, 1) void attn_mma_kernel(
    const float* __restrict__ gam, const float* __restrict__ bet,
    float* __restrict__ out) {
  extern __shared__ char smem[];
  uint32_t sb = smem_u32(smem);
  float* SCR = (float*)(smem + AOFF_SCR);

  const int tid = threadIdx.x;
  const int lane = tid & 31;
  const int wid = tid >> 5;
  const int wm = (wid & 3) * 16;
  const int m = wid >> 2;       // map 0/1
  const int lrow = lane & 7;
  const int sel = lane >> 3;
  const int selm = (sel & 1) * 8;
  const int selc = (sel >> 1) * 16;
  const int r = lane >> 2;
  const int cq = (lane & 3) * 2;

  const int rowbase = (int)blockIdx.y * Tn;
  const float lam = g_lam;

  auto issueKV = [&](int kt, int b) {
    const int k0g = kt * 64;
    const uint32_t dst = sb + b * KVBUF;
#pragma unroll
    for (int it = 0; it < 16; it++) {
      int idx = tid + it * 256;
      int part = idx >> 9;
      int j = idx & 511;
      int key = j >> 3, c = j & 7;
      uint32_t so = (uint32_t)part * 8192 + sw128((uint32_t)(key * 128 + c * 16));
      size_t go = (size_t)(rowbase + k0g + key) * 128 + (part & 1) * 64 + c * 8;
      const __nv_bfloat16* src =
          (part < 2) ? g_kh : (part < 4) ? g_kl : (part < 6) ? g_vh : g_vl;
      cpasync16(dst + so, src + go);
    }
  };
  auto issueQ = [&](int q0) {
#pragma unroll
    for (int it = 0; it < 8; it++) {
      int idx = tid + it * 256;
      int part = idx >> 9;
      int j = idx & 511;
      int row = j >> 3, c = j & 7;
      uint32_t so = AOFF_Q + (uint32_t)part * 8192 + sw128((uint32_t)(row * 128 + c * 16));
      size_t go = (size_t)(rowbase + q0 + row) * 128 + (part & 1) * 64 + c * 8;
      const __nv_bfloat16* src = (part < 2) ? g_qh : g_ql;
      cpasync16(sb + so, src + go);
    }
  };

  for (int half = 0; half < 2; half++) {
    const int qt = half ? (35 - (int)blockIdx.x) : (int)blockIdx.x;
    const int q0 = qt * 64;

    float oacc[16][4];              // this map's O: 16 rows x 128 cols
    float mrow[2], lrow_s[2];
#pragma unroll
    for (int h = 0; h < 2; h++) { mrow[h] = -3.0e38f; lrow_s[h] = 0.f; }
#pragma unroll
    for (int nt = 0; nt < 16; nt++)
#pragma unroll
      for (int j = 0; j < 4; j++) oacc[nt][j] = 0.f;

    issueQ(q0);
    issueKV(0, 0);
    cp_commit();

    for (int kt = 0; kt <= qt; kt++) {
      if (kt < qt) {
        issueKV(kt + 1, (kt + 1) & 1);
        cp_commit();
        cp_wait1();
      } else {
        cp_wait0();
      }
      __syncthreads();   // A: buffers ready

      const uint32_t buf = sb + (kt & 1) * KVBUF;
      const int k0 = kt * 64;

      // ---- S = Q K^T for this warp's map: 16 rows x 64 keys ----
      float sacc[8][4];
#pragma unroll
      for (int nt = 0; nt < 8; nt++)
#pragma unroll
        for (int j = 0; j < 4; j++) sacc[nt][j] = 0.f;

      {
        const uint32_t Qh = sb + AOFF_Q + m * 8192;
        const uint32_t Ql = sb + AOFF_Q + 16384 + m * 8192;
        const uint32_t Kh = buf + m * 8192;
        const uint32_t Kl = buf + 16384 + m * 8192;
#pragma unroll
        for (int ks = 0; ks < 4; ks++) {
          const int colb = ks * 32 + selc;
          uint32_t aoff = sw128((uint32_t)((wm + selm + lrow) * 128 + colb));
          uint32_t qh[4], ql[4];
          ldsm4(qh, Qh + aoff);
          ldsm4(ql, Ql + aoff);
          uint32_t bh[8][2], bl[8][2];
#pragma unroll
          for (int np = 0; np < 4; np++) {
            uint32_t boff = sw128((uint32_t)((np * 16 + selm + lrow) * 128 + colb));
            uint32_t t4[4];
            ldsm4(t4, Kh + boff);
            bh[2 * np][0] = t4[0]; bh[2 * np][1] = t4[2];
            bh[2 * np + 1][0] = t4[1]; bh[2 * np + 1][1] = t4[3];
            ldsm4(t4, Kl + boff);
            bl[2 * np][0] = t4[0]; bl[2 * np][1] = t4[2];
            bl[2 * np + 1][0] = t4[1]; bl[2 * np + 1][1] = t4[3];
          }
#pragma unroll
          for (int nt = 0; nt < 8; nt++) {
            mma16816(sacc[nt], qh, bh[nt][0], bh[nt][1]);
            mma16816(sacc[nt], ql, bh[nt][0], bh[nt][1]);
            mma16816(sacc[nt], qh, bl[nt][0], bl[nt][1]);
          }
        }
      }

      // ---- warp-local softmax ----
      const bool diag = (kt == qt);
      float mx[2] = {-3.0e38f, -3.0e38f};
#pragma unroll
      for (int nt = 0; nt < 8; nt++)
#pragma unroll
        for (int h = 0; h < 2; h++)
#pragma unroll
          for (int j = 0; j < 2; j++) {
            float v = sacc[nt][h * 2 + j] * QSCALE;
            if (diag && (k0 + nt * 8 + cq + j) > (q0 + wm + r + h * 8)) v = -3.0e38f;
            sacc[nt][h * 2 + j] = v;
            mx[h] = fmaxf(mx[h], v);
          }
#pragma unroll
      for (int h = 0; h < 2; h++) {
        mx[h] = fmaxf(mx[h], __shfl_xor_sync(0xffffffffu, mx[h], 1));
        mx[h] = fmaxf(mx[h], __shfl_xor_sync(0xffffffffu, mx[h], 2));
      }

      float alpha[2], lsum[2] = {0.f, 0.f};
#pragma unroll
      for (int h = 0; h < 2; h++) {
        float mn = fmaxf(mrow[h], mx[h]);
        alpha[h] = fast_exp2(mrow[h] - mn);
        mrow[h] = mn;
      }

      // exp in place; P fragments in registers
      uint32_t pfh[4][4], pfl[4][4];
#pragma unroll
      for (int nt = 0; nt < 8; nt++)
#pragma unroll
        for (int h = 0; h < 2; h++) {
          float p0 = fast_exp2(sacc[nt][h * 2 + 0] - mrow[h]);
          float p1 = fast_exp2(sacc[nt][h * 2 + 1] - mrow[h]);
          lsum[h] += p0 + p1;
          sacc[nt][h * 2 + 0] = p0;
          sacc[nt][h * 2 + 1] = p1;
        }
#pragma unroll
      for (int ks = 0; ks < 4; ks++) {
        hilo(sacc[2 * ks][0], sacc[2 * ks][1], pfh[ks][0], pfl[ks][0]);
        hilo(sacc[2 * ks][2], sacc[2 * ks][3], pfh[ks][1], pfl[ks][1]);
        hilo(sacc[2 * ks + 1][0], sacc[2 * ks + 1][1], pfh[ks][2], pfl[ks][2]);
        hilo(sacc[2 * ks + 1][2], sacc[2 * ks + 1][3], pfh[ks][3], pfl[ks][3]);
      }
#pragma unroll
      for (int h = 0; h < 2; h++) {
        lsum[h] += __shfl_xor_sync(0xffffffffu, lsum[h], 1);
        lsum[h] += __shfl_xor_sync(0xffffffffu, lsum[h], 2);
        lrow_s[h] = lrow_s[h] * alpha[h] + lsum[h];
      }
      // rescale O by alpha
#pragma unroll
      for (int nt = 0; nt < 16; nt++) {
        oacc[nt][0] *= alpha[0];
        oacc[nt][1] *= alpha[0];
        oacc[nt][2] *= alpha[1];
        oacc[nt][3] *= alpha[1];
      }

      // ---- O += P V (P in registers; V: 64 keys x 128 dims) ----
#pragma unroll
      for (int ks = 0; ks < 4; ks++) {
        const int vrow = ks * 16 + selm + lrow;
#pragma unroll
        for (int np = 0; np < 8; np++) {
          const int part = np >> 2;
          const uint32_t boff = (uint32_t)part * 8192 +
              sw128((uint32_t)(vrow * 128 + (np & 3) * 32 + selc));
          uint32_t vh4[4], vl4[4];
          ldsm4t(vh4, buf + 32768 + boff);
          ldsm4t(vl4, buf + 49152 + boff);
#pragma unroll
          for (int e = 0; e < 2; e++) {
            float* d = oacc[2 * np + e];
            mma16816(d, pfh[ks], vh4[2 * e], vh4[2 * e + 1]);
            mma16816(d, pfl[ks], vh4[2 * e], vh4[2 * e + 1]);
            mma16816(d, pfh[ks], vl4[2 * e], vl4[2 * e + 1]);
          }
        }
      }
      __syncthreads();   // D: protect KV buffer reuse
    }

    // ---- epilogue: cross-map combine + output LN ----
    if (m == 1) {
      float inv2[2];
#pragma unroll
      for (int h = 0; h < 2; h++) inv2[h] = lam / lrow_s[h];
#pragma unroll
      for (int nt = 0; nt < 16; nt++)
#pragma unroll
        for (int h = 0; h < 2; h++) {
          int rr = wm + r + h * 8;
          SCR[rr * 132 + nt * 8 + cq]     = oacc[nt][h * 2 + 0] * inv2[h];
          SCR[rr * 132 + nt * 8 + cq + 1] = oacc[nt][h * 2 + 1] * inv2[h];
        }
    }
    __syncthreads();
    if (m == 0) {
      float inv1[2];
#pragma unroll
      for (int h = 0; h < 2; h++) inv1[h] = 1.0f / lrow_s[h];
      float att[16][4];
      float rs[2] = {0.f, 0.f};
#pragma unroll
      for (int nt = 0; nt < 16; nt++)
#pragma unroll
        for (int h = 0; h < 2; h++) {
          int rr = wm + r + h * 8;
          float a0 = oacc[nt][h * 2 + 0] * inv1[h] - SCR[rr * 132 + nt * 8 + cq];
          float a1 = oacc[nt][h * 2 + 1] * inv1[h] - SCR[rr * 132 + nt * 8 + cq + 1];
          att[nt][h * 2 + 0] = a0;
          att[nt][h * 2 + 1] = a1;
          rs[h] += a0 + a1;
        }
#pragma unroll
      for (int h = 0; h < 2; h++) {
        rs[h] += __shfl_xor_sync(0xffffffffu, rs[h], 1);
        rs[h] += __shfl_xor_sync(0xffffffffu, rs[h], 2);
      }
      float mean_[2];
#pragma unroll
      for (int h = 0; h < 2; h++) mean_[h] = rs[h] * (1.0f / 128.0f);

      float vs[2] = {0.f, 0.f};
#pragma unroll
      for (int nt = 0; nt < 16; nt++)
#pragma unroll
        for (int h = 0; h < 2; h++)
#pragma unroll
          for (int j = 0; j < 2; j++) {
            float a = att[nt][h * 2 + j] - mean_[h];
            vs[h] += a * a;
          }
#pragma unroll
      for (int h = 0; h < 2; h++) {
        vs[h] += __shfl_xor_sync(0xffffffffu, vs[h], 1);
        vs[h] += __shfl_xor_sync(0xffffffffu, vs[h], 2);
      }
      float rstd_[2];
#pragma unroll
      for (int h = 0; h < 2; h++)
        rstd_[h] = rsqrtf(vs[h] * (1.0f / 128.0f) + 1e-5f);

#pragma unroll
      for (int nt = 0; nt < 16; nt++) {
        int c = nt * 8 + cq;
        float2 g2 = *(const float2*)&gam[c];
        float2 b2 = *(const float2*)&bet[c];
#pragma unroll
        for (int h = 0; h < 2; h++) {
          float o0 = (att[nt][h * 2 + 0] - mean_[h]) * rstd_[h] * g2.x + b2.x;
          float o1 = (att[nt][h * 2 + 1] - mean_[h]) * rstd_[h] * g2.y + b2.y;
          size_t off = (size_t)(rowbase + q0 + wm + r + h * 8) * 128 + c;
          *(float2*)&out[off] = make_float2(o0, o1);
        }
      }
    }
    __syncthreads();   // protect SCR + smem before next half
  }
}

// ---------------- launch ----------------
extern "C" void kernel_launch(void* const* d_in, const int* in_sizes, int n_in,
                              void* d_out, int out_size) {
  const float* x     = (const float*)d_in[0];
  const float* Wq    = (const float*)d_in[1];
  const float* Wk    = (const float*)d_in[2];
  const float* Wv    = (const float*)d_in[3];
  const float* Wq_ss = (const float*)d_in[4];
  const float* Wk_ss = (const float*)d_in[5];
  const float* Wv_ss = (const float*)d_in[6];
  const float* Wq_se = (const float*)d_in[7];
  const float* Wk_se = (const float*)d_in[8];
  const float* Wv_se = (const float*)d_in[9];
  const float* g_in  = (const float*)d_in[10];
  const float* b_in  = (const float*)d_in[11];
  const float* g_ss  = (const float*)d_in[12];
  const float* b_ss  = (const float*)d_in[13];
  const float* g_se  = (const float*)d_in[14];
  const float* b_se  = (const float*)d_in[15];
  const float* g_out = (const float*)d_in[16];
  const float* b_out = (const float*)d_in[17];
  const float* lq1   = (const float*)d_in[18];
  const float* lq2   = (const float*)d_in[19];
  const float* lk1   = (const float*)d_in[20];
  const float* lk2   = (const float*)d_in[21];

  static bool attr_set = false;
  if (!attr_set) {
    cudaFuncSetAttribute(proj_mma_kernel, cudaFuncAttributeMaxDynamicSharedMemorySize,
                         PROJ_SMEM);
    cudaFuncSetAttribute(attn_mma_kernel, cudaFuncAttributeMaxDynamicSharedMemorySize,
                         ATTN_SMEM);
    attr_set = true;
  }

  lambda_kernel<<<1, 64>>>(lq1, lq2, lk1, lk2);

  WPrepParams wp;
  wp.W[0] = Wq_ss; wp.W[1] = Wq; wp.W[2] = Wq_se;
  wp.W[3] = Wk_ss; wp.W[4] = Wk; wp.W[5] = Wk_se;
  wp.W[6] = Wv_ss; wp.W[7] = Wv; wp.W[8] = Wv_se;
  wprep_kernel<<<dim3(32, 4, 9), dim3(32, 32)>>>(wp);

  NormParams np;
  np.x = x;
  np.g[0] = g_ss; np.g[1] = g_in; np.g[2] = g_se;
  np.b[0] = b_ss; np.b[1] = b_in; np.b[2] = b_se;
  norm_split_kernel<<<NROW / 8, dim3(32, 8)>>>(np);

  proj_mma_kernel<<<dim3(144, 3, 2), 256, PROJ_SMEM>>>();

  attn_mma_kernel<<<dim3(18, 8), 256, ATTN_SMEM>>>(g_out, b_out, (float*)d_out);
}